// round 1
// baseline (speedup 1.0000x reference)
#include <cuda_runtime.h>
#include <math.h>

#define N_NODES 50000
#define N_EDGES 800000
#define IN_CH   256
#define D       64
#define NC      8

typedef unsigned long long u64;

// ---------------- f32x2 packed helpers (FFMA2: PTX-only, 2x FMA throughput) ----
__device__ __forceinline__ u64 pk2(float lo, float hi) {
    u64 r; asm("mov.b64 %0, {%1, %2};" : "=l"(r) : "f"(lo), "f"(hi)); return r;
}
__device__ __forceinline__ void up2(u64 v, float& lo, float& hi) {
    asm("mov.b64 {%0, %1}, %2;" : "=f"(lo), "=f"(hi) : "l"(v));
}
__device__ __forceinline__ void fma2(u64& d, u64 a, u64 b) {
    asm("fma.rn.f32x2 %0, %1, %2, %0;" : "+l"(d) : "l"(a), "l"(b));
}
// rank-1 update: acc[0..63] += s * wrow[0..63], packed as 32 u64 pairs
__device__ __forceinline__ void rank1_64(u64* acc, float s, const float* wrow) {
    u64 s2 = pk2(s, s);
    const ulonglong2* w = reinterpret_cast<const ulonglong2*>(wrow);
#pragma unroll
    for (int t = 0; t < 16; t++) {
        ulonglong2 ww = w[t];
        fma2(acc[2*t],   s2, ww.x);
        fma2(acc[2*t+1], s2, ww.y);
    }
}
// dot of packed tf (32 u64 pairs) with a 64-float shared row
__device__ __forceinline__ float dot64(const u64* a, const float* wrow) {
    u64 s = 0ull;
    const ulonglong2* w = reinterpret_cast<const ulonglong2*>(wrow);
#pragma unroll
    for (int t = 0; t < 16; t++) {
        ulonglong2 ww = w[t];
        fma2(s, a[2*t],   ww.x);
        fma2(s, a[2*t+1], ww.y);
    }
    float lo, hi; up2(s, lo, hi); return lo + hi;
}
// vector float4 reduction, no return
__device__ __forceinline__ void red4(float* p, float a, float b, float c, float d) {
    asm volatile("red.global.add.v4.f32 [%0], {%1,%2,%3,%4};"
                 :: "l"(p), "f"(a), "f"(b), "f"(c), "f"(d) : "memory");
}
// order-preserving float<->uint encoding for atomicMax on floats
__device__ __forceinline__ unsigned fenc(float f) {
    unsigned u = __float_as_uint(f);
    return (u & 0x80000000u) ? ~u : (u | 0x80000000u);
}
__device__ __forceinline__ float fdec(unsigned u) {
    return __uint_as_float((u & 0x80000000u) ? (u & 0x7FFFFFFFu) : ~u);
}

// ---------------- scratch (static device globals; no runtime alloc) ----------
__device__ float g_nf  [N_NODES * D];        // relu(x@Wd+bd)
__device__ float g_qk  [N_NODES * D];        // nf@Wqk + bqk   (q folded with Wk^T)
__device__ float g_qb  [N_NODES];            // q . bk
__device__ float g_attn[N_EDGES];
__device__ int   g_clu [N_EDGES];
__device__ unsigned g_m[N_NODES * NC];       // encoded segment max
__device__ float g_denom[N_NODES * NC];
__device__ float g_cnt  [N_NODES * NC];
__device__ float g_sums [N_NODES * NC * D];  // sum of ex*tf per segment (102.4MB)
__device__ float g_cec  [NC];                // edges per cluster
__device__ float g_accN [N_NODES * D];       // per-node weighted tf sum
__device__ float g_bsc  [N_NODES];
__device__ float g_fused[N_NODES * D];
// precomputed folded weights
__device__ float g_Wqk[D * D], g_bqk[D], g_wqb[D], g_sqb;
__device__ float g_Wvo[D * D], g_bvo[D];

// ---------------- K0: zero scratch --------------------------------------------
__global__ void k_init() {
    int i = blockIdx.x * blockDim.x + threadIdx.x;
    int stride = gridDim.x * blockDim.x;
    float4 z = make_float4(0.f, 0.f, 0.f, 0.f);
    for (int t = i; t < N_NODES * NC * D / 4; t += stride)
        reinterpret_cast<float4*>(g_sums)[t] = z;
    for (int t = i; t < N_NODES * NC; t += stride) {
        g_denom[t] = 0.f; g_cnt[t] = 0.f; g_m[t] = 0u;
    }
    if (i < NC) g_cec[i] = 0.f;
}

// ---------------- K1: fold weights --------------------------------------------
// Wqk[t][j] = sum_d Wq[t][d]*Wk[j][d];  bqk[j] = sum_d bq[d]*Wk[j][d]
// wqb[t]    = sum_d Wq[t][d]*bk[d];     sqb    = bq.bk
// Wvo[t][j] = sum_d Wv[t][d]*Wout[d][j]; bvo[j] = sum_d bv[d]*Wout[d][j]
__global__ void k_prep(const float* __restrict__ Wq, const float* __restrict__ bq,
                       const float* __restrict__ Wk, const float* __restrict__ bk,
                       const float* __restrict__ Wv, const float* __restrict__ bv,
                       const float* __restrict__ Wo, const float* __restrict__ bo) {
    int idx = blockIdx.x * blockDim.x + threadIdx.x;
    if (idx < D * D) {
        int t = idx >> 6, j = idx & 63;
        float s1 = 0.f, s2 = 0.f;
        for (int d = 0; d < D; d++) {
            s1 = fmaf(Wq[t * D + d], Wk[j * D + d], s1);
            s2 = fmaf(Wv[t * D + d], Wo[d * D + j], s2);
        }
        g_Wqk[t * D + j] = s1;
        g_Wvo[t * D + j] = s2;
    }
    if (idx < D) {
        int j = idx;
        float a = 0.f, b = 0.f, c = 0.f;
        for (int d = 0; d < D; d++) {
            a = fmaf(bq[d], Wk[j * D + d], a);
            b = fmaf(bv[d], Wo[d * D + j], b);
            c = fmaf(Wq[j * D + d], bk[d], c);
        }
        g_bqk[j] = a; g_bvo[j] = b; g_wqb[j] = c;
        if (idx == 0) {
            float s = 0.f;
            for (int d = 0; d < D; d++) s = fmaf(bq[d], bk[d], s);
            g_sqb = s;
        }
    }
}

// ---------------- K2: nf = relu(x @ Wd + bd) -----------------------------------
__global__ void k_nodeA1(const float* __restrict__ x,
                         const float* __restrict__ Wd, const float* __restrict__ bd) {
    extern __shared__ float smem[];
    float* sW = smem;                 // 256*64
    float* sb = smem + IN_CH * D;     // 64
    for (int t = threadIdx.x; t < IN_CH * D / 4; t += blockDim.x)
        reinterpret_cast<float4*>(sW)[t] = reinterpret_cast<const float4*>(Wd)[t];
    for (int t = threadIdx.x; t < D; t += blockDim.x) sb[t] = bd[t];
    __syncthreads();
    int n = blockIdx.x * blockDim.x + threadIdx.x;
    if (n >= N_NODES) return;

    u64 acc[32];
    const u64* sb2 = reinterpret_cast<const u64*>(sb);
#pragma unroll
    for (int t = 0; t < 32; t++) acc[t] = sb2[t];

    const float4* xr = reinterpret_cast<const float4*>(x + (size_t)n * IN_CH);
#pragma unroll 2
    for (int jv = 0; jv < IN_CH / 4; jv++) {
        float4 xv = xr[jv];
        const float* w0 = sW + (jv * 4) * D;
        rank1_64(acc, xv.x, w0);
        rank1_64(acc, xv.y, w0 + D);
        rank1_64(acc, xv.z, w0 + 2 * D);
        rank1_64(acc, xv.w, w0 + 3 * D);
    }
    float4* outp = reinterpret_cast<float4*>(g_nf + n * D);
#pragma unroll
    for (int t = 0; t < 16; t++) {
        float a, b, c, d;
        up2(acc[2*t], a, b); up2(acc[2*t+1], c, d);
        outp[t] = make_float4(fmaxf(a, 0.f), fmaxf(b, 0.f), fmaxf(c, 0.f), fmaxf(d, 0.f));
    }
}

// ---------------- K3: qk = nf @ Wqk + bqk ; qb = nf.wqb + sqb ------------------
__global__ void k_nodeA2() {
    extern __shared__ float smem[];
    float* sW = smem;                 // 64*64
    float* sbq = smem + D * D;        // 64
    float* swq = sbq + D;             // 64
    for (int t = threadIdx.x; t < D * D / 4; t += blockDim.x)
        reinterpret_cast<float4*>(sW)[t] = reinterpret_cast<const float4*>(g_Wqk)[t];
    for (int t = threadIdx.x; t < D; t += blockDim.x) { sbq[t] = g_bqk[t]; swq[t] = g_wqb[t]; }
    __syncthreads();
    int n = blockIdx.x * blockDim.x + threadIdx.x;
    if (n >= N_NODES) return;

    u64 acc[32];
    const u64* sb2 = reinterpret_cast<const u64*>(sbq);
#pragma unroll
    for (int t = 0; t < 32; t++) acc[t] = sb2[t];
    float qb = g_sqb;

    const float4* nr = reinterpret_cast<const float4*>(g_nf + n * D);
#pragma unroll 2
    for (int jv = 0; jv < 16; jv++) {
        float4 v = nr[jv];
        const float* w0 = sW + (jv * 4) * D;
        rank1_64(acc, v.x, w0);         qb = fmaf(v.x, swq[jv*4+0], qb);
        rank1_64(acc, v.y, w0 + D);     qb = fmaf(v.y, swq[jv*4+1], qb);
        rank1_64(acc, v.z, w0 + 2*D);   qb = fmaf(v.z, swq[jv*4+2], qb);
        rank1_64(acc, v.w, w0 + 3*D);   qb = fmaf(v.w, swq[jv*4+3], qb);
    }
    float4* outp = reinterpret_cast<float4*>(g_qk + n * D);
#pragma unroll
    for (int t = 0; t < 16; t++) {
        float a, b, c, d;
        up2(acc[2*t], a, b); up2(acc[2*t+1], c, d);
        outp[t] = make_float4(a, b, c, d);
    }
    g_qb[n] = qb;
}

// common per-edge time_feat compute (packed, with relu applied)
__device__ __forceinline__ void edge_tf(u64* acc, const float* __restrict__ ea, int e,
                                        const float* sW, const float* sb) {
    const u64* sb2 = reinterpret_cast<const u64*>(sb);
#pragma unroll
    for (int t = 0; t < 32; t++) acc[t] = sb2[t];
    const float4* ar = reinterpret_cast<const float4*>(ea + (size_t)e * 16);
#pragma unroll
    for (int jv = 0; jv < 4; jv++) {
        float4 a = ar[jv];
        const float* w0 = sW + (jv * 4) * D;
        rank1_64(acc, a.x, w0);
        rank1_64(acc, a.y, w0 + D);
        rank1_64(acc, a.z, w0 + 2 * D);
        rank1_64(acc, a.w, w0 + 3 * D);
    }
#pragma unroll
    for (int t = 0; t < 32; t++) {
        float lo, hi; up2(acc[t], lo, hi);
        acc[t] = pk2(fmaxf(lo, 0.f), fmaxf(hi, 0.f));
    }
}

// ---------------- K4: per-edge attn + cluster + segment max --------------------
__global__ void k_edge1(const float* __restrict__ ea, const int* __restrict__ ei,
                        const float* __restrict__ Wt, const float* __restrict__ bt,
                        const float* __restrict__ ce) {
    extern __shared__ float smem[];
    float* sW = smem;            // 16*64
    float* sb = sW + 16 * D;     // 64
    float* sc = sb + D;          // 8*64
    for (int t = threadIdx.x; t < 16 * D / 4; t += blockDim.x)
        reinterpret_cast<float4*>(sW)[t] = reinterpret_cast<const float4*>(Wt)[t];
    for (int t = threadIdx.x; t < D; t += blockDim.x) sb[t] = bt[t];
    for (int t = threadIdx.x; t < NC * D / 4; t += blockDim.x)
        reinterpret_cast<float4*>(sc)[t] = reinterpret_cast<const float4*>(ce)[t];
    __syncthreads();
    int e = blockIdx.x * blockDim.x + threadIdx.x;
    if (e >= N_EDGES) return;

    u64 tf[32];
    edge_tf(tf, ea, e, sW, sb);

    // cluster argmax (positive scaling preserves argmax -> skip 0.125)
    int bc = 0; float bv = dot64(tf, sc);
#pragma unroll
    for (int c = 1; c < NC; c++) {
        float s = dot64(tf, sc + c * D);
        if (s > bv) { bv = s; bc = c; }
    }

    int src = ei[e];
    const float4* qr = reinterpret_cast<const float4*>(g_qk + src * D);
    u64 s = 0ull;
#pragma unroll
    for (int tv = 0; tv < 16; tv++) {
        float4 q = qr[tv];
        fma2(s, tf[2*tv],   pk2(q.x, q.y));
        fma2(s, tf[2*tv+1], pk2(q.z, q.w));
    }
    float lo, hi; up2(s, lo, hi);
    float attn = (lo + hi + g_qb[src]) * 0.125f;

    g_attn[e] = attn;
    g_clu[e] = bc;
    atomicMax(&g_m[src * NC + bc], fenc(attn));
}

// ---------------- K5: ex accumulation into segments ----------------------------
__global__ void k_edge2(const float* __restrict__ ea, const int* __restrict__ ei,
                        const float* __restrict__ Wt, const float* __restrict__ bt) {
    extern __shared__ float smem[];
    float* sW = smem;
    float* sb = sW + 16 * D;
    float* scec = sb + D;   // 8
    for (int t = threadIdx.x; t < 16 * D / 4; t += blockDim.x)
        reinterpret_cast<float4*>(sW)[t] = reinterpret_cast<const float4*>(Wt)[t];
    for (int t = threadIdx.x; t < D; t += blockDim.x) sb[t] = bt[t];
    if (threadIdx.x < NC) scec[threadIdx.x] = 0.f;
    __syncthreads();
    int e = blockIdx.x * blockDim.x + threadIdx.x;
    if (e < N_EDGES) {
        u64 tf[32];
        edge_tf(tf, ea, e, sW, sb);
        int src = ei[e];
        int c = g_clu[e];
        int seg = src * NC + c;
        float m = fdec(g_m[seg]);
        float ex = expf(g_attn[e] - m);
        atomicAdd(&g_denom[seg], ex);
        atomicAdd(&g_cnt[seg], 1.0f);
        atomicAdd(&scec[c], 1.0f);
        float* base = g_sums + (size_t)seg * D;
#pragma unroll
        for (int tv = 0; tv < 16; tv++) {
            float a, b; up2(tf[2*tv], a, b);
            float cc, d; up2(tf[2*tv+1], cc, d);
            red4(base + tv * 4, a * ex, b * ex, cc * ex, d * ex);
        }
    }
    __syncthreads();
    if (threadIdx.x < NC) atomicAdd(&g_cec[threadIdx.x], scec[threadIdx.x]);
}

// ---------------- K6: per-node weighted aggregate ------------------------------
__global__ void k_E1() {
    int n = blockIdx.x * blockDim.x + threadIdx.x;
    if (n >= N_NODES) return;
    u64 acc[32];
#pragma unroll
    for (int t = 0; t < 32; t++) acc[t] = 0ull;
    float bscale = 0.f;
#pragma unroll
    for (int c = 0; c < NC; c++) {
        float cnt = g_cnt[n * NC + c];
        if (cnt > 0.f) {
            float sc = 1.0f / (g_denom[n * NC + c] * cnt);
            bscale += 1.0f / cnt;
            u64 sc2 = pk2(sc, sc);
            const float4* sr = reinterpret_cast<const float4*>(g_sums + ((size_t)n * NC + c) * D);
#pragma unroll
            for (int tv = 0; tv < 16; tv++) {
                float4 v = sr[tv];
                fma2(acc[2*tv],   pk2(v.x, v.y), sc2);
                fma2(acc[2*tv+1], pk2(v.z, v.w), sc2);
            }
        }
    }
    float4* outp = reinterpret_cast<float4*>(g_accN + n * D);
#pragma unroll
    for (int t = 0; t < 16; t++) {
        float a, b, c, d;
        up2(acc[2*t], a, b); up2(acc[2*t+1], c, d);
        outp[t] = make_float4(a, b, c, d);
    }
    g_bsc[n] = bscale;
}

// ---------------- K7: fused = relu((acc@Wvo + bvo*bsc)/nne + b_out) -------------
__global__ void k_E2(const float* __restrict__ bo) {
    extern __shared__ float smem[];
    float* sW = smem;             // 64*64 (Wvo)
    float* sbv = smem + D * D;    // 64
    float* sbo = sbv + D;         // 64
    for (int t = threadIdx.x; t < D * D / 4; t += blockDim.x)
        reinterpret_cast<float4*>(sW)[t] = reinterpret_cast<const float4*>(g_Wvo)[t];
    for (int t = threadIdx.x; t < D; t += blockDim.x) { sbv[t] = g_bvo[t]; sbo[t] = bo[t]; }
    __syncthreads();
    int n = blockIdx.x * blockDim.x + threadIdx.x;
    if (n >= N_NODES) return;

    float nne = 0.f;
#pragma unroll
    for (int c = 0; c < NC; c++) nne += (g_cec[c] > 0.f) ? 1.f : 0.f;
    float inv = 1.0f / nne;
    float bsc = g_bsc[n] * inv;

    u64 acc[32];
#pragma unroll
    for (int t = 0; t < 32; t++)
        acc[t] = pk2(fmaf(sbv[2*t], bsc, sbo[2*t]), fmaf(sbv[2*t+1], bsc, sbo[2*t+1]));

    const float4* ar = reinterpret_cast<const float4*>(g_accN + n * D);
#pragma unroll 2
    for (int jv = 0; jv < 16; jv++) {
        float4 v = ar[jv];
        const float* w0 = sW + (jv * 4) * D;
        rank1_64(acc, v.x * inv, w0);
        rank1_64(acc, v.y * inv, w0 + D);
        rank1_64(acc, v.z * inv, w0 + 2 * D);
        rank1_64(acc, v.w * inv, w0 + 3 * D);
    }
    float4* outp = reinterpret_cast<float4*>(g_fused + n * D);
#pragma unroll
    for (int t = 0; t < 16; t++) {
        float a, b, c, d;
        up2(acc[2*t], a, b); up2(acc[2*t+1], c, d);
        outp[t] = make_float4(fmaxf(a, 0.f), fmaxf(b, 0.f), fmaxf(c, 0.f), fmaxf(d, 0.f));
    }
}

// ---------------- K8: out = x + fused @ W_up + b_up -----------------------------
// thread = (node, chunk-of-64-outputs); 4 chunks cover 256 outputs
__global__ void k_E3(const float* __restrict__ x, const float* __restrict__ Wup,
                     const float* __restrict__ bup, float* __restrict__ out) {
    extern __shared__ float smem[];
    float* sW = smem;                 // 64*256
    float* sb = smem + D * IN_CH;     // 256
    for (int t = threadIdx.x; t < D * IN_CH / 4; t += blockDim.x)
        reinterpret_cast<float4*>(sW)[t] = reinterpret_cast<const float4*>(Wup)[t];
    for (int t = threadIdx.x; t < IN_CH; t += blockDim.x) sb[t] = bup[t];
    __syncthreads();
    int tid = blockIdx.x * blockDim.x + threadIdx.x;
    if (tid >= N_NODES * 4) return;
    int n = tid >> 2, ch = tid & 3;

    u64 acc[32];
    const u64* sb2 = reinterpret_cast<const u64*>(sb + ch * D);
#pragma unroll
    for (int t = 0; t < 32; t++) acc[t] = sb2[t];

    const float4* fr = reinterpret_cast<const float4*>(g_fused + n * D);
#pragma unroll 2
    for (int jv = 0; jv < 16; jv++) {
        float4 f = fr[jv];
        const float* w0 = sW + (jv * 4) * IN_CH + ch * D;
        rank1_64(acc, f.x, w0);
        rank1_64(acc, f.y, w0 + IN_CH);
        rank1_64(acc, f.z, w0 + 2 * IN_CH);
        rank1_64(acc, f.w, w0 + 3 * IN_CH);
    }
    const float4* xr = reinterpret_cast<const float4*>(x + (size_t)n * IN_CH + ch * D);
    float4* orow = reinterpret_cast<float4*>(out + (size_t)n * IN_CH + ch * D);
#pragma unroll
    for (int tv = 0; tv < 16; tv++) {
        float a, b; up2(acc[2*tv], a, b);
        float c, d; up2(acc[2*tv+1], c, d);
        float4 xv = xr[tv];
        orow[tv] = make_float4(xv.x + a, xv.y + b, xv.z + c, xv.w + d);
    }
}

// -------------------------------------------------------------------------------
extern "C" void kernel_launch(void* const* d_in, const int* in_sizes, int n_in,
                              void* d_out, int out_size) {
    const float* x   = (const float*)d_in[0];
    const float* ea  = (const float*)d_in[1];
    const int*   ei  = (const int*)  d_in[2];
    const float* Wd  = (const float*)d_in[3];
    const float* bd  = (const float*)d_in[4];
    const float* Wup = (const float*)d_in[5];
    const float* bup = (const float*)d_in[6];
    const float* Wt  = (const float*)d_in[7];
    const float* bt  = (const float*)d_in[8];
    const float* Wq  = (const float*)d_in[9];
    const float* bq  = (const float*)d_in[10];
    const float* Wk  = (const float*)d_in[11];
    const float* bk  = (const float*)d_in[12];
    const float* Wv  = (const float*)d_in[13];
    const float* bv  = (const float*)d_in[14];
    const float* ce  = (const float*)d_in[15];
    const float* Wo  = (const float*)d_in[16];
    const float* bo  = (const float*)d_in[17];
    float* out = (float*)d_out;

    int smA1 = (IN_CH * D + D) * 4;          // 65.8 KB
    int smA2 = (D * D + 2 * D) * 4;
    int smE1g = (16 * D + D + NC * D) * 4;   // edge1
    int smE2g = (16 * D + D + NC) * 4;       // edge2
    int smE2 = (D * D + 2 * D) * 4;
    int smE3 = (D * IN_CH + IN_CH) * 4;      // 66.6 KB
    cudaFuncSetAttribute(k_nodeA1, cudaFuncAttributeMaxDynamicSharedMemorySize, smA1);
    cudaFuncSetAttribute(k_E3,     cudaFuncAttributeMaxDynamicSharedMemorySize, smE3);

    k_init <<<512, 256>>>();
    k_prep <<<16, 256>>>(Wq, bq, Wk, bk, Wv, bv, Wo, bo);
    k_nodeA1<<<(N_NODES + 127) / 128, 128, smA1>>>(x, Wd, bd);
    k_nodeA2<<<(N_NODES + 127) / 128, 128, smA2>>>();
    k_edge1<<<(N_EDGES + 255) / 256, 256, smE1g>>>(ea, ei, Wt, bt, ce);
    k_edge2<<<(N_EDGES + 255) / 256, 256, smE2g>>>(ea, ei, Wt, bt);
    k_E1   <<<(N_NODES + 255) / 256, 256>>>();
    k_E2   <<<(N_NODES + 127) / 128, 128, smE2>>>(bo);
    k_E3   <<<(N_NODES * 4 + 255) / 256, 256, smE3>>>(x, Wup, bup, out);
}

// round 2
// speedup vs baseline: 1.1495x; 1.1495x over previous
#include <cuda_runtime.h>
#include <math.h>

#define N_NODES 50000
#define N_EDGES 800000
#define IN_CH   256
#define D       64
#define NC      8
#define NSEG    (N_NODES * NC)

typedef unsigned long long u64;

// ---------------- f32x2 packed helpers ----------------------------------------
__device__ __forceinline__ u64 pk2(float lo, float hi) {
    u64 r; asm("mov.b64 %0, {%1, %2};" : "=l"(r) : "f"(lo), "f"(hi)); return r;
}
__device__ __forceinline__ void up2(u64 v, float& lo, float& hi) {
    asm("mov.b64 {%0, %1}, %2;" : "=f"(lo), "=f"(hi) : "l"(v));
}
__device__ __forceinline__ void fma2(u64& d, u64 a, u64 b) {
    asm("fma.rn.f32x2 %0, %1, %2, %0;" : "+l"(d) : "l"(a), "l"(b));
}
__device__ __forceinline__ void rank1_64(u64* acc, float s, const float* wrow) {
    u64 s2 = pk2(s, s);
    const ulonglong2* w = reinterpret_cast<const ulonglong2*>(wrow);
#pragma unroll
    for (int t = 0; t < 16; t++) {
        ulonglong2 ww = w[t];
        fma2(acc[2*t],   s2, ww.x);
        fma2(acc[2*t+1], s2, ww.y);
    }
}
__device__ __forceinline__ float dot64(const u64* a, const float* wrow) {
    u64 s = 0ull;
    const ulonglong2* w = reinterpret_cast<const ulonglong2*>(wrow);
#pragma unroll
    for (int t = 0; t < 16; t++) {
        ulonglong2 ww = w[t];
        fma2(s, a[2*t],   ww.x);
        fma2(s, a[2*t+1], ww.y);
    }
    float lo, hi; up2(s, lo, hi); return lo + hi;
}
// column update: 2 rows x 16 outputs (8 u64 accumulators per row)
__device__ __forceinline__ void colupd(u64* a0, u64* a1, float s0, float s1,
                                       const float* wp) {
    u64 p0 = pk2(s0, s0), p1 = pk2(s1, s1);
    const ulonglong2* w = reinterpret_cast<const ulonglong2*>(wp);
    ulonglong2 wa = w[0], wb = w[1], wc = w[2], wd = w[3];
    fma2(a0[0], p0, wa.x); fma2(a1[0], p1, wa.x);
    fma2(a0[1], p0, wa.y); fma2(a1[1], p1, wa.y);
    fma2(a0[2], p0, wb.x); fma2(a1[2], p1, wb.x);
    fma2(a0[3], p0, wb.y); fma2(a1[3], p1, wb.y);
    fma2(a0[4], p0, wc.x); fma2(a1[4], p1, wc.x);
    fma2(a0[5], p0, wc.y); fma2(a1[5], p1, wc.y);
    fma2(a0[6], p0, wd.x); fma2(a1[6], p1, wd.x);
    fma2(a0[7], p0, wd.y); fma2(a1[7], p1, wd.y);
}
__device__ __forceinline__ float4 relu4(u64 a, u64 b) {
    float x, y, z, w; up2(a, x, y); up2(b, z, w);
    return make_float4(fmaxf(x, 0.f), fmaxf(y, 0.f), fmaxf(z, 0.f), fmaxf(w, 0.f));
}
__device__ __forceinline__ float4 raw4(u64 a, u64 b) {
    float x, y, z, w; up2(a, x, y); up2(b, z, w);
    return make_float4(x, y, z, w);
}
__device__ __forceinline__ void red4(float* p, float a, float b, float c, float d) {
    asm volatile("red.global.add.v4.f32 [%0], {%1,%2,%3,%4};"
                 :: "l"(p), "f"(a), "f"(b), "f"(c), "f"(d) : "memory");
}
__device__ __forceinline__ unsigned fenc(float f) {
    unsigned u = __float_as_uint(f);
    return (u & 0x80000000u) ? ~u : (u | 0x80000000u);
}
__device__ __forceinline__ float fdec(unsigned u) {
    return __uint_as_float((u & 0x80000000u) ? (u & 0x7FFFFFFFu) : ~u);
}

// ---------------- scratch ------------------------------------------------------
__device__ float g_nf  [N_NODES * D];
__device__ float g_qk  [N_NODES * D];
__device__ float g_qb  [N_NODES];
__device__ float g_tf  [(size_t)N_EDGES * D];   // 204.8MB streamed tf
__device__ float g_attn[N_EDGES];
__device__ float g_ex  [N_EDGES];
__device__ int   g_clu [N_EDGES];
__device__ unsigned g_m[NSEG];
__device__ float g_denom[NSEG];
__device__ float g_cnt  [NSEG];
__device__ float g_sinv [NSEG];                 // 1/(denom*cnt*nne)
__device__ float g_cec  [NC];
__device__ float g_accN [N_NODES * D];          // per-node weighted tf sum
__device__ float g_fused[N_NODES * D];
__device__ float g_Wqk[D * D], g_bqk[D], g_wqb[D], g_sqb;
__device__ float g_Wvo[D * D], g_bvo[D];

// ---------------- K0: zero scratch ---------------------------------------------
__global__ void k_init() {
    int i = blockIdx.x * blockDim.x + threadIdx.x;
    int stride = gridDim.x * blockDim.x;
    float4 z = make_float4(0.f, 0.f, 0.f, 0.f);
    for (int t = i; t < N_NODES * D / 4; t += stride)
        reinterpret_cast<float4*>(g_accN)[t] = z;
    for (int t = i; t < NSEG; t += stride) {
        g_denom[t] = 0.f; g_cnt[t] = 0.f; g_m[t] = 0u;
    }
    if (i < NC) g_cec[i] = 0.f;
}

// ---------------- K1: fold weights ---------------------------------------------
__global__ void k_prep(const float* __restrict__ Wq, const float* __restrict__ bq,
                       const float* __restrict__ Wk, const float* __restrict__ bk,
                       const float* __restrict__ Wv, const float* __restrict__ bv,
                       const float* __restrict__ Wo, const float* __restrict__ bo) {
    int idx = blockIdx.x * blockDim.x + threadIdx.x;
    if (idx < D * D) {
        int t = idx >> 6, j = idx & 63;
        float s1 = 0.f, s2 = 0.f;
        for (int d = 0; d < D; d++) {
            s1 = fmaf(Wq[t * D + d], Wk[j * D + d], s1);
            s2 = fmaf(Wv[t * D + d], Wo[d * D + j], s2);
        }
        g_Wqk[t * D + j] = s1;
        g_Wvo[t * D + j] = s2;
    }
    if (idx < D) {
        int j = idx;
        float a = 0.f, b = 0.f, c = 0.f;
        for (int d = 0; d < D; d++) {
            a = fmaf(bq[d], Wk[j * D + d], a);
            b = fmaf(bv[d], Wo[d * D + j], b);
            c = fmaf(Wq[j * D + d], bk[d], c);
        }
        g_bqk[j] = a; g_bvo[j] = b; g_wqb[j] = c;
        if (idx == 0) {
            float s = 0.f;
            for (int d = 0; d < D; d++) s = fmaf(bq[d], bk[d], s);
            g_sqb = s;
        }
    }
}

// ---------------- K2: nf = relu(x @ Wd + bd)   [2 rows x 16 outs / thread] ------
__global__ __launch_bounds__(256) void k_nodeA1(const float* __restrict__ x,
                                                const float* __restrict__ Wd,
                                                const float* __restrict__ bd) {
    extern __shared__ float smem[];
    float* sW = smem;                 // 256*64
    float* sb = smem + IN_CH * D;
    for (int t = threadIdx.x; t < IN_CH * D / 4; t += 256)
        reinterpret_cast<float4*>(sW)[t] = reinterpret_cast<const float4*>(Wd)[t];
    if (threadIdx.x < D) sb[threadIdx.x] = bd[threadIdx.x];
    __syncthreads();
    int tid = blockIdx.x * 256 + threadIdx.x;
    if (tid >= (N_NODES / 2) * 4) return;
    int q = tid & 3, p = tid >> 2;
    int n0 = 2 * p;

    u64 a0[8], a1[8];
    const u64* bb = reinterpret_cast<const u64*>(sb + q * 16);
#pragma unroll
    for (int k = 0; k < 8; k++) { a0[k] = bb[k]; a1[k] = bb[k]; }

    const float4* x0 = reinterpret_cast<const float4*>(x + (size_t)n0 * IN_CH);
    const float4* x1 = x0 + IN_CH / 4;
    const float* wq = sW + q * 16;
#pragma unroll 4
    for (int jv = 0; jv < IN_CH / 4; jv++) {
        float4 v0 = x0[jv], v1 = x1[jv];
        const float* w0 = wq + (4 * jv) * D;
        colupd(a0, a1, v0.x, v1.x, w0);
        colupd(a0, a1, v0.y, v1.y, w0 + D);
        colupd(a0, a1, v0.z, v1.z, w0 + 2 * D);
        colupd(a0, a1, v0.w, v1.w, w0 + 3 * D);
    }
    float4* o0 = reinterpret_cast<float4*>(g_nf + (size_t)n0 * D + q * 16);
    float4* o1 = reinterpret_cast<float4*>(g_nf + (size_t)(n0 + 1) * D + q * 16);
#pragma unroll
    for (int k = 0; k < 4; k++) {
        o0[k] = relu4(a0[2*k], a0[2*k+1]);
        o1[k] = relu4(a1[2*k], a1[2*k+1]);
    }
}

// ---------------- K3: qk = nf @ Wqk + bqk ; qb = nf.wqb + sqb -------------------
__global__ __launch_bounds__(256) void k_nodeA2() {
    extern __shared__ float smem[];
    float* sW  = smem;            // 64*64
    float* sbq = smem + D * D;
    float* swq = sbq + D;
    for (int t = threadIdx.x; t < D * D / 4; t += 256)
        reinterpret_cast<float4*>(sW)[t] = reinterpret_cast<const float4*>(g_Wqk)[t];
    if (threadIdx.x < D) { sbq[threadIdx.x] = g_bqk[threadIdx.x]; swq[threadIdx.x] = g_wqb[threadIdx.x]; }
    __syncthreads();
    int tid = blockIdx.x * 256 + threadIdx.x;
    if (tid >= (N_NODES / 2) * 4) return;
    int q = tid & 3, p = tid >> 2;
    int n0 = 2 * p;

    u64 a0[8], a1[8];
    const u64* bb = reinterpret_cast<const u64*>(sbq + q * 16);
#pragma unroll
    for (int k = 0; k < 8; k++) { a0[k] = bb[k]; a1[k] = bb[k]; }
    float qb0 = g_sqb, qb1 = g_sqb;

    const float4* x0 = reinterpret_cast<const float4*>(g_nf + (size_t)n0 * D);
    const float4* x1 = x0 + D / 4;
    const float* wq = sW + q * 16;
#pragma unroll 4
    for (int jv = 0; jv < D / 4; jv++) {
        float4 v0 = x0[jv], v1 = x1[jv];
        const float* w0 = wq + (4 * jv) * D;
        colupd(a0, a1, v0.x, v1.x, w0);
        colupd(a0, a1, v0.y, v1.y, w0 + D);
        colupd(a0, a1, v0.z, v1.z, w0 + 2 * D);
        colupd(a0, a1, v0.w, v1.w, w0 + 3 * D);
        qb0 = fmaf(v0.x, swq[4*jv], fmaf(v0.y, swq[4*jv+1], fmaf(v0.z, swq[4*jv+2], fmaf(v0.w, swq[4*jv+3], qb0))));
        qb1 = fmaf(v1.x, swq[4*jv], fmaf(v1.y, swq[4*jv+1], fmaf(v1.z, swq[4*jv+2], fmaf(v1.w, swq[4*jv+3], qb1))));
    }
    float4* o0 = reinterpret_cast<float4*>(g_qk + (size_t)n0 * D + q * 16);
    float4* o1 = reinterpret_cast<float4*>(g_qk + (size_t)(n0 + 1) * D + q * 16);
#pragma unroll
    for (int k = 0; k < 4; k++) {
        o0[k] = raw4(a0[2*k], a0[2*k+1]);
        o1[k] = raw4(a1[2*k], a1[2*k+1]);
    }
    if (q == 0) { g_qb[n0] = qb0; g_qb[n0 + 1] = qb1; }
}

// per-edge time_feat (packed, relu applied)
__device__ __forceinline__ void edge_tf(u64* acc, const float* __restrict__ ea, int e,
                                        const float* sW, const float* sb) {
    const u64* sb2 = reinterpret_cast<const u64*>(sb);
#pragma unroll
    for (int t = 0; t < 32; t++) acc[t] = sb2[t];
    const float4* ar = reinterpret_cast<const float4*>(ea + (size_t)e * 16);
#pragma unroll
    for (int jv = 0; jv < 4; jv++) {
        float4 a = ar[jv];
        const float* w0 = sW + (jv * 4) * D;
        rank1_64(acc, a.x, w0);
        rank1_64(acc, a.y, w0 + D);
        rank1_64(acc, a.z, w0 + 2 * D);
        rank1_64(acc, a.w, w0 + 3 * D);
    }
#pragma unroll
    for (int t = 0; t < 32; t++) {
        float lo, hi; up2(acc[t], lo, hi);
        acc[t] = pk2(fmaxf(lo, 0.f), fmaxf(hi, 0.f));
    }
}

// ---------------- K4: pass1 — tf, cluster, attn, seg max; store tf --------------
__global__ __launch_bounds__(256) void k_edge1(const float* __restrict__ ea,
                                               const int* __restrict__ ei,
                                               const float* __restrict__ Wt,
                                               const float* __restrict__ bt,
                                               const float* __restrict__ ce) {
    extern __shared__ float smem[];
    float* sW = smem;            // 16*64
    float* sb = sW + 16 * D;     // 64
    float* sc = sb + D;          // 8*64
    for (int t = threadIdx.x; t < 16 * D / 4; t += 256)
        reinterpret_cast<float4*>(sW)[t] = reinterpret_cast<const float4*>(Wt)[t];
    if (threadIdx.x < D) sb[threadIdx.x] = bt[threadIdx.x];
    for (int t = threadIdx.x; t < NC * D / 4; t += 256)
        reinterpret_cast<float4*>(sc)[t] = reinterpret_cast<const float4*>(ce)[t];
    __syncthreads();
    int e = blockIdx.x * 256 + threadIdx.x;
    if (e >= N_EDGES) return;

    u64 tf[32];
    edge_tf(tf, ea, e, sW, sb);

    int bc = 0; float bv = dot64(tf, sc);
#pragma unroll
    for (int c = 1; c < NC; c++) {
        float s = dot64(tf, sc + c * D);
        if (s > bv) { bv = s; bc = c; }
    }

    int src = ei[e];
    const float4* qr = reinterpret_cast<const float4*>(g_qk + (size_t)src * D);
    u64 s = 0ull;
#pragma unroll
    for (int tv = 0; tv < 16; tv++) {
        float4 qv = qr[tv];
        fma2(s, tf[2*tv],   pk2(qv.x, qv.y));
        fma2(s, tf[2*tv+1], pk2(qv.z, qv.w));
    }
    float lo, hi; up2(s, lo, hi);
    float attn = (lo + hi + g_qb[src]) * 0.125f;

    g_attn[e] = attn;
    g_clu[e] = bc;
    atomicMax(&g_m[src * NC + bc], fenc(attn));

    float4* tp = reinterpret_cast<float4*>(g_tf + (size_t)e * D);
#pragma unroll
    for (int tv = 0; tv < 16; tv++) tp[tv] = raw4(tf[2*tv], tf[2*tv+1]);
}

// ---------------- K5: pass2 — ex, denom, cnt, cec (scalar only) -----------------
__global__ void k_pass2(const int* __restrict__ ei) {
    __shared__ float scec[NC];
    if (threadIdx.x < NC) scec[threadIdx.x] = 0.f;
    __syncthreads();
    int e = blockIdx.x * blockDim.x + threadIdx.x;
    if (e < N_EDGES) {
        int src = ei[e];
        int c = g_clu[e];
        int seg = src * NC + c;
        float m = fdec(g_m[seg]);
        float ex = expf(g_attn[e] - m);
        g_ex[e] = ex;
        atomicAdd(&g_denom[seg], ex);
        atomicAdd(&g_cnt[seg], 1.0f);
        atomicAdd(&scec[c], 1.0f);
    }
    __syncthreads();
    if (threadIdx.x < NC) atomicAdd(&g_cec[threadIdx.x], scec[threadIdx.x]);
}

// ---------------- K6: per-segment inverse coefficient ---------------------------
__global__ void k_seginv() {
    int i = blockIdx.x * blockDim.x + threadIdx.x;
    if (i >= NSEG) return;
    float nne = 0.f;
#pragma unroll
    for (int c = 0; c < NC; c++) nne += (g_cec[c] > 0.f) ? 1.f : 0.f;
    float cnt = g_cnt[i];
    g_sinv[i] = (cnt > 0.f) ? 1.0f / (g_denom[i] * cnt * nne) : 0.f;
}

// ---------------- K7: pass3 — accumulate coef*tf into per-node sum --------------
__global__ __launch_bounds__(256) void k_pass3(const int* __restrict__ ei) {
    int e = blockIdx.x * 256 + threadIdx.x;
    if (e >= N_EDGES) return;
    int src = ei[e];
    int c = g_clu[e];
    float coef = g_ex[e] * g_sinv[src * NC + c];
    const float4* tp = reinterpret_cast<const float4*>(g_tf + (size_t)e * D);
    float* base = g_accN + (size_t)src * D;
#pragma unroll
    for (int tv = 0; tv < 16; tv++) {
        float4 v = tp[tv];
        red4(base + tv * 4, v.x * coef, v.y * coef, v.z * coef, v.w * coef);
    }
}

// ---------------- K8: fused = relu(accN @ Wvo + bvo*bsc/nne + b_out) ------------
__global__ __launch_bounds__(256) void k_E2(const float* __restrict__ bo) {
    extern __shared__ float smem[];
    float* sW  = smem;            // 64*64 Wvo
    float* sbv = smem + D * D;
    float* sbo = sbv + D;
    for (int t = threadIdx.x; t < D * D / 4; t += 256)
        reinterpret_cast<float4*>(sW)[t] = reinterpret_cast<const float4*>(g_Wvo)[t];
    if (threadIdx.x < D) { sbv[threadIdx.x] = g_bvo[threadIdx.x]; sbo[threadIdx.x] = bo[threadIdx.x]; }
    __syncthreads();
    int tid = blockIdx.x * 256 + threadIdx.x;
    if (tid >= (N_NODES / 2) * 4) return;
    int q = tid & 3, p = tid >> 2;
    int n0 = 2 * p;

    float nne = 0.f;
#pragma unroll
    for (int c = 0; c < NC; c++) nne += (g_cec[c] > 0.f) ? 1.f : 0.f;
    float inv = 1.0f / nne;
    float bs0 = 0.f, bs1 = 0.f;
#pragma unroll
    for (int c = 0; c < NC; c++) {
        float c0 = g_cnt[n0 * NC + c];
        float c1 = g_cnt[(n0 + 1) * NC + c];
        if (c0 > 0.f) bs0 += 1.0f / c0;
        if (c1 > 0.f) bs1 += 1.0f / c1;
    }
    bs0 *= inv; bs1 *= inv;

    u64 a0[8], a1[8];
    const float* bvq = sbv + q * 16;
    const float* boq = sbo + q * 16;
#pragma unroll
    for (int k = 0; k < 8; k++) {
        a0[k] = pk2(fmaf(bvq[2*k], bs0, boq[2*k]), fmaf(bvq[2*k+1], bs0, boq[2*k+1]));
        a1[k] = pk2(fmaf(bvq[2*k], bs1, boq[2*k]), fmaf(bvq[2*k+1], bs1, boq[2*k+1]));
    }
    // note: accN already has 1/nne folded in via g_sinv
    const float4* x0 = reinterpret_cast<const float4*>(g_accN + (size_t)n0 * D);
    const float4* x1 = x0 + D / 4;
    const float* wq = sW + q * 16;
#pragma unroll 4
    for (int jv = 0; jv < D / 4; jv++) {
        float4 v0 = x0[jv], v1 = x1[jv];
        const float* w0 = wq + (4 * jv) * D;
        colupd(a0, a1, v0.x, v1.x, w0);
        colupd(a0, a1, v0.y, v1.y, w0 + D);
        colupd(a0, a1, v0.z, v1.z, w0 + 2 * D);
        colupd(a0, a1, v0.w, v1.w, w0 + 3 * D);
    }
    float4* o0 = reinterpret_cast<float4*>(g_fused + (size_t)n0 * D + q * 16);
    float4* o1 = reinterpret_cast<float4*>(g_fused + (size_t)(n0 + 1) * D + q * 16);
#pragma unroll
    for (int k = 0; k < 4; k++) {
        o0[k] = relu4(a0[2*k], a0[2*k+1]);
        o1[k] = relu4(a1[2*k], a1[2*k+1]);
    }
}

// ---------------- K9: out = x + fused @ W_up + b_up -----------------------------
__global__ __launch_bounds__(256) void k_E3(const float* __restrict__ x,
                                            const float* __restrict__ Wup,
                                            const float* __restrict__ bup,
                                            float* __restrict__ out) {
    extern __shared__ float smem[];
    float* sW = smem;                 // 64*256
    float* sb = smem + D * IN_CH;     // 256
    for (int t = threadIdx.x; t < D * IN_CH / 4; t += 256)
        reinterpret_cast<float4*>(sW)[t] = reinterpret_cast<const float4*>(Wup)[t];
    if (threadIdx.x < IN_CH) sb[threadIdx.x] = bup[threadIdx.x];
    __syncthreads();
    int tid = blockIdx.x * 256 + threadIdx.x;
    if (tid >= (N_NODES / 2) * 16) return;
    int ch = tid & 15, p = tid >> 4;
    int n0 = 2 * p;

    u64 a0[8], a1[8];
    const u64* bb = reinterpret_cast<const u64*>(sb + ch * 16);
#pragma unroll
    for (int k = 0; k < 8; k++) { a0[k] = bb[k]; a1[k] = bb[k]; }

    const float4* f0 = reinterpret_cast<const float4*>(g_fused + (size_t)n0 * D);
    const float4* f1 = f0 + D / 4;
    const float* wc = sW + ch * 16;
#pragma unroll 4
    for (int jv = 0; jv < D / 4; jv++) {
        float4 v0 = f0[jv], v1 = f1[jv];
        const float* w0 = wc + (4 * jv) * IN_CH;
        colupd(a0, a1, v0.x, v1.x, w0);
        colupd(a0, a1, v0.y, v1.y, w0 + IN_CH);
        colupd(a0, a1, v0.z, v1.z, w0 + 2 * IN_CH);
        colupd(a0, a1, v0.w, v1.w, w0 + 3 * IN_CH);
    }
    const float4* xr0 = reinterpret_cast<const float4*>(x + (size_t)n0 * IN_CH + ch * 16);
    const float4* xr1 = reinterpret_cast<const float4*>(x + (size_t)(n0 + 1) * IN_CH + ch * 16);
    float4* o0 = reinterpret_cast<float4*>(out + (size_t)n0 * IN_CH + ch * 16);
    float4* o1 = reinterpret_cast<float4*>(out + (size_t)(n0 + 1) * IN_CH + ch * 16);
#pragma unroll
    for (int k = 0; k < 4; k++) {
        float4 r0 = raw4(a0[2*k], a0[2*k+1]);
        float4 r1 = raw4(a1[2*k], a1[2*k+1]);
        float4 xv0 = xr0[k], xv1 = xr1[k];
        o0[k] = make_float4(xv0.x + r0.x, xv0.y + r0.y, xv0.z + r0.z, xv0.w + r0.w);
        o1[k] = make_float4(xv1.x + r1.x, xv1.y + r1.y, xv1.z + r1.z, xv1.w + r1.w);
    }
}

// -------------------------------------------------------------------------------
extern "C" void kernel_launch(void* const* d_in, const int* in_sizes, int n_in,
                              void* d_out, int out_size) {
    const float* x   = (const float*)d_in[0];
    const float* ea  = (const float*)d_in[1];
    const int*   ei  = (const int*)  d_in[2];
    const float* Wd  = (const float*)d_in[3];
    const float* bd  = (const float*)d_in[4];
    const float* Wup = (const float*)d_in[5];
    const float* bup = (const float*)d_in[6];
    const float* Wt  = (const float*)d_in[7];
    const float* bt  = (const float*)d_in[8];
    const float* Wq  = (const float*)d_in[9];
    const float* bq  = (const float*)d_in[10];
    const float* Wk  = (const float*)d_in[11];
    const float* bk  = (const float*)d_in[12];
    const float* Wv  = (const float*)d_in[13];
    const float* bv  = (const float*)d_in[14];
    const float* ce  = (const float*)d_in[15];
    const float* Wo  = (const float*)d_in[16];
    const float* bo  = (const float*)d_in[17];
    float* out = (float*)d_out;

    int smA1 = (IN_CH * D + D) * 4;            // 65792
    int smA2 = (D * D + 2 * D) * 4;            // 16896
    int smE1 = (16 * D + D + NC * D) * 4;      // 6400
    int smE2 = (D * D + 2 * D) * 4;            // 16896
    int smE3 = (D * IN_CH + IN_CH) * 4;        // 66560
    cudaFuncSetAttribute(k_nodeA1, cudaFuncAttributeMaxDynamicSharedMemorySize, smA1);
    cudaFuncSetAttribute(k_E3,     cudaFuncAttributeMaxDynamicSharedMemorySize, smE3);

    k_init  <<<512, 256>>>();
    k_prep  <<<16, 256>>>(Wq, bq, Wk, bk, Wv, bv, Wo, bo);
    k_nodeA1<<<(N_NODES / 2 * 4 + 255) / 256, 256, smA1>>>(x, Wd, bd);
    k_nodeA2<<<(N_NODES / 2 * 4 + 255) / 256, 256, smA2>>>();
    k_edge1 <<<(N_EDGES + 255) / 256, 256, smE1>>>(ea, ei, Wt, bt, ce);
    k_pass2 <<<(N_EDGES + 255) / 256, 256>>>(ei);
    k_seginv<<<(NSEG + 255) / 256, 256>>>();
    k_pass3 <<<(N_EDGES + 255) / 256, 256>>>(ei);
    k_E2    <<<(N_NODES / 2 * 4 + 255) / 256, 256, smE2>>>(bo);
    k_E3    <<<(N_NODES / 2 * 16 + 255) / 256, 256, smE3>>>(x, Wup, bup, out);
}

// round 3
// speedup vs baseline: 1.4314x; 1.2453x over previous
#include <cuda_runtime.h>
#include <math.h>

#define N_NODES 50000
#define N_EDGES 800000
#define IN_CH   256
#define D       64
#define NC      8
#define SLOT_CAP 128

typedef unsigned long long u64;

// ---------------- f32x2 packed helpers ----------------------------------------
__device__ __forceinline__ u64 pk2(float lo, float hi) {
    u64 r; asm("mov.b64 %0, {%1, %2};" : "=l"(r) : "f"(lo), "f"(hi)); return r;
}
__device__ __forceinline__ void up2(u64 v, float& lo, float& hi) {
    asm("mov.b64 {%0, %1}, %2;" : "=f"(lo), "=f"(hi) : "l"(v));
}
__device__ __forceinline__ void fma2(u64& d, u64 a, u64 b) {
    asm("fma.rn.f32x2 %0, %1, %2, %0;" : "+l"(d) : "l"(a), "l"(b));
}
__device__ __forceinline__ void rank1_64(u64* acc, float s, const float* wrow) {
    u64 s2 = pk2(s, s);
    const ulonglong2* w = reinterpret_cast<const ulonglong2*>(wrow);
#pragma unroll
    for (int t = 0; t < 16; t++) {
        ulonglong2 ww = w[t];
        fma2(acc[2*t],   s2, ww.x);
        fma2(acc[2*t+1], s2, ww.y);
    }
}
__device__ __forceinline__ float dot64(const u64* a, const float* wrow) {
    u64 s = 0ull;
    const ulonglong2* w = reinterpret_cast<const ulonglong2*>(wrow);
#pragma unroll
    for (int t = 0; t < 16; t++) {
        ulonglong2 ww = w[t];
        fma2(s, a[2*t],   ww.x);
        fma2(s, a[2*t+1], ww.y);
    }
    float lo, hi; up2(s, lo, hi); return lo + hi;
}
// 2 rows x 16 outputs per input column; wp is WARP-UNIFORM (broadcast LDS)
__device__ __forceinline__ void colupd(u64* a0, u64* a1, float s0, float s1,
                                       const float* wp) {
    u64 p0 = pk2(s0, s0), p1 = pk2(s1, s1);
    const ulonglong2* w = reinterpret_cast<const ulonglong2*>(wp);
    ulonglong2 wa = w[0], wb = w[1], wc = w[2], wd = w[3];
    fma2(a0[0], p0, wa.x); fma2(a1[0], p1, wa.x);
    fma2(a0[1], p0, wa.y); fma2(a1[1], p1, wa.y);
    fma2(a0[2], p0, wb.x); fma2(a1[2], p1, wb.x);
    fma2(a0[3], p0, wb.y); fma2(a1[3], p1, wb.y);
    fma2(a0[4], p0, wc.x); fma2(a1[4], p1, wc.x);
    fma2(a0[5], p0, wc.y); fma2(a1[5], p1, wc.y);
    fma2(a0[6], p0, wd.x); fma2(a1[6], p1, wd.x);
    fma2(a0[7], p0, wd.y); fma2(a1[7], p1, wd.y);
}
__device__ __forceinline__ float4 relu4(u64 a, u64 b) {
    float x, y, z, w; up2(a, x, y); up2(b, z, w);
    return make_float4(fmaxf(x, 0.f), fmaxf(y, 0.f), fmaxf(z, 0.f), fmaxf(w, 0.f));
}
__device__ __forceinline__ float4 raw4(u64 a, u64 b) {
    float x, y, z, w; up2(a, x, y); up2(b, z, w);
    return make_float4(x, y, z, w);
}

// ---------------- scratch ------------------------------------------------------
__device__ float g_nf  [N_NODES * D];
__device__ float g_qk  [N_NODES * D];
__device__ float g_qb  [N_NODES];
__device__ float g_tf  [(size_t)N_EDGES * D];       // 204.8MB
__device__ int   g_deg [N_NODES];
__device__ u64   g_slot_ac [(size_t)N_NODES * SLOT_CAP];  // {attn, cluster}
__device__ int   g_slot_eid[(size_t)N_NODES * SLOT_CAP];
__device__ float g_cec [NC];
__device__ float g_accN[N_NODES * D];
__device__ float g_bsc [N_NODES];
__device__ float g_fused[N_NODES * D];
__device__ float g_Wqk[D * D], g_bqk[D], g_wqb[D], g_sqb;
__device__ float g_Wvo[D * D], g_bvo[D];

// ---------------- K0: zero deg + cec -------------------------------------------
__global__ void k_init() {
    int i = blockIdx.x * blockDim.x + threadIdx.x;
    if (i < N_NODES) g_deg[i] = 0;
    if (i < NC) g_cec[i] = 0.f;
}

// ---------------- K1: fold weights ---------------------------------------------
__global__ void k_prep(const float* __restrict__ Wq, const float* __restrict__ bq,
                       const float* __restrict__ Wk, const float* __restrict__ bk,
                       const float* __restrict__ Wv, const float* __restrict__ bv,
                       const float* __restrict__ Wo, const float* __restrict__ bo) {
    int idx = blockIdx.x * blockDim.x + threadIdx.x;
    if (idx < D * D) {
        int t = idx >> 6, j = idx & 63;
        float s1 = 0.f, s2 = 0.f;
        for (int d = 0; d < D; d++) {
            s1 = fmaf(Wq[t * D + d], Wk[j * D + d], s1);
            s2 = fmaf(Wv[t * D + d], Wo[d * D + j], s2);
        }
        g_Wqk[t * D + j] = s1;
        g_Wvo[t * D + j] = s2;
    }
    if (idx < D) {
        int j = idx;
        float a = 0.f, b = 0.f, c = 0.f;
        for (int d = 0; d < D; d++) {
            a = fmaf(bq[d], Wk[j * D + d], a);
            b = fmaf(bv[d], Wo[d * D + j], b);
            c = fmaf(Wq[j * D + d], bk[d], c);
        }
        g_bqk[j] = a; g_bvo[j] = b; g_wqb[j] = c;
        if (idx == 0) {
            float s = 0.f;
            for (int d = 0; d < D; d++) s = fmaf(bq[d], bk[d], s);
            g_sqb = s;
        }
    }
}

// ---------------- K2: nf = relu(x @ Wd + bd)  [warp-uniform weight chunks] ------
// block = 256 thr = 8 warps: q = wid&3 (output chunk), grp = wid>>2
// lanes own node rows: r0 = blk*128 + grp*64 + lane, r1 = r0 + 32
__global__ __launch_bounds__(256) void k_nodeA1(const float* __restrict__ x,
                                                const float* __restrict__ Wd,
                                                const float* __restrict__ bd) {
    extern __shared__ float smem[];
    float* sW = smem;                 // 256*64
    float* sb = smem + IN_CH * D;     // 64
    for (int t = threadIdx.x; t < IN_CH * D / 4; t += 256)
        reinterpret_cast<float4*>(sW)[t] = reinterpret_cast<const float4*>(Wd)[t];
    if (threadIdx.x < D) sb[threadIdx.x] = bd[threadIdx.x];
    __syncthreads();
    int wid = threadIdx.x >> 5, lane = threadIdx.x & 31;
    int q = wid & 3, grp = wid >> 2;
    int r0 = blockIdx.x * 128 + grp * 64 + lane;
    int r1 = r0 + 32;
    int r0c = min(r0, N_NODES - 1), r1c = min(r1, N_NODES - 1);

    u64 a0[8], a1[8];
    const u64* bb = reinterpret_cast<const u64*>(sb + q * 16);
#pragma unroll
    for (int k = 0; k < 8; k++) { a0[k] = bb[k]; a1[k] = bb[k]; }

    const float4* x0 = reinterpret_cast<const float4*>(x + (size_t)r0c * IN_CH);
    const float4* x1 = reinterpret_cast<const float4*>(x + (size_t)r1c * IN_CH);
    const float* wq = sW + q * 16;
#pragma unroll 4
    for (int jv = 0; jv < IN_CH / 4; jv++) {
        float4 v0 = x0[jv], v1 = x1[jv];
        const float* w0 = wq + (4 * jv) * D;
        colupd(a0, a1, v0.x, v1.x, w0);
        colupd(a0, a1, v0.y, v1.y, w0 + D);
        colupd(a0, a1, v0.z, v1.z, w0 + 2 * D);
        colupd(a0, a1, v0.w, v1.w, w0 + 3 * D);
    }
    if (r0 < N_NODES) {
        float4* o0 = reinterpret_cast<float4*>(g_nf + (size_t)r0 * D + q * 16);
#pragma unroll
        for (int k = 0; k < 4; k++) o0[k] = relu4(a0[2*k], a0[2*k+1]);
    }
    if (r1 < N_NODES) {
        float4* o1 = reinterpret_cast<float4*>(g_nf + (size_t)r1 * D + q * 16);
#pragma unroll
        for (int k = 0; k < 4; k++) o1[k] = relu4(a1[2*k], a1[2*k+1]);
    }
}

// ---------------- K3: qk = nf @ Wqk + bqk ; qb = nf.wqb + sqb -------------------
__global__ __launch_bounds__(256) void k_nodeA2() {
    extern __shared__ float smem[];
    float* sW  = smem;            // 64*64
    float* sbq = smem + D * D;
    float* swq = sbq + D;
    for (int t = threadIdx.x; t < D * D / 4; t += 256)
        reinterpret_cast<float4*>(sW)[t] = reinterpret_cast<const float4*>(g_Wqk)[t];
    if (threadIdx.x < D) { sbq[threadIdx.x] = g_bqk[threadIdx.x]; swq[threadIdx.x] = g_wqb[threadIdx.x]; }
    __syncthreads();
    int wid = threadIdx.x >> 5, lane = threadIdx.x & 31;
    int q = wid & 3, grp = wid >> 2;
    int r0 = blockIdx.x * 128 + grp * 64 + lane;
    int r1 = r0 + 32;
    int r0c = min(r0, N_NODES - 1), r1c = min(r1, N_NODES - 1);

    u64 a0[8], a1[8];
    const u64* bb = reinterpret_cast<const u64*>(sbq + q * 16);
#pragma unroll
    for (int k = 0; k < 8; k++) { a0[k] = bb[k]; a1[k] = bb[k]; }

    const float4* x0 = reinterpret_cast<const float4*>(g_nf + (size_t)r0c * D);
    const float4* x1 = reinterpret_cast<const float4*>(g_nf + (size_t)r1c * D);
    const float* wq = sW + q * 16;
#pragma unroll 4
    for (int jv = 0; jv < D / 4; jv++) {
        float4 v0 = x0[jv], v1 = x1[jv];
        const float* w0 = wq + (4 * jv) * D;
        colupd(a0, a1, v0.x, v1.x, w0);
        colupd(a0, a1, v0.y, v1.y, w0 + D);
        colupd(a0, a1, v0.z, v1.z, w0 + 2 * D);
        colupd(a0, a1, v0.w, v1.w, w0 + 3 * D);
    }
    if (r0 < N_NODES) {
        float4* o0 = reinterpret_cast<float4*>(g_qk + (size_t)r0 * D + q * 16);
#pragma unroll
        for (int k = 0; k < 4; k++) o0[k] = raw4(a0[2*k], a0[2*k+1]);
    }
    if (r1 < N_NODES) {
        float4* o1 = reinterpret_cast<float4*>(g_qk + (size_t)r1 * D + q * 16);
#pragma unroll
        for (int k = 0; k < 4; k++) o1[k] = raw4(a1[2*k], a1[2*k+1]);
    }
    if (q == 0) {   // qb: re-read rows (L1-hot), only 2 of 8 warps
        float qb0 = g_sqb, qb1 = g_sqb;
#pragma unroll 4
        for (int jv = 0; jv < D / 4; jv++) {
            float4 v0 = x0[jv], v1 = x1[jv];
            qb0 = fmaf(v0.x, swq[4*jv], fmaf(v0.y, swq[4*jv+1], fmaf(v0.z, swq[4*jv+2], fmaf(v0.w, swq[4*jv+3], qb0))));
            qb1 = fmaf(v1.x, swq[4*jv], fmaf(v1.y, swq[4*jv+1], fmaf(v1.z, swq[4*jv+2], fmaf(v1.w, swq[4*jv+3], qb1))));
        }
        if (r0 < N_NODES) g_qb[r0] = qb0;
        if (r1 < N_NODES) g_qb[r1] = qb1;
    }
}

// per-edge time_feat (weights warp-uniform already)
__device__ __forceinline__ void edge_tf(u64* acc, const float* __restrict__ ea, int e,
                                        const float* sW, const float* sb) {
    const u64* sb2 = reinterpret_cast<const u64*>(sb);
#pragma unroll
    for (int t = 0; t < 32; t++) acc[t] = sb2[t];
    const float4* ar = reinterpret_cast<const float4*>(ea + (size_t)e * 16);
#pragma unroll
    for (int jv = 0; jv < 4; jv++) {
        float4 a = ar[jv];
        const float* w0 = sW + (jv * 4) * D;
        rank1_64(acc, a.x, w0);
        rank1_64(acc, a.y, w0 + D);
        rank1_64(acc, a.z, w0 + 2 * D);
        rank1_64(acc, a.w, w0 + 3 * D);
    }
#pragma unroll
    for (int t = 0; t < 32; t++) {
        float lo, hi; up2(acc[t], lo, hi);
        acc[t] = pk2(fmaxf(lo, 0.f), fmaxf(hi, 0.f));
    }
}

// ---------------- K4: edge pass — tf, cluster, attn, slot assignment ------------
__global__ __launch_bounds__(256) void k_edge1(const float* __restrict__ ea,
                                               const int* __restrict__ ei,
                                               const float* __restrict__ Wt,
                                               const float* __restrict__ bt,
                                               const float* __restrict__ ce) {
    extern __shared__ float smem[];
    float* sW = smem;            // 16*64
    float* sb = sW + 16 * D;     // 64
    float* sc = sb + D;          // 8*64
    float* scec = sc + NC * D;   // 8
    for (int t = threadIdx.x; t < 16 * D / 4; t += 256)
        reinterpret_cast<float4*>(sW)[t] = reinterpret_cast<const float4*>(Wt)[t];
    if (threadIdx.x < D) sb[threadIdx.x] = bt[threadIdx.x];
    for (int t = threadIdx.x; t < NC * D / 4; t += 256)
        reinterpret_cast<float4*>(sc)[t] = reinterpret_cast<const float4*>(ce)[t];
    if (threadIdx.x < NC) scec[threadIdx.x] = 0.f;
    __syncthreads();
    int e = blockIdx.x * 256 + threadIdx.x;   // N_EDGES % 256 == 0

    u64 tf[32];
    edge_tf(tf, ea, e, sW, sb);

    int bc = 0; float bv = dot64(tf, sc);
#pragma unroll
    for (int c = 1; c < NC; c++) {
        float s = dot64(tf, sc + c * D);
        if (s > bv) { bv = s; bc = c; }
    }

    int src = ei[e];
    const float4* qr = reinterpret_cast<const float4*>(g_qk + (size_t)src * D);
    u64 s = 0ull;
#pragma unroll
    for (int tv = 0; tv < 16; tv++) {
        float4 qv = qr[tv];
        fma2(s, tf[2*tv],   pk2(qv.x, qv.y));
        fma2(s, tf[2*tv+1], pk2(qv.z, qv.w));
    }
    float lo, hi; up2(s, lo, hi);
    float attn = (lo + hi + g_qb[src]) * 0.125f;

    atomicAdd(&scec[bc], 1.f);
    int slot = atomicAdd(&g_deg[src], 1);
    if (slot < SLOT_CAP) {
        size_t si = (size_t)src * SLOT_CAP + slot;
        g_slot_ac[si]  = pk2(attn, __int_as_float(bc));
        g_slot_eid[si] = e;
    }
    float4* tp = reinterpret_cast<float4*>(g_tf + (size_t)e * D);
#pragma unroll
    for (int tv = 0; tv < 16; tv++) tp[tv] = raw4(tf[2*tv], tf[2*tv+1]);

    __syncthreads();
    if (threadIdx.x < NC) atomicAdd(&g_cec[threadIdx.x], scec[threadIdx.x]);
}

// ---------------- K5: per-node gather — softmax + weighted tf sum ---------------
__global__ __launch_bounds__(256) void k_gather() {
    int n = blockIdx.x * 256 + threadIdx.x;
    if (n >= N_NODES) return;
    int deg = min(g_deg[n], SLOT_CAP);

    float nne = 0.f;
#pragma unroll
    for (int c = 0; c < NC; c++) nne += (g_cec[c] > 0.f) ? 1.f : 0.f;
    float inv = 1.0f / nne;

    const u64* ac = g_slot_ac + (size_t)n * SLOT_CAP;
    const int* eid = g_slot_eid + (size_t)n * SLOT_CAP;

    float cm[NC];
#pragma unroll
    for (int c = 0; c < NC; c++) cm[c] = -3.4e38f;
    for (int s = 0; s < deg; s++) {
        float a, cf; up2(ac[s], a, cf);
        int c = __float_as_int(cf);
        cm[c] = fmaxf(cm[c], a);
    }
    float den[NC], cnt[NC];
#pragma unroll
    for (int c = 0; c < NC; c++) { den[c] = 0.f; cnt[c] = 0.f; }
    for (int s = 0; s < deg; s++) {
        float a, cf; up2(ac[s], a, cf);
        int c = __float_as_int(cf);
        den[c] += __expf(a - cm[c]);
        cnt[c] += 1.f;
    }
    float sinv[NC]; float bsc = 0.f;
#pragma unroll
    for (int c = 0; c < NC; c++) {
        if (cnt[c] > 0.f) {
            sinv[c] = inv / (den[c] * cnt[c]);
            bsc += 1.0f / cnt[c];
        } else sinv[c] = 0.f;
    }
    g_bsc[n] = bsc * inv;

    u64 acc[32];
#pragma unroll
    for (int t = 0; t < 32; t++) acc[t] = 0ull;
    for (int s = 0; s < deg; s++) {
        float a, cf; up2(ac[s], a, cf);
        int c = __float_as_int(cf);
        float coef = __expf(a - cm[c]) * sinv[c];
        u64 c2 = pk2(coef, coef);
        const ulonglong2* tp = reinterpret_cast<const ulonglong2*>(g_tf + (size_t)eid[s] * D);
#pragma unroll
        for (int t = 0; t < 16; t++) {
            ulonglong2 tv = tp[t];
            fma2(acc[2*t],   c2, tv.x);
            fma2(acc[2*t+1], c2, tv.y);
        }
    }
    float4* outp = reinterpret_cast<float4*>(g_accN + (size_t)n * D);
#pragma unroll
    for (int t = 0; t < 16; t++) outp[t] = raw4(acc[2*t], acc[2*t+1]);
}

// ---------------- K6: fused = relu(accN @ Wvo + bvo*bsc + b_out) ----------------
__global__ __launch_bounds__(256) void k_E2(const float* __restrict__ bo) {
    extern __shared__ float smem[];
    float* sW  = smem;            // 64*64 Wvo
    float* sbv = smem + D * D;
    float* sbo = sbv + D;
    for (int t = threadIdx.x; t < D * D / 4; t += 256)
        reinterpret_cast<float4*>(sW)[t] = reinterpret_cast<const float4*>(g_Wvo)[t];
    if (threadIdx.x < D) { sbv[threadIdx.x] = g_bvo[threadIdx.x]; sbo[threadIdx.x] = bo[threadIdx.x]; }
    __syncthreads();
    int wid = threadIdx.x >> 5, lane = threadIdx.x & 31;
    int q = wid & 3, grp = wid >> 2;
    int r0 = blockIdx.x * 128 + grp * 64 + lane;
    int r1 = r0 + 32;
    int r0c = min(r0, N_NODES - 1), r1c = min(r1, N_NODES - 1);
    float bs0 = g_bsc[r0c], bs1 = g_bsc[r1c];

    u64 a0[8], a1[8];
    const float* bvq = sbv + q * 16;
    const float* boq = sbo + q * 16;
#pragma unroll
    for (int k = 0; k < 8; k++) {
        a0[k] = pk2(fmaf(bvq[2*k], bs0, boq[2*k]), fmaf(bvq[2*k+1], bs0, boq[2*k+1]));
        a1[k] = pk2(fmaf(bvq[2*k], bs1, boq[2*k]), fmaf(bvq[2*k+1], bs1, boq[2*k+1]));
    }
    const float4* x0 = reinterpret_cast<const float4*>(g_accN + (size_t)r0c * D);
    const float4* x1 = reinterpret_cast<const float4*>(g_accN + (size_t)r1c * D);
    const float* wq = sW + q * 16;
#pragma unroll 4
    for (int jv = 0; jv < D / 4; jv++) {
        float4 v0 = x0[jv], v1 = x1[jv];
        const float* w0 = wq + (4 * jv) * D;
        colupd(a0, a1, v0.x, v1.x, w0);
        colupd(a0, a1, v0.y, v1.y, w0 + D);
        colupd(a0, a1, v0.z, v1.z, w0 + 2 * D);
        colupd(a0, a1, v0.w, v1.w, w0 + 3 * D);
    }
    if (r0 < N_NODES) {
        float4* o0 = reinterpret_cast<float4*>(g_fused + (size_t)r0 * D + q * 16);
#pragma unroll
        for (int k = 0; k < 4; k++) o0[k] = relu4(a0[2*k], a0[2*k+1]);
    }
    if (r1 < N_NODES) {
        float4* o1 = reinterpret_cast<float4*>(g_fused + (size_t)r1 * D + q * 16);
#pragma unroll
        for (int k = 0; k < 4; k++) o1[k] = relu4(a1[2*k], a1[2*k+1]);
    }
}

// ---------------- K7: out = x + fused @ W_up + b_up -----------------------------
// grid (nblk, 2): gy selects 128 output cols; warp q=wid handles 16 cols
__global__ __launch_bounds__(256) void k_E3(const float* __restrict__ x,
                                            const float* __restrict__ Wup,
                                            const float* __restrict__ bup,
                                            float* __restrict__ out) {
    extern __shared__ float smem[];
    float* sW = smem;                 // 64 x 128 slice
    float* sb = smem + D * 128;       // 128
    int gy = blockIdx.y;
    for (int t = threadIdx.x; t < D * 128 / 4; t += 256) {
        int row = t >> 5, c4 = t & 31;
        reinterpret_cast<float4*>(sW + row * 128)[c4] =
            reinterpret_cast<const float4*>(Wup + row * IN_CH + gy * 128)[c4];
    }
    if (threadIdx.x < 128) sb[threadIdx.x] = bup[gy * 128 + threadIdx.x];
    __syncthreads();
    int wid = threadIdx.x >> 5, lane = threadIdx.x & 31;
    int q = wid;                       // 8 warps -> 8 chunks of 16 cols
    int r0 = blockIdx.x * 64 + lane;
    int r1 = r0 + 32;
    int r0c = min(r0, N_NODES - 1), r1c = min(r1, N_NODES - 1);

    u64 a0[8], a1[8];
    const u64* bb = reinterpret_cast<const u64*>(sb + q * 16);
#pragma unroll
    for (int k = 0; k < 8; k++) { a0[k] = bb[k]; a1[k] = bb[k]; }

    const float4* f0 = reinterpret_cast<const float4*>(g_fused + (size_t)r0c * D);
    const float4* f1 = reinterpret_cast<const float4*>(g_fused + (size_t)r1c * D);
    const float* wq = sW + q * 16;
#pragma unroll 4
    for (int jv = 0; jv < D / 4; jv++) {
        float4 v0 = f0[jv], v1 = f1[jv];
        const float* w0 = wq + (4 * jv) * 128;
        colupd(a0, a1, v0.x, v1.x, w0);
        colupd(a0, a1, v0.y, v1.y, w0 + 128);
        colupd(a0, a1, v0.z, v1.z, w0 + 2 * 128);
        colupd(a0, a1, v0.w, v1.w, w0 + 3 * 128);
    }
    int colbase = gy * 128 + q * 16;
    if (r0 < N_NODES) {
        const float4* xr = reinterpret_cast<const float4*>(x + (size_t)r0 * IN_CH + colbase);
        float4* o = reinterpret_cast<float4*>(out + (size_t)r0 * IN_CH + colbase);
#pragma unroll
        for (int k = 0; k < 4; k++) {
            float4 r = raw4(a0[2*k], a0[2*k+1]);
            float4 xv = xr[k];
            o[k] = make_float4(xv.x + r.x, xv.y + r.y, xv.z + r.z, xv.w + r.w);
        }
    }
    if (r1 < N_NODES) {
        const float4* xr = reinterpret_cast<const float4*>(x + (size_t)r1 * IN_CH + colbase);
        float4* o = reinterpret_cast<float4*>(out + (size_t)r1 * IN_CH + colbase);
#pragma unroll
        for (int k = 0; k < 4; k++) {
            float4 r = raw4(a1[2*k], a1[2*k+1]);
            float4 xv = xr[k];
            o[k] = make_float4(xv.x + r.x, xv.y + r.y, xv.z + r.z, xv.w + r.w);
        }
    }
}

// -------------------------------------------------------------------------------
extern "C" void kernel_launch(void* const* d_in, const int* in_sizes, int n_in,
                              void* d_out, int out_size) {
    const float* x   = (const float*)d_in[0];
    const float* ea  = (const float*)d_in[1];
    const int*   ei  = (const int*)  d_in[2];
    const float* Wd  = (const float*)d_in[3];
    const float* bd  = (const float*)d_in[4];
    const float* Wup = (const float*)d_in[5];
    const float* bup = (const float*)d_in[6];
    const float* Wt  = (const float*)d_in[7];
    const float* bt  = (const float*)d_in[8];
    const float* Wq  = (const float*)d_in[9];
    const float* bq  = (const float*)d_in[10];
    const float* Wk  = (const float*)d_in[11];
    const float* bk  = (const float*)d_in[12];
    const float* Wv  = (const float*)d_in[13];
    const float* bv  = (const float*)d_in[14];
    const float* ce  = (const float*)d_in[15];
    const float* Wo  = (const float*)d_in[16];
    const float* bo  = (const float*)d_in[17];
    float* out = (float*)d_out;

    int smA1 = (IN_CH * D + D) * 4;            // 65792
    int smA2 = (D * D + 2 * D) * 4;            // 16896
    int smE1 = (16 * D + D + NC * D + NC) * 4; // 6432
    int smE2 = (D * D + 2 * D) * 4;            // 16896
    int smE3 = (D * 128 + 128) * 4;            // 33280
    cudaFuncSetAttribute(k_nodeA1, cudaFuncAttributeMaxDynamicSharedMemorySize, smA1);

    int nblk128 = (N_NODES + 127) / 128;       // 391
    k_init  <<<(N_NODES + 255) / 256, 256>>>();
    k_prep  <<<16, 256>>>(Wq, bq, Wk, bk, Wv, bv, Wo, bo);
    k_nodeA1<<<nblk128, 256, smA1>>>(x, Wd, bd);
    k_nodeA2<<<nblk128, 256, smA2>>>();
    k_edge1 <<<N_EDGES / 256, 256, smE1>>>(ea, ei, Wt, bt, ce);
    k_gather<<<(N_NODES + 255) / 256, 256>>>();
    k_E2    <<<nblk128, 256, smE2>>>(bo);
    k_E3    <<<dim3((N_NODES + 63) / 64, 2), 256, smE3>>>(x, Wup, bup, out);
}

// round 4
// speedup vs baseline: 1.5166x; 1.0595x over previous
#include <cuda_runtime.h>
#include <math.h>

#define N_NODES 50000
#define N_EDGES 800000
#define IN_CH   256
#define D       64
#define NC      8
#define PAD     68          // padded smem row stride (floats)
#define NBLK_SC 196         // ceil(50000/256)

typedef unsigned long long u64;

// ---------------- f32x2 packed helpers ----------------------------------------
__device__ __forceinline__ u64 pk2(float lo, float hi) {
    u64 r; asm("mov.b64 %0, {%1, %2};" : "=l"(r) : "f"(lo), "f"(hi)); return r;
}
__device__ __forceinline__ void up2(u64 v, float& lo, float& hi) {
    asm("mov.b64 {%0, %1}, %2;" : "=f"(lo), "=f"(hi) : "l"(v));
}
__device__ __forceinline__ void fma2(u64& d, u64 a, u64 b) {
    asm("fma.rn.f32x2 %0, %1, %2, %0;" : "+l"(d) : "l"(a), "l"(b));
}
__device__ __forceinline__ void rank1_64(u64* acc, float s, const float* wrow) {
    u64 s2 = pk2(s, s);
    const ulonglong2* w = reinterpret_cast<const ulonglong2*>(wrow);
#pragma unroll
    for (int t = 0; t < 16; t++) {
        ulonglong2 ww = w[t];
        fma2(acc[2*t],   s2, ww.x);
        fma2(acc[2*t+1], s2, ww.y);
    }
}
__device__ __forceinline__ float dot64(const u64* a, const float* wrow) {
    u64 s = 0ull;
    const ulonglong2* w = reinterpret_cast<const ulonglong2*>(wrow);
#pragma unroll
    for (int t = 0; t < 16; t++) {
        ulonglong2 ww = w[t];
        fma2(s, a[2*t],   ww.x);
        fma2(s, a[2*t+1], ww.y);
    }
    float lo, hi; up2(s, lo, hi); return lo + hi;
}
// 2 rows x 16 outputs per input column; wp is WARP-UNIFORM (broadcast LDS)
__device__ __forceinline__ void colupd(u64* a0, u64* a1, float s0, float s1,
                                       const float* wp) {
    u64 p0 = pk2(s0, s0), p1 = pk2(s1, s1);
    const ulonglong2* w = reinterpret_cast<const ulonglong2*>(wp);
    ulonglong2 wa = w[0], wb = w[1], wc = w[2], wd = w[3];
    fma2(a0[0], p0, wa.x); fma2(a1[0], p1, wa.x);
    fma2(a0[1], p0, wa.y); fma2(a1[1], p1, wa.y);
    fma2(a0[2], p0, wb.x); fma2(a1[2], p1, wb.x);
    fma2(a0[3], p0, wb.y); fma2(a1[3], p1, wb.y);
    fma2(a0[4], p0, wc.x); fma2(a1[4], p1, wc.x);
    fma2(a0[5], p0, wc.y); fma2(a1[5], p1, wc.y);
    fma2(a0[6], p0, wd.x); fma2(a1[6], p1, wd.x);
    fma2(a0[7], p0, wd.y); fma2(a1[7], p1, wd.y);
}
__device__ __forceinline__ float4 relu4(u64 a, u64 b) {
    float x, y, z, w; up2(a, x, y); up2(b, z, w);
    return make_float4(fmaxf(x, 0.f), fmaxf(y, 0.f), fmaxf(z, 0.f), fmaxf(w, 0.f));
}
__device__ __forceinline__ float4 raw4(u64 a, u64 b) {
    float x, y, z, w; up2(a, x, y); up2(b, z, w);
    return make_float4(x, y, z, w);
}

// ---------------- scratch ------------------------------------------------------
__device__ float g_nf  [N_NODES * D];
__device__ float g_qk  [N_NODES * D];
__device__ float g_qb  [N_NODES];
__device__ float g_tfc [(size_t)N_EDGES * D];   // CSR-ordered tf (204.8MB)
__device__ u64   g_ac  [N_EDGES];               // CSR-ordered {attn, cluster}
__device__ int   g_deg [N_NODES];
__device__ int   g_off [N_NODES + 1];
__device__ int   g_cur [N_NODES];
__device__ int   g_bsum[NBLK_SC], g_boff[NBLK_SC];
__device__ float g_cec [NC];
__device__ float g_accN[N_NODES * D];
__device__ float g_bsc [N_NODES];
__device__ float g_fused[N_NODES * D];
__device__ float g_Wqk[D * D], g_bqk[D], g_wqb[D], g_sqb;
__device__ float g_Wvo[D * D], g_bvo[D];

// ---------------- K0: zero deg + cec -------------------------------------------
__global__ void k_init() {
    int i = blockIdx.x * blockDim.x + threadIdx.x;
    if (i < N_NODES) g_deg[i] = 0;
    if (i < NC) g_cec[i] = 0.f;
}
// ---------------- K0b: degree count --------------------------------------------
__global__ void k_count(const int* __restrict__ ei) {
    int e = blockIdx.x * blockDim.x + threadIdx.x;
    if (e < N_EDGES) atomicAdd(&g_deg[ei[e]], 1);
}
// ---------------- scan (3 stages) ----------------------------------------------
__global__ void k_scan1() {
    __shared__ int s[256];
    int t = threadIdx.x;
    int i = blockIdx.x * 256 + t;
    int v = (i < N_NODES) ? g_deg[i] : 0;
    s[t] = v; __syncthreads();
#pragma unroll
    for (int o = 1; o < 256; o <<= 1) {
        int xv = (t >= o) ? s[t - o] : 0;
        __syncthreads();
        s[t] += xv;
        __syncthreads();
    }
    if (i < N_NODES) g_off[i] = s[t] - v;     // local exclusive
    if (t == 255) g_bsum[blockIdx.x] = s[255];
}
__global__ void k_scan2() {
    __shared__ int s[256];
    int t = threadIdx.x;
    int v = (t < NBLK_SC) ? g_bsum[t] : 0;
    s[t] = v; __syncthreads();
#pragma unroll
    for (int o = 1; o < 256; o <<= 1) {
        int xv = (t >= o) ? s[t - o] : 0;
        __syncthreads();
        s[t] += xv;
        __syncthreads();
    }
    if (t < NBLK_SC) g_boff[t] = s[t] - v;    // exclusive
}
__global__ void k_scan3() {
    int i = blockIdx.x * 256 + threadIdx.x;
    if (i < N_NODES) {
        int o = g_off[i] + g_boff[blockIdx.x];
        g_off[i] = o;
        g_cur[i] = o;
    }
    if (i == 0) g_off[N_NODES] = N_EDGES;
}

// ---------------- K1: fold weights ---------------------------------------------
__global__ void k_prep(const float* __restrict__ Wq, const float* __restrict__ bq,
                       const float* __restrict__ Wk, const float* __restrict__ bk,
                       const float* __restrict__ Wv, const float* __restrict__ bv,
                       const float* __restrict__ Wo, const float* __restrict__ bo) {
    int idx = blockIdx.x * blockDim.x + threadIdx.x;
    if (idx < D * D) {
        int t = idx >> 6, j = idx & 63;
        float s1 = 0.f, s2 = 0.f;
        for (int d = 0; d < D; d++) {
            s1 = fmaf(Wq[t * D + d], Wk[j * D + d], s1);
            s2 = fmaf(Wv[t * D + d], Wo[d * D + j], s2);
        }
        g_Wqk[t * D + j] = s1;
        g_Wvo[t * D + j] = s2;
    }
    if (idx < D) {
        int j = idx;
        float a = 0.f, b = 0.f, c = 0.f;
        for (int d = 0; d < D; d++) {
            a = fmaf(bq[d], Wk[j * D + d], a);
            b = fmaf(bv[d], Wo[d * D + j], b);
            c = fmaf(Wq[j * D + d], bk[d], c);
        }
        g_bqk[j] = a; g_bvo[j] = b; g_wqb[j] = c;
        if (idx == 0) {
            float s = 0.f;
            for (int d = 0; d < D; d++) s = fmaf(bq[d], bk[d], s);
            g_sqb = s;
        }
    }
}

// ---------------- K2: nf = relu(x @ Wd + bd)  [staged input, k-chunked] ---------
__global__ __launch_bounds__(256) void k_nodeA1(const float* __restrict__ x,
                                                const float* __restrict__ Wd,
                                                const float* __restrict__ bd) {
    extern __shared__ float smem[];
    float* sW = smem;                     // 256*64
    float* sb = sW + IN_CH * D;           // 64
    float* sx = sb + D;                   // 128*PAD
    for (int t = threadIdx.x; t < IN_CH * D / 4; t += 256)
        reinterpret_cast<float4*>(sW)[t] = reinterpret_cast<const float4*>(Wd)[t];
    if (threadIdx.x < D) sb[threadIdx.x] = bd[threadIdx.x];

    int wid = threadIdx.x >> 5, lane = threadIdx.x & 31;
    int q = wid & 3, grp = wid >> 2;
    int rl0 = grp * 64 + lane, rl1 = rl0 + 32;
    int r0 = blockIdx.x * 128 + rl0, r1 = blockIdx.x * 128 + rl1;

    u64 a0[8], a1[8];
    const u64* bb = reinterpret_cast<const u64*>(sb + q * 16);
    // bias init deferred until after first sync (sb ready after first __syncthreads)
    const float* wq = sW + q * 16;

#pragma unroll
    for (int kc = 0; kc < 4; kc++) {
        __syncthreads();
        // stage x[:, kc*64 : kc*64+64] for 128 rows
        for (int t = threadIdx.x; t < 128 * 16; t += 256) {
            int row = t >> 4, c4 = t & 15;
            int rsrc = min(blockIdx.x * 128 + row, N_NODES - 1);
            reinterpret_cast<float4*>(sx + row * PAD)[c4] =
                reinterpret_cast<const float4*>(x + (size_t)rsrc * IN_CH + kc * 64)[c4];
        }
        __syncthreads();
        if (kc == 0) {
#pragma unroll
            for (int k = 0; k < 8; k++) { a0[k] = bb[k]; a1[k] = bb[k]; }
        }
        const float* x0 = sx + rl0 * PAD;
        const float* x1 = sx + rl1 * PAD;
#pragma unroll
        for (int jv = 0; jv < 16; jv++) {
            float4 v0 = reinterpret_cast<const float4*>(x0)[jv];
            float4 v1 = reinterpret_cast<const float4*>(x1)[jv];
            const float* w0 = wq + (kc * 64 + 4 * jv) * D;
            colupd(a0, a1, v0.x, v1.x, w0);
            colupd(a0, a1, v0.y, v1.y, w0 + D);
            colupd(a0, a1, v0.z, v1.z, w0 + 2 * D);
            colupd(a0, a1, v0.w, v1.w, w0 + 3 * D);
        }
    }
    if (r0 < N_NODES) {
        float4* o0 = reinterpret_cast<float4*>(g_nf + (size_t)r0 * D + q * 16);
#pragma unroll
        for (int k = 0; k < 4; k++) o0[k] = relu4(a0[2*k], a0[2*k+1]);
    }
    if (r1 < N_NODES) {
        float4* o1 = reinterpret_cast<float4*>(g_nf + (size_t)r1 * D + q * 16);
#pragma unroll
        for (int k = 0; k < 4; k++) o1[k] = relu4(a1[2*k], a1[2*k+1]);
    }
}

// ---------------- K3: qk = nf @ Wqk + bqk ; qb = nf.wqb + sqb  [staged] ---------
__global__ __launch_bounds__(256) void k_nodeA2() {
    extern __shared__ float smem[];
    float* sW  = smem;                // 64*64
    float* sbq = sW + D * D;          // 64
    float* swq = sbq + D;             // 64
    float* sx  = swq + D;             // 128*PAD
    for (int t = threadIdx.x; t < D * D / 4; t += 256)
        reinterpret_cast<float4*>(sW)[t] = reinterpret_cast<const float4*>(g_Wqk)[t];
    if (threadIdx.x < D) { sbq[threadIdx.x] = g_bqk[threadIdx.x]; swq[threadIdx.x] = g_wqb[threadIdx.x]; }
    for (int t = threadIdx.x; t < 128 * 16; t += 256) {
        int row = t >> 4, c4 = t & 15;
        int rsrc = min(blockIdx.x * 128 + row, N_NODES - 1);
        reinterpret_cast<float4*>(sx + row * PAD)[c4] =
            reinterpret_cast<const float4*>(g_nf + (size_t)rsrc * D)[c4];
    }
    __syncthreads();
    int wid = threadIdx.x >> 5, lane = threadIdx.x & 31;
    int q = wid & 3, grp = wid >> 2;
    int rl0 = grp * 64 + lane, rl1 = rl0 + 32;
    int r0 = blockIdx.x * 128 + rl0, r1 = blockIdx.x * 128 + rl1;

    u64 a0[8], a1[8];
    const u64* bb = reinterpret_cast<const u64*>(sbq + q * 16);
#pragma unroll
    for (int k = 0; k < 8; k++) { a0[k] = bb[k]; a1[k] = bb[k]; }

    const float* x0 = sx + rl0 * PAD;
    const float* x1 = sx + rl1 * PAD;
    const float* wq = sW + q * 16;
#pragma unroll
    for (int jv = 0; jv < 16; jv++) {
        float4 v0 = reinterpret_cast<const float4*>(x0)[jv];
        float4 v1 = reinterpret_cast<const float4*>(x1)[jv];
        const float* w0 = wq + (4 * jv) * D;
        colupd(a0, a1, v0.x, v1.x, w0);
        colupd(a0, a1, v0.y, v1.y, w0 + D);
        colupd(a0, a1, v0.z, v1.z, w0 + 2 * D);
        colupd(a0, a1, v0.w, v1.w, w0 + 3 * D);
    }
    if (r0 < N_NODES) {
        float4* o0 = reinterpret_cast<float4*>(g_qk + (size_t)r0 * D + q * 16);
#pragma unroll
        for (int k = 0; k < 4; k++) o0[k] = raw4(a0[2*k], a0[2*k+1]);
    }
    if (r1 < N_NODES) {
        float4* o1 = reinterpret_cast<float4*>(g_qk + (size_t)r1 * D + q * 16);
#pragma unroll
        for (int k = 0; k < 4; k++) o1[k] = raw4(a1[2*k], a1[2*k+1]);
    }
    if (q == 0) {
        float qb0 = g_sqb, qb1 = g_sqb;
#pragma unroll
        for (int jv = 0; jv < 16; jv++) {
            float4 v0 = reinterpret_cast<const float4*>(x0)[jv];
            float4 v1 = reinterpret_cast<const float4*>(x1)[jv];
            qb0 = fmaf(v0.x, swq[4*jv], fmaf(v0.y, swq[4*jv+1], fmaf(v0.z, swq[4*jv+2], fmaf(v0.w, swq[4*jv+3], qb0))));
            qb1 = fmaf(v1.x, swq[4*jv], fmaf(v1.y, swq[4*jv+1], fmaf(v1.z, swq[4*jv+2], fmaf(v1.w, swq[4*jv+3], qb1))));
        }
        if (r0 < N_NODES) g_qb[r0] = qb0;
        if (r1 < N_NODES) g_qb[r1] = qb1;
    }
}

// per-edge time_feat (weights warp-uniform via identical addressing)
__device__ __forceinline__ void edge_tf(u64* acc, const float* __restrict__ ea, int e,
                                        const float* sW, const float* sb) {
    const u64* sb2 = reinterpret_cast<const u64*>(sb);
#pragma unroll
    for (int t = 0; t < 32; t++) acc[t] = sb2[t];
    const float4* ar = reinterpret_cast<const float4*>(ea + (size_t)e * 16);
#pragma unroll
    for (int jv = 0; jv < 4; jv++) {
        float4 a = ar[jv];
        const float* w0 = sW + (jv * 4) * D;
        rank1_64(acc, a.x, w0);
        rank1_64(acc, a.y, w0 + D);
        rank1_64(acc, a.z, w0 + 2 * D);
        rank1_64(acc, a.w, w0 + 3 * D);
    }
#pragma unroll
    for (int t = 0; t < 32; t++) {
        float lo, hi; up2(acc[t], lo, hi);
        acc[t] = pk2(fmaxf(lo, 0.f), fmaxf(hi, 0.f));
    }
}

// ---------------- K4: edge pass — tf, cluster, attn → CSR -----------------------
__global__ __launch_bounds__(256) void k_edge1(const float* __restrict__ ea,
                                               const int* __restrict__ ei,
                                               const float* __restrict__ Wt,
                                               const float* __restrict__ bt,
                                               const float* __restrict__ ce) {
    extern __shared__ float smem[];
    float* sW = smem;            // 16*64
    float* sb = sW + 16 * D;     // 64
    float* sc = sb + D;          // 8*64
    float* scec = sc + NC * D;   // 8
    for (int t = threadIdx.x; t < 16 * D / 4; t += 256)
        reinterpret_cast<float4*>(sW)[t] = reinterpret_cast<const float4*>(Wt)[t];
    if (threadIdx.x < D) sb[threadIdx.x] = bt[threadIdx.x];
    for (int t = threadIdx.x; t < NC * D / 4; t += 256)
        reinterpret_cast<float4*>(sc)[t] = reinterpret_cast<const float4*>(ce)[t];
    if (threadIdx.x < NC) scec[threadIdx.x] = 0.f;
    __syncthreads();
    int e = blockIdx.x * 256 + threadIdx.x;   // N_EDGES % 256 == 0

    u64 tf[32];
    edge_tf(tf, ea, e, sW, sb);

    int bc = 0; float bv = dot64(tf, sc);
#pragma unroll
    for (int c = 1; c < NC; c++) {
        float s = dot64(tf, sc + c * D);
        if (s > bv) { bv = s; bc = c; }
    }

    int src = ei[e];
    const float4* qr = reinterpret_cast<const float4*>(g_qk + (size_t)src * D);
    u64 s = 0ull;
#pragma unroll
    for (int tv = 0; tv < 16; tv++) {
        float4 qv = qr[tv];
        fma2(s, tf[2*tv],   pk2(qv.x, qv.y));
        fma2(s, tf[2*tv+1], pk2(qv.z, qv.w));
    }
    float lo, hi; up2(s, lo, hi);
    float attn = (lo + hi + g_qb[src]) * 0.125f;

    atomicAdd(&scec[bc], 1.f);
    int pos = atomicAdd(&g_cur[src], 1);
    g_ac[pos] = pk2(attn, __int_as_float(bc));
    float4* tp = reinterpret_cast<float4*>(g_tfc + (size_t)pos * D);
#pragma unroll
    for (int tv = 0; tv < 16; tv++) tp[tv] = raw4(tf[2*tv], tf[2*tv+1]);

    __syncthreads();
    if (threadIdx.x < NC) atomicAdd(&g_cec[threadIdx.x], scec[threadIdx.x]);
}

// ---------------- K5: warp-per-node gather --------------------------------------
__global__ __launch_bounds__(256) void k_gather() {
    int wid = threadIdx.x >> 5, lane = threadIdx.x & 31;
    int n = blockIdx.x * 8 + wid;           // grid = 6250 exact
    int off = g_off[n];
    int deg = g_off[n + 1] - off;

    float nne = 0.f;
#pragma unroll
    for (int c = 0; c < NC; c++) nne += (g_cec[c] > 0.f) ? 1.f : 0.f;
    float inv = 1.0f / nne;

    // phase 1: per-cluster max
    float pm[NC];
#pragma unroll
    for (int c = 0; c < NC; c++) pm[c] = -3.4e38f;
    for (int j = lane; j < deg; j += 32) {
        float a, cf; up2(g_ac[off + j], a, cf);
        int cc = __float_as_int(cf);
#pragma unroll
        for (int c = 0; c < NC; c++) if (cc == c) pm[c] = fmaxf(pm[c], a);
    }
#pragma unroll
    for (int c = 0; c < NC; c++)
#pragma unroll
        for (int o = 16; o > 0; o >>= 1)
            pm[c] = fmaxf(pm[c], __shfl_xor_sync(0xFFFFFFFFu, pm[c], o));

    // phase 2: per-cluster denom + count
    float pd[NC], pc[NC];
#pragma unroll
    for (int c = 0; c < NC; c++) { pd[c] = 0.f; pc[c] = 0.f; }
    for (int j = lane; j < deg; j += 32) {
        float a, cf; up2(g_ac[off + j], a, cf);
        int cc = __float_as_int(cf);
        float cmv = 0.f;
#pragma unroll
        for (int c = 0; c < NC; c++) if (cc == c) cmv = pm[c];
        float e = __expf(a - cmv);
#pragma unroll
        for (int c = 0; c < NC; c++) {
            pd[c] += (cc == c) ? e : 0.f;
            pc[c] += (cc == c) ? 1.f : 0.f;
        }
    }
#pragma unroll
    for (int c = 0; c < NC; c++)
#pragma unroll
        for (int o = 16; o > 0; o >>= 1) {
            pd[c] += __shfl_xor_sync(0xFFFFFFFFu, pd[c], o);
            pc[c] += __shfl_xor_sync(0xFFFFFFFFu, pc[c], o);
        }

    float sinv[NC]; float bsc = 0.f;
#pragma unroll
    for (int c = 0; c < NC; c++) {
        if (pc[c] > 0.f) {
            sinv[c] = inv / (pd[c] * pc[c]);
            bsc += 1.0f / pc[c];
        } else sinv[c] = 0.f;
    }

    // phase 3: weighted sum, coalesced tf reads, 2-deep prefetch
    u64 acc = 0ull;
    if (deg > 0) {
        u64 ac_n = g_ac[off];
        float2 tv_n = *reinterpret_cast<const float2*>(g_tfc + (size_t)off * D + 2 * lane);
        for (int j = 0; j < deg; j++) {
            u64 acj = ac_n; float2 tv = tv_n;
            if (j + 1 < deg) {
                ac_n = g_ac[off + j + 1];
                tv_n = *reinterpret_cast<const float2*>(g_tfc + (size_t)(off + j + 1) * D + 2 * lane);
            }
            float a, cf; up2(acj, a, cf);
            int cc = __float_as_int(cf);
            float cmv = 0.f, sv = 0.f;
#pragma unroll
            for (int c = 0; c < NC; c++) if (cc == c) { cmv = pm[c]; sv = sinv[c]; }
            float coef = __expf(a - cmv) * sv;
            fma2(acc, pk2(coef, coef), pk2(tv.x, tv.y));
        }
    }
    float lo, hi; up2(acc, lo, hi);
    reinterpret_cast<float2*>(g_accN + (size_t)n * D)[lane] = make_float2(lo, hi);
    if (lane == 0) g_bsc[n] = bsc * inv;
}

// ---------------- K6: fused = relu(accN @ Wvo + bvo*bsc + b_out)  [staged] ------
__global__ __launch_bounds__(256) void k_E2(const float* __restrict__ bo) {
    extern __shared__ float smem[];
    float* sW  = smem;            // 64*64
    float* sbv = sW + D * D;
    float* sbo = sbv + D;
    float* sx  = sbo + D;         // 128*PAD
    for (int t = threadIdx.x; t < D * D / 4; t += 256)
        reinterpret_cast<float4*>(sW)[t] = reinterpret_cast<const float4*>(g_Wvo)[t];
    if (threadIdx.x < D) { sbv[threadIdx.x] = g_bvo[threadIdx.x]; sbo[threadIdx.x] = bo[threadIdx.x]; }
    for (int t = threadIdx.x; t < 128 * 16; t += 256) {
        int row = t >> 4, c4 = t & 15;
        int rsrc = min(blockIdx.x * 128 + row, N_NODES - 1);
        reinterpret_cast<float4*>(sx + row * PAD)[c4] =
            reinterpret_cast<const float4*>(g_accN + (size_t)rsrc * D)[c4];
    }
    __syncthreads();
    int wid = threadIdx.x >> 5, lane = threadIdx.x & 31;
    int q = wid & 3, grp = wid >> 2;
    int rl0 = grp * 64 + lane, rl1 = rl0 + 32;
    int r0 = blockIdx.x * 128 + rl0, r1 = blockIdx.x * 128 + rl1;
    int r0c = min(r0, N_NODES - 1), r1c = min(r1, N_NODES - 1);
    float bs0 = g_bsc[r0c], bs1 = g_bsc[r1c];

    u64 a0[8], a1[8];
    const float* bvq = sbv + q * 16;
    const float* boq = sbo + q * 16;
#pragma unroll
    for (int k = 0; k < 8; k++) {
        a0[k] = pk2(fmaf(bvq[2*k], bs0, boq[2*k]), fmaf(bvq[2*k+1], bs0, boq[2*k+1]));
        a1[k] = pk2(fmaf(bvq[2*k], bs1, boq[2*k]), fmaf(bvq[2*k+1], bs1, boq[2*k+1]));
    }
    const float* x0 = sx + rl0 * PAD;
    const float* x1 = sx + rl1 * PAD;
    const float* wq = sW + q * 16;
#pragma unroll
    for (int jv = 0; jv < 16; jv++) {
        float4 v0 = reinterpret_cast<const float4*>(x0)[jv];
        float4 v1 = reinterpret_cast<const float4*>(x1)[jv];
        const float* w0 = wq + (4 * jv) * D;
        colupd(a0, a1, v0.x, v1.x, w0);
        colupd(a0, a1, v0.y, v1.y, w0 + D);
        colupd(a0, a1, v0.z, v1.z, w0 + 2 * D);
        colupd(a0, a1, v0.w, v1.w, w0 + 3 * D);
    }
    if (r0 < N_NODES) {
        float4* o0 = reinterpret_cast<float4*>(g_fused + (size_t)r0 * D + q * 16);
#pragma unroll
        for (int k = 0; k < 4; k++) o0[k] = relu4(a0[2*k], a0[2*k+1]);
    }
    if (r1 < N_NODES) {
        float4* o1 = reinterpret_cast<float4*>(g_fused + (size_t)r1 * D + q * 16);
#pragma unroll
        for (int k = 0; k < 4; k++) o1[k] = relu4(a1[2*k], a1[2*k+1]);
    }
}

// ---------------- K7: out = x + fused @ W_up + b_up  [staged] -------------------
__global__ __launch_bounds__(256) void k_E3(const float* __restrict__ x,
                                            const float* __restrict__ Wup,
                                            const float* __restrict__ bup,
                                            float* __restrict__ out) {
    extern __shared__ float smem[];
    float* sW = smem;                 // 64 x 128 slice
    float* sb = sW + D * 128;         // 128
    float* sx = sb + 128;             // 64*PAD
    int gy = blockIdx.y;
    for (int t = threadIdx.x; t < D * 128 / 4; t += 256) {
        int row = t >> 5, c4 = t & 31;
        reinterpret_cast<float4*>(sW + row * 128)[c4] =
            reinterpret_cast<const float4*>(Wup + row * IN_CH + gy * 128)[c4];
    }
    if (threadIdx.x < 128) sb[threadIdx.x] = bup[gy * 128 + threadIdx.x];
    for (int t = threadIdx.x; t < 64 * 16; t += 256) {
        int row = t >> 4, c4 = t & 15;
        int rsrc = min(blockIdx.x * 64 + row, N_NODES - 1);
        reinterpret_cast<float4*>(sx + row * PAD)[c4] =
            reinterpret_cast<const float4*>(g_fused + (size_t)rsrc * D)[c4];
    }
    __syncthreads();
    int wid = threadIdx.x >> 5, lane = threadIdx.x & 31;
    int q = wid;                       // 8 warps -> 8 chunks of 16 cols
    int rl0 = lane, rl1 = lane + 32;
    int r0 = blockIdx.x * 64 + rl0, r1 = blockIdx.x * 64 + rl1;

    u64 a0[8], a1[8];
    const u64* bb = reinterpret_cast<const u64*>(sb + q * 16);
#pragma unroll
    for (int k = 0; k < 8; k++) { a0[k] = bb[k]; a1[k] = bb[k]; }

    const float* f0 = sx + rl0 * PAD;
    const float* f1 = sx + rl1 * PAD;
    const float* wq = sW + q * 16;
#pragma unroll
    for (int jv = 0; jv < 16; jv++) {
        float4 v0 = reinterpret_cast<const float4*>(f0)[jv];
        float4 v1 = reinterpret_cast<const float4*>(f1)[jv];
        const float* w0 = wq + (4 * jv) * 128;
        colupd(a0, a1, v0.x, v1.x, w0);
        colupd(a0, a1, v0.y, v1.y, w0 + 128);
        colupd(a0, a1, v0.z, v1.z, w0 + 2 * 128);
        colupd(a0, a1, v0.w, v1.w, w0 + 3 * 128);
    }
    int colbase = gy * 128 + q * 16;
    if (r0 < N_NODES) {
        const float4* xr = reinterpret_cast<const float4*>(x + (size_t)r0 * IN_CH + colbase);
        float4* o = reinterpret_cast<float4*>(out + (size_t)r0 * IN_CH + colbase);
#pragma unroll
        for (int k = 0; k < 4; k++) {
            float4 r = raw4(a0[2*k], a0[2*k+1]);
            float4 xv = xr[k];
            o[k] = make_float4(xv.x + r.x, xv.y + r.y, xv.z + r.z, xv.w + r.w);
        }
    }
    if (r1 < N_NODES) {
        const float4* xr = reinterpret_cast<const float4*>(x + (size_t)r1 * IN_CH + colbase);
        float4* o = reinterpret_cast<float4*>(out + (size_t)r1 * IN_CH + colbase);
#pragma unroll
        for (int k = 0; k < 4; k++) {
            float4 r = raw4(a1[2*k], a1[2*k+1]);
            float4 xv = xr[k];
            o[k] = make_float4(xv.x + r.x, xv.y + r.y, xv.z + r.z, xv.w + r.w);
        }
    }
}

// -------------------------------------------------------------------------------
extern "C" void kernel_launch(void* const* d_in, const int* in_sizes, int n_in,
                              void* d_out, int out_size) {
    const float* x   = (const float*)d_in[0];
    const float* ea  = (const float*)d_in[1];
    const int*   ei  = (const int*)  d_in[2];
    const float* Wd  = (const float*)d_in[3];
    const float* bd  = (const float*)d_in[4];
    const float* Wup = (const float*)d_in[5];
    const float* bup = (const float*)d_in[6];
    const float* Wt  = (const float*)d_in[7];
    const float* bt  = (const float*)d_in[8];
    const float* Wq  = (const float*)d_in[9];
    const float* bq  = (const float*)d_in[10];
    const float* Wk  = (const float*)d_in[11];
    const float* bk  = (const float*)d_in[12];
    const float* Wv  = (const float*)d_in[13];
    const float* bv  = (const float*)d_in[14];
    const float* ce  = (const float*)d_in[15];
    const float* Wo  = (const float*)d_in[16];
    const float* bo  = (const float*)d_in[17];
    float* out = (float*)d_out;

    int smA1 = (IN_CH * D + D + 128 * PAD) * 4;        // ~100.6KB
    int smA2 = (D * D + 2 * D + 128 * PAD) * 4;        // ~51.7KB
    int smE1 = (16 * D + D + NC * D + NC) * 4;         // 6432
    int smE2 = smA2;
    int smE3 = (D * 128 + 128 + 64 * PAD) * 4;         // ~50.7KB
    cudaFuncSetAttribute(k_nodeA1, cudaFuncAttributeMaxDynamicSharedMemorySize, smA1);
    cudaFuncSetAttribute(k_nodeA2, cudaFuncAttributeMaxDynamicSharedMemorySize, smA2);
    cudaFuncSetAttribute(k_E2,     cudaFuncAttributeMaxDynamicSharedMemorySize, smE2);
    cudaFuncSetAttribute(k_E3,     cudaFuncAttributeMaxDynamicSharedMemorySize, smE3);

    int nblk128 = (N_NODES + 127) / 128;       // 391
    k_init  <<<(N_NODES + 255) / 256, 256>>>();
    k_count <<<(N_EDGES + 255) / 256, 256>>>(ei);
    k_scan1 <<<NBLK_SC, 256>>>();
    k_scan2 <<<1, 256>>>();
    k_scan3 <<<NBLK_SC, 256>>>();
    k_prep  <<<16, 256>>>(Wq, bq, Wk, bk, Wv, bv, Wo, bo);
    k_nodeA1<<<nblk128, 256, smA1>>>(x, Wd, bd);
    k_nodeA2<<<nblk128, 256, smA2>>>();
    k_edge1 <<<N_EDGES / 256, 256, smE1>>>(ea, ei, Wt, bt, ce);
    k_gather<<<N_NODES / 8, 256>>>();
    k_E2    <<<nblk128, 256, smE2>>>(bo);
    k_E3    <<<dim3((N_NODES + 63) / 64, 2), 256, smE3>>>(x, Wup, bup, out);
}

// round 5
// speedup vs baseline: 1.5603x; 1.0288x over previous
#include <cuda_runtime.h>
#include <cuda_fp16.h>
#include <math.h>

#define N_NODES 50000
#define N_EDGES 800000
#define IN_CH   256
#define D       64
#define NC      8
#define PAD     68          // padded smem row stride (floats)
#define NBLK_SC 196         // ceil(50000/256)

typedef unsigned long long u64;
typedef unsigned int u32;

// ---------------- f32x2 packed helpers ----------------------------------------
__device__ __forceinline__ u64 pk2(float lo, float hi) {
    u64 r; asm("mov.b64 %0, {%1, %2};" : "=l"(r) : "f"(lo), "f"(hi)); return r;
}
__device__ __forceinline__ void up2(u64 v, float& lo, float& hi) {
    asm("mov.b64 {%0, %1}, %2;" : "=f"(lo), "=f"(hi) : "l"(v));
}
__device__ __forceinline__ void fma2(u64& d, u64 a, u64 b) {
    asm("fma.rn.f32x2 %0, %1, %2, %0;" : "+l"(d) : "l"(a), "l"(b));
}
__device__ __forceinline__ void rank1_64(u64* acc, float s, const float* wrow) {
    u64 s2 = pk2(s, s);
    const ulonglong2* w = reinterpret_cast<const ulonglong2*>(wrow);
#pragma unroll
    for (int t = 0; t < 16; t++) {
        ulonglong2 ww = w[t];
        fma2(acc[2*t],   s2, ww.x);
        fma2(acc[2*t+1], s2, ww.y);
    }
}
__device__ __forceinline__ float dot64(const u64* a, const float* wrow) {
    u64 s = 0ull;
    const ulonglong2* w = reinterpret_cast<const ulonglong2*>(wrow);
#pragma unroll
    for (int t = 0; t < 16; t++) {
        ulonglong2 ww = w[t];
        fma2(s, a[2*t],   ww.x);
        fma2(s, a[2*t+1], ww.y);
    }
    float lo, hi; up2(s, lo, hi); return lo + hi;
}
// 2 rows x 16 outputs per input column; wp is WARP-UNIFORM (broadcast LDS)
__device__ __forceinline__ void colupd(u64* a0, u64* a1, float s0, float s1,
                                       const float* wp) {
    u64 p0 = pk2(s0, s0), p1 = pk2(s1, s1);
    const ulonglong2* w = reinterpret_cast<const ulonglong2*>(wp);
    ulonglong2 wa = w[0], wb = w[1], wc = w[2], wd = w[3];
    fma2(a0[0], p0, wa.x); fma2(a1[0], p1, wa.x);
    fma2(a0[1], p0, wa.y); fma2(a1[1], p1, wa.y);
    fma2(a0[2], p0, wb.x); fma2(a1[2], p1, wb.x);
    fma2(a0[3], p0, wb.y); fma2(a1[3], p1, wb.y);
    fma2(a0[4], p0, wc.x); fma2(a1[4], p1, wc.x);
    fma2(a0[5], p0, wc.y); fma2(a1[5], p1, wc.y);
    fma2(a0[6], p0, wd.x); fma2(a1[6], p1, wd.x);
    fma2(a0[7], p0, wd.y); fma2(a1[7], p1, wd.y);
}
__device__ __forceinline__ float4 relu4(u64 a, u64 b) {
    float x, y, z, w; up2(a, x, y); up2(b, z, w);
    return make_float4(fmaxf(x, 0.f), fmaxf(y, 0.f), fmaxf(z, 0.f), fmaxf(w, 0.f));
}
__device__ __forceinline__ float4 raw4(u64 a, u64 b) {
    float x, y, z, w; up2(a, x, y); up2(b, z, w);
    return make_float4(x, y, z, w);
}

// ---------------- scratch ------------------------------------------------------
__device__ float g_qk  [N_NODES * D];
__device__ float g_qb  [N_NODES];
__device__ u32   g_tfh [(size_t)N_EDGES * 32];  // fp16 tf, edge order (102.4MB)
__device__ u64   g_ac  [N_EDGES];               // CSR-pos {attn, cluster}
__device__ int   g_eid [N_EDGES];               // CSR-pos -> edge id
__device__ int   g_deg [N_NODES];
__device__ int   g_off [N_NODES + 1];
__device__ int   g_cur [N_NODES];
__device__ int   g_bsum[NBLK_SC], g_boff[NBLK_SC];
__device__ float g_cec [NC];
__device__ float g_accN[N_NODES * D];
__device__ float g_bsc [N_NODES];
__device__ float g_fused[N_NODES * D];
__device__ float g_Wqk[D * D], g_bqk[D], g_wqb[D], g_sqb;
__device__ float g_Wvo[D * D], g_bvo[D];

// ---------------- K0: zero deg + cec -------------------------------------------
__global__ void k_init() {
    int i = blockIdx.x * blockDim.x + threadIdx.x;
    if (i < N_NODES) g_deg[i] = 0;
    if (i < NC) g_cec[i] = 0.f;
}
__global__ void k_count(const int* __restrict__ ei) {
    int e = blockIdx.x * blockDim.x + threadIdx.x;
    if (e < N_EDGES) atomicAdd(&g_deg[ei[e]], 1);
}
// ---------------- scan (3 stages) ----------------------------------------------
__global__ void k_scan1() {
    __shared__ int s[256];
    int t = threadIdx.x;
    int i = blockIdx.x * 256 + t;
    int v = (i < N_NODES) ? g_deg[i] : 0;
    s[t] = v; __syncthreads();
#pragma unroll
    for (int o = 1; o < 256; o <<= 1) {
        int xv = (t >= o) ? s[t - o] : 0;
        __syncthreads();
        s[t] += xv;
        __syncthreads();
    }
    if (i < N_NODES) g_off[i] = s[t] - v;
    if (t == 255) g_bsum[blockIdx.x] = s[255];
}
__global__ void k_scan2() {
    __shared__ int s[256];
    int t = threadIdx.x;
    int v = (t < NBLK_SC) ? g_bsum[t] : 0;
    s[t] = v; __syncthreads();
#pragma unroll
    for (int o = 1; o < 256; o <<= 1) {
        int xv = (t >= o) ? s[t - o] : 0;
        __syncthreads();
        s[t] += xv;
        __syncthreads();
    }
    if (t < NBLK_SC) g_boff[t] = s[t] - v;
}
__global__ void k_scan3() {
    int i = blockIdx.x * 256 + threadIdx.x;
    if (i < N_NODES) {
        int o = g_off[i] + g_boff[blockIdx.x];
        g_off[i] = o;
        g_cur[i] = o;
    }
    if (i == 0) g_off[N_NODES] = N_EDGES;
}

// ---------------- K1: fold weights ---------------------------------------------
__global__ void k_prep(const float* __restrict__ Wq, const float* __restrict__ bq,
                       const float* __restrict__ Wk, const float* __restrict__ bk,
                       const float* __restrict__ Wv, const float* __restrict__ bv,
                       const float* __restrict__ Wo, const float* __restrict__ bo) {
    int idx = blockIdx.x * blockDim.x + threadIdx.x;
    if (idx < D * D) {
        int t = idx >> 6, j = idx & 63;
        float s1 = 0.f, s2 = 0.f;
        for (int d = 0; d < D; d++) {
            s1 = fmaf(Wq[t * D + d], Wk[j * D + d], s1);
            s2 = fmaf(Wv[t * D + d], Wo[d * D + j], s2);
        }
        g_Wqk[t * D + j] = s1;
        g_Wvo[t * D + j] = s2;
    }
    if (idx < D) {
        int j = idx;
        float a = 0.f, b = 0.f, c = 0.f;
        for (int d = 0; d < D; d++) {
            a = fmaf(bq[d], Wk[j * D + d], a);
            b = fmaf(bv[d], Wo[d * D + j], b);
            c = fmaf(Wq[j * D + d], bk[d], c);
        }
        g_bqk[j] = a; g_bvo[j] = b; g_wqb[j] = c;
        if (idx == 0) {
            float s = 0.f;
            for (int d = 0; d < D; d++) s = fmaf(bq[d], bk[d], s);
            g_sqb = s;
        }
    }
}

// ---------------- K2: FUSED nodeA — qk = relu(x@Wd+bd)@Wqk + bqk, qb -------------
__global__ __launch_bounds__(256) void k_nodeA(const float* __restrict__ x,
                                               const float* __restrict__ Wd,
                                               const float* __restrict__ bd) {
    extern __shared__ float smem[];
    float* sWd = smem;                     // 256*64
    float* sWq = sWd + IN_CH * D;          // 64*64
    float* sbd = sWq + D * D;              // 64
    float* sbq = sbd + D;                  // 64
    float* swq = sbq + D;                  // 64
    float* sx  = swq + D;                  // 128*PAD
    for (int t = threadIdx.x; t < IN_CH * D / 4; t += 256)
        reinterpret_cast<float4*>(sWd)[t] = reinterpret_cast<const float4*>(Wd)[t];
    for (int t = threadIdx.x; t < D * D / 4; t += 256)
        reinterpret_cast<float4*>(sWq)[t] = reinterpret_cast<const float4*>(g_Wqk)[t];
    if (threadIdx.x < D) {
        sbd[threadIdx.x] = bd[threadIdx.x];
        sbq[threadIdx.x] = g_bqk[threadIdx.x];
        swq[threadIdx.x] = g_wqb[threadIdx.x];
    }

    int wid = threadIdx.x >> 5, lane = threadIdx.x & 31;
    int q = wid & 3, grp = wid >> 2;
    int rl0 = grp * 64 + lane, rl1 = rl0 + 32;
    int r0 = blockIdx.x * 128 + rl0, r1 = blockIdx.x * 128 + rl1;

    u64 a0[8], a1[8];
    const float* wq1 = sWd + q * 16;
    // phase 1: nf = relu(x @ Wd + bd), k-chunked staging
#pragma unroll
    for (int kc = 0; kc < 4; kc++) {
        __syncthreads();
        for (int t = threadIdx.x; t < 128 * 16; t += 256) {
            int row = t >> 4, c4 = t & 15;
            int rsrc = min(blockIdx.x * 128 + row, N_NODES - 1);
            reinterpret_cast<float4*>(sx + row * PAD)[c4] =
                reinterpret_cast<const float4*>(x + (size_t)rsrc * IN_CH + kc * 64)[c4];
        }
        __syncthreads();
        if (kc == 0) {
            const u64* bb = reinterpret_cast<const u64*>(sbd + q * 16);
#pragma unroll
            for (int k = 0; k < 8; k++) { a0[k] = bb[k]; a1[k] = bb[k]; }
        }
        const float* x0 = sx + rl0 * PAD;
        const float* x1 = sx + rl1 * PAD;
#pragma unroll
        for (int jv = 0; jv < 16; jv++) {
            float4 v0 = reinterpret_cast<const float4*>(x0)[jv];
            float4 v1 = reinterpret_cast<const float4*>(x1)[jv];
            const float* w0 = wq1 + (kc * 64 + 4 * jv) * D;
            colupd(a0, a1, v0.x, v1.x, w0);
            colupd(a0, a1, v0.y, v1.y, w0 + D);
            colupd(a0, a1, v0.z, v1.z, w0 + 2 * D);
            colupd(a0, a1, v0.w, v1.w, w0 + 3 * D);
        }
    }
    // write relu(nf) tile into sx
    __syncthreads();
    {
        float4* o0 = reinterpret_cast<float4*>(sx + rl0 * PAD + q * 16);
        float4* o1 = reinterpret_cast<float4*>(sx + rl1 * PAD + q * 16);
#pragma unroll
        for (int k = 0; k < 4; k++) {
            o0[k] = relu4(a0[2*k], a0[2*k+1]);
            o1[k] = relu4(a1[2*k], a1[2*k+1]);
        }
    }
    __syncthreads();
    // phase 2: qk = nf @ Wqk + bqk
    {
        const u64* bb = reinterpret_cast<const u64*>(sbq + q * 16);
#pragma unroll
        for (int k = 0; k < 8; k++) { a0[k] = bb[k]; a1[k] = bb[k]; }
    }
    const float* x0 = sx + rl0 * PAD;
    const float* x1 = sx + rl1 * PAD;
    const float* wq2 = sWq + q * 16;
#pragma unroll
    for (int jv = 0; jv < 16; jv++) {
        float4 v0 = reinterpret_cast<const float4*>(x0)[jv];
        float4 v1 = reinterpret_cast<const float4*>(x1)[jv];
        const float* w0 = wq2 + (4 * jv) * D;
        colupd(a0, a1, v0.x, v1.x, w0);
        colupd(a0, a1, v0.y, v1.y, w0 + D);
        colupd(a0, a1, v0.z, v1.z, w0 + 2 * D);
        colupd(a0, a1, v0.w, v1.w, w0 + 3 * D);
    }
    if (r0 < N_NODES) {
        float4* o0 = reinterpret_cast<float4*>(g_qk + (size_t)r0 * D + q * 16);
#pragma unroll
        for (int k = 0; k < 4; k++) o0[k] = raw4(a0[2*k], a0[2*k+1]);
    }
    if (r1 < N_NODES) {
        float4* o1 = reinterpret_cast<float4*>(g_qk + (size_t)r1 * D + q * 16);
#pragma unroll
        for (int k = 0; k < 4; k++) o1[k] = raw4(a1[2*k], a1[2*k+1]);
    }
    if (q == 0) {
        float qb0 = g_sqb, qb1 = g_sqb;
#pragma unroll
        for (int jv = 0; jv < 16; jv++) {
            float4 v0 = reinterpret_cast<const float4*>(x0)[jv];
            float4 v1 = reinterpret_cast<const float4*>(x1)[jv];
            qb0 = fmaf(v0.x, swq[4*jv], fmaf(v0.y, swq[4*jv+1], fmaf(v0.z, swq[4*jv+2], fmaf(v0.w, swq[4*jv+3], qb0))));
            qb1 = fmaf(v1.x, swq[4*jv], fmaf(v1.y, swq[4*jv+1], fmaf(v1.z, swq[4*jv+2], fmaf(v1.w, swq[4*jv+3], qb1))));
        }
        if (r0 < N_NODES) g_qb[r0] = qb0;
        if (r1 < N_NODES) g_qb[r1] = qb1;
    }
}

// per-edge time_feat (weights warp-uniform)
__device__ __forceinline__ void edge_tf(u64* acc, const float* __restrict__ ea, int e,
                                        const float* sW, const float* sb) {
    const u64* sb2 = reinterpret_cast<const u64*>(sb);
#pragma unroll
    for (int t = 0; t < 32; t++) acc[t] = sb2[t];
    const float4* ar = reinterpret_cast<const float4*>(ea + (size_t)e * 16);
#pragma unroll
    for (int jv = 0; jv < 4; jv++) {
        float4 a = ar[jv];
        const float* w0 = sW + (jv * 4) * D;
        rank1_64(acc, a.x, w0);
        rank1_64(acc, a.y, w0 + D);
        rank1_64(acc, a.z, w0 + 2 * D);
        rank1_64(acc, a.w, w0 + 3 * D);
    }
#pragma unroll
    for (int t = 0; t < 32; t++) {
        float lo, hi; up2(acc[t], lo, hi);
        acc[t] = pk2(fmaxf(lo, 0.f), fmaxf(hi, 0.f));
    }
}

// ---------------- K4: edge pass — tf(fp16, coalesced), cluster, attn → CSR meta -
__global__ __launch_bounds__(256) void k_edge1(const float* __restrict__ ea,
                                               const int* __restrict__ ei,
                                               const float* __restrict__ Wt,
                                               const float* __restrict__ bt,
                                               const float* __restrict__ ce) {
    extern __shared__ float smem[];
    float* sW = smem;            // 16*64
    float* sb = sW + 16 * D;     // 64
    float* sc = sb + D;          // 8*64
    float* scec = sc + NC * D;   // 8
    u64* su = reinterpret_cast<u64*>(scec + NC);  // 256*17 u64 stage
    for (int t = threadIdx.x; t < 16 * D / 4; t += 256)
        reinterpret_cast<float4*>(sW)[t] = reinterpret_cast<const float4*>(Wt)[t];
    if (threadIdx.x < D) sb[threadIdx.x] = bt[threadIdx.x];
    for (int t = threadIdx.x; t < NC * D / 4; t += 256)
        reinterpret_cast<float4*>(sc)[t] = reinterpret_cast<const float4*>(ce)[t];
    if (threadIdx.x < NC) scec[threadIdx.x] = 0.f;
    __syncthreads();
    int e = blockIdx.x * 256 + threadIdx.x;   // N_EDGES % 256 == 0

    u64 tf[32];
    edge_tf(tf, ea, e, sW, sb);

    int bc = 0; float bv = dot64(tf, sc);
#pragma unroll
    for (int c = 1; c < NC; c++) {
        float s = dot64(tf, sc + c * D);
        if (s > bv) { bv = s; bc = c; }
    }

    int src = ei[e];
    const float4* qr = reinterpret_cast<const float4*>(g_qk + (size_t)src * D);
    u64 s = 0ull;
#pragma unroll
    for (int tv = 0; tv < 16; tv++) {
        float4 qv = qr[tv];
        fma2(s, tf[2*tv],   pk2(qv.x, qv.y));
        fma2(s, tf[2*tv+1], pk2(qv.z, qv.w));
    }
    float lo, hi; up2(s, lo, hi);
    float attn = (lo + hi + g_qb[src]) * 0.125f;

    atomicAdd(&scec[bc], 1.f);
    int pos = atomicAdd(&g_cur[src], 1);
    g_ac[pos] = pk2(attn, __int_as_float(bc));
    g_eid[pos] = e;

    // convert tf -> fp16 pairs, stage in smem, store coalesced (edge order)
#pragma unroll
    for (int c = 0; c < 16; c++) {
        float a, b; up2(tf[2*c], a, b);
        float cc, d; up2(tf[2*c+1], cc, d);
        __half2 h0 = __floats2half2_rn(a, b);
        __half2 h1 = __floats2half2_rn(cc, d);
        u32 l0 = *reinterpret_cast<u32*>(&h0);
        u32 l1 = *reinterpret_cast<u32*>(&h1);
        su[threadIdx.x * 17 + c] = (u64)l0 | ((u64)l1 << 32);
    }
    __syncthreads();
    u64* gout = reinterpret_cast<u64*>(g_tfh) + (size_t)blockIdx.x * 4096;
#pragma unroll
    for (int k = 0; k < 16; k++) {
        int idx = threadIdx.x + k * 256;
        int el = idx >> 4, c = idx & 15;
        gout[idx] = su[el * 17 + c];
    }
    if (threadIdx.x < NC) atomicAdd(&g_cec[threadIdx.x], scec[threadIdx.x]);
}

// ---------------- K5: warp-per-node gather --------------------------------------
__global__ __launch_bounds__(256) void k_gather() {
    int wid = threadIdx.x >> 5, lane = threadIdx.x & 31;
    int n = blockIdx.x * 8 + wid;           // grid = 6250 exact
    int off = g_off[n];
    int deg = g_off[n + 1] - off;

    float nne = 0.f;
#pragma unroll
    for (int c = 0; c < NC; c++) nne += (g_cec[c] > 0.f) ? 1.f : 0.f;
    float inv = 1.0f / nne;

    // phase 1: per-cluster max (lane-parallel over edges)
    float pm[NC];
#pragma unroll
    for (int c = 0; c < NC; c++) pm[c] = -3.4e38f;
    for (int j = lane; j < deg; j += 32) {
        float a, cf; up2(g_ac[off + j], a, cf);
        int cc = __float_as_int(cf);
#pragma unroll
        for (int c = 0; c < NC; c++) if (cc == c) pm[c] = fmaxf(pm[c], a);
    }
#pragma unroll
    for (int c = 0; c < NC; c++)
#pragma unroll
        for (int o = 16; o > 0; o >>= 1)
            pm[c] = fmaxf(pm[c], __shfl_xor_sync(0xFFFFFFFFu, pm[c], o));

    // phase 2: per-cluster denom + count
    float pd[NC], pc[NC];
#pragma unroll
    for (int c = 0; c < NC; c++) { pd[c] = 0.f; pc[c] = 0.f; }
    for (int j = lane; j < deg; j += 32) {
        float a, cf; up2(g_ac[off + j], a, cf);
        int cc = __float_as_int(cf);
        float cmv = 0.f;
#pragma unroll
        for (int c = 0; c < NC; c++) if (cc == c) cmv = pm[c];
        float e = __expf(a - cmv);
#pragma unroll
        for (int c = 0; c < NC; c++) {
            pd[c] += (cc == c) ? e : 0.f;
            pc[c] += (cc == c) ? 1.f : 0.f;
        }
    }
#pragma unroll
    for (int c = 0; c < NC; c++)
#pragma unroll
        for (int o = 16; o > 0; o >>= 1) {
            pd[c] += __shfl_xor_sync(0xFFFFFFFFu, pd[c], o);
            pc[c] += __shfl_xor_sync(0xFFFFFFFFu, pc[c], o);
        }

    float sinv[NC]; float bsc = 0.f;
#pragma unroll
    for (int c = 0; c < NC; c++) {
        if (pc[c] > 0.f) {
            sinv[c] = inv / (pd[c] * pc[c]);
            bsc += 1.0f / pc[c];
        } else sinv[c] = 0.f;
    }

    // phase 3: weighted sum; tf read fp16 via eid (1 line / edge / warp)
    u64 acc = 0ull;
    if (deg > 0) {
        u64 ac_n = g_ac[off];
        int eid_n = g_eid[off];
        u32 tv_n = g_tfh[(size_t)eid_n * 32 + lane];
        for (int j = 0; j < deg; j++) {
            u64 acj = ac_n; u32 tv = tv_n;
            if (j + 1 < deg) {
                ac_n = g_ac[off + j + 1];
                eid_n = g_eid[off + j + 1];
                tv_n = g_tfh[(size_t)eid_n * 32 + lane];
            }
            float a, cf; up2(acj, a, cf);
            int cc = __float_as_int(cf);
            float cmv = 0.f, sv = 0.f;
#pragma unroll
            for (int c = 0; c < NC; c++) if (cc == c) { cmv = pm[c]; sv = sinv[c]; }
            float coef = __expf(a - cmv) * sv;
            __half2 h = *reinterpret_cast<__half2*>(&tv);
            float2 f = __half22float2(h);
            fma2(acc, pk2(coef, coef), pk2(f.x, f.y));
        }
    }
    float lo, hi; up2(acc, lo, hi);
    reinterpret_cast<float2*>(g_accN + (size_t)n * D)[lane] = make_float2(lo, hi);
    if (lane == 0) g_bsc[n] = bsc * inv;
}

// ---------------- K6: fused = relu(accN @ Wvo + bvo*bsc + b_out)  [staged] ------
__global__ __launch_bounds__(256) void k_E2(const float* __restrict__ bo) {
    extern __shared__ float smem[];
    float* sW  = smem;            // 64*64
    float* sbv = sW + D * D;
    float* sbo = sbv + D;
    float* sx  = sbo + D;         // 128*PAD
    for (int t = threadIdx.x; t < D * D / 4; t += 256)
        reinterpret_cast<float4*>(sW)[t] = reinterpret_cast<const float4*>(g_Wvo)[t];
    if (threadIdx.x < D) { sbv[threadIdx.x] = g_bvo[threadIdx.x]; sbo[threadIdx.x] = bo[threadIdx.x]; }
    for (int t = threadIdx.x; t < 128 * 16; t += 256) {
        int row = t >> 4, c4 = t & 15;
        int rsrc = min(blockIdx.x * 128 + row, N_NODES - 1);
        reinterpret_cast<float4*>(sx + row * PAD)[c4] =
            reinterpret_cast<const float4*>(g_accN + (size_t)rsrc * D)[c4];
    }
    __syncthreads();
    int wid = threadIdx.x >> 5, lane = threadIdx.x & 31;
    int q = wid & 3, grp = wid >> 2;
    int rl0 = grp * 64 + lane, rl1 = rl0 + 32;
    int r0 = blockIdx.x * 128 + rl0, r1 = blockIdx.x * 128 + rl1;
    int r0c = min(r0, N_NODES - 1), r1c = min(r1, N_NODES - 1);
    float bs0 = g_bsc[r0c], bs1 = g_bsc[r1c];

    u64 a0[8], a1[8];
    const float* bvq = sbv + q * 16;
    const float* boq = sbo + q * 16;
#pragma unroll
    for (int k = 0; k < 8; k++) {
        a0[k] = pk2(fmaf(bvq[2*k], bs0, boq[2*k]), fmaf(bvq[2*k+1], bs0, boq[2*k+1]));
        a1[k] = pk2(fmaf(bvq[2*k], bs1, boq[2*k]), fmaf(bvq[2*k+1], bs1, boq[2*k+1]));
    }
    const float* x0 = sx + rl0 * PAD;
    const float* x1 = sx + rl1 * PAD;
    const float* wq = sW + q * 16;
#pragma unroll
    for (int jv = 0; jv < 16; jv++) {
        float4 v0 = reinterpret_cast<const float4*>(x0)[jv];
        float4 v1 = reinterpret_cast<const float4*>(x1)[jv];
        const float* w0 = wq + (4 * jv) * D;
        colupd(a0, a1, v0.x, v1.x, w0);
        colupd(a0, a1, v0.y, v1.y, w0 + D);
        colupd(a0, a1, v0.z, v1.z, w0 + 2 * D);
        colupd(a0, a1, v0.w, v1.w, w0 + 3 * D);
    }
    if (r0 < N_NODES) {
        float4* o0 = reinterpret_cast<float4*>(g_fused + (size_t)r0 * D + q * 16);
#pragma unroll
        for (int k = 0; k < 4; k++) o0[k] = relu4(a0[2*k], a0[2*k+1]);
    }
    if (r1 < N_NODES) {
        float4* o1 = reinterpret_cast<float4*>(g_fused + (size_t)r1 * D + q * 16);
#pragma unroll
        for (int k = 0; k < 4; k++) o1[k] = relu4(a1[2*k], a1[2*k+1]);
    }
}

// ---------------- K7: out = x + fused @ W_up + b_up  [staged] -------------------
__global__ __launch_bounds__(256) void k_E3(const float* __restrict__ x,
                                            const float* __restrict__ Wup,
                                            const float* __restrict__ bup,
                                            float* __restrict__ out) {
    extern __shared__ float smem[];
    float* sW = smem;                 // 64 x 128 slice
    float* sb = sW + D * 128;         // 128
    float* sx = sb + 128;             // 64*PAD
    int gy = blockIdx.y;
    for (int t = threadIdx.x; t < D * 128 / 4; t += 256) {
        int row = t >> 5, c4 = t & 31;
        reinterpret_cast<float4*>(sW + row * 128)[c4] =
            reinterpret_cast<const float4*>(Wup + row * IN_CH + gy * 128)[c4];
    }
    if (threadIdx.x < 128) sb[threadIdx.x] = bup[gy * 128 + threadIdx.x];
    for (int t = threadIdx.x; t < 64 * 16; t += 256) {
        int row = t >> 4, c4 = t & 15;
        int rsrc = min(blockIdx.x * 64 + row, N_NODES - 1);
        reinterpret_cast<float4*>(sx + row * PAD)[c4] =
            reinterpret_cast<const float4*>(g_fused + (size_t)rsrc * D)[c4];
    }
    __syncthreads();
    int wid = threadIdx.x >> 5, lane = threadIdx.x & 31;
    int q = wid;
    int rl0 = lane, rl1 = lane + 32;
    int r0 = blockIdx.x * 64 + rl0, r1 = blockIdx.x * 64 + rl1;

    u64 a0[8], a1[8];
    const u64* bb = reinterpret_cast<const u64*>(sb + q * 16);
#pragma unroll
    for (int k = 0; k < 8; k++) { a0[k] = bb[k]; a1[k] = bb[k]; }

    const float* f0 = sx + rl0 * PAD;
    const float* f1 = sx + rl1 * PAD;
    const float* wq = sW + q * 16;
#pragma unroll
    for (int jv = 0; jv < 16; jv++) {
        float4 v0 = reinterpret_cast<const float4*>(f0)[jv];
        float4 v1 = reinterpret_cast<const float4*>(f1)[jv];
        const float* w0 = wq + (4 * jv) * 128;
        colupd(a0, a1, v0.x, v1.x, w0);
        colupd(a0, a1, v0.y, v1.y, w0 + 128);
        colupd(a0, a1, v0.z, v1.z, w0 + 2 * 128);
        colupd(a0, a1, v0.w, v1.w, w0 + 3 * 128);
    }
    int colbase = gy * 128 + q * 16;
    if (r0 < N_NODES) {
        const float4* xr = reinterpret_cast<const float4*>(x + (size_t)r0 * IN_CH + colbase);
        float4* o = reinterpret_cast<float4*>(out + (size_t)r0 * IN_CH + colbase);
#pragma unroll
        for (int k = 0; k < 4; k++) {
            float4 r = raw4(a0[2*k], a0[2*k+1]);
            float4 xv = xr[k];
            o[k] = make_float4(xv.x + r.x, xv.y + r.y, xv.z + r.z, xv.w + r.w);
        }
    }
    if (r1 < N_NODES) {
        const float4* xr = reinterpret_cast<const float4*>(x + (size_t)r1 * IN_CH + colbase);
        float4* o = reinterpret_cast<float4*>(out + (size_t)r1 * IN_CH + colbase);
#pragma unroll
        for (int k = 0; k < 4; k++) {
            float4 r = raw4(a1[2*k], a1[2*k+1]);
            float4 xv = xr[k];
            o[k] = make_float4(xv.x + r.x, xv.y + r.y, xv.z + r.z, xv.w + r.w);
        }
    }
}

// -------------------------------------------------------------------------------
extern "C" void kernel_launch(void* const* d_in, const int* in_sizes, int n_in,
                              void* d_out, int out_size) {
    const float* x   = (const float*)d_in[0];
    const float* ea  = (const float*)d_in[1];
    const int*   ei  = (const int*)  d_in[2];
    const float* Wd  = (const float*)d_in[3];
    const float* bd  = (const float*)d_in[4];
    const float* Wup = (const float*)d_in[5];
    const float* bup = (const float*)d_in[6];
    const float* Wt  = (const float*)d_in[7];
    const float* bt  = (const float*)d_in[8];
    const float* Wq  = (const float*)d_in[9];
    const float* bq  = (const float*)d_in[10];
    const float* Wk  = (const float*)d_in[11];
    const float* bk  = (const float*)d_in[12];
    const float* Wv  = (const float*)d_in[13];
    const float* bv  = (const float*)d_in[14];
    const float* ce  = (const float*)d_in[15];
    const float* Wo  = (const float*)d_in[16];
    const float* bo  = (const float*)d_in[17];
    float* out = (float*)d_out;

    int smA  = (IN_CH * D + D * D + 3 * D + 128 * PAD) * 4;  // ~117.5KB
    int smE1 = (16 * D + D + NC * D + NC) * 4 + 256 * 17 * 8; // ~41.2KB
    int smE2 = (D * D + 2 * D + 128 * PAD) * 4;               // ~51.7KB
    int smE3 = (D * 128 + 128 + 64 * PAD) * 4;                // ~50.7KB
    cudaFuncSetAttribute(k_nodeA, cudaFuncAttributeMaxDynamicSharedMemorySize, smA);
    cudaFuncSetAttribute(k_E2,    cudaFuncAttributeMaxDynamicSharedMemorySize, smE2);
    cudaFuncSetAttribute(k_E3,    cudaFuncAttributeMaxDynamicSharedMemorySize, smE3);

    int nblk128 = (N_NODES + 127) / 128;       // 391
    k_init  <<<(N_NODES + 255) / 256, 256>>>();
    k_count <<<(N_EDGES + 255) / 256, 256>>>(ei);
    k_scan1 <<<NBLK_SC, 256>>>();
    k_scan2 <<<1, 256>>>();
    k_scan3 <<<NBLK_SC, 256>>>();
    k_prep  <<<16, 256>>>(Wq, bq, Wk, bk, Wv, bv, Wo, bo);
    k_nodeA <<<nblk128, 256, smA>>>(x, Wd, bd);
    k_edge1 <<<N_EDGES / 256, 256, smE1>>>(ea, ei, Wt, bt, ce);
    k_gather<<<N_NODES / 8, 256>>>();
    k_E2    <<<nblk128, 256, smE2>>>(bo);
    k_E3    <<<dim3((N_NODES + 63) / 64, 2), 256, smE3>>>(x, Wup, bup, out);
}

// round 6
// speedup vs baseline: 1.5825x; 1.0142x over previous
#include <cuda_runtime.h>
#include <cuda_fp16.h>
#include <math.h>

#define N_NODES 50000
#define N_EDGES 800000
#define IN_CH   256
#define D       64
#define NC      8
#define NBLK_SC 196         // ceil(50000/256)

typedef unsigned long long u64;
typedef unsigned int u32;

// ---------------- f32x2 packed helpers ----------------------------------------
__device__ __forceinline__ u64 pk2(float lo, float hi) {
    u64 r; asm("mov.b64 %0, {%1, %2};" : "=l"(r) : "f"(lo), "f"(hi)); return r;
}
__device__ __forceinline__ void up2(u64 v, float& lo, float& hi) {
    asm("mov.b64 {%0, %1}, %2;" : "=f"(lo), "=f"(hi) : "l"(v));
}
__device__ __forceinline__ void fma2(u64& d, u64 a, u64 b) {
    asm("fma.rn.f32x2 %0, %1, %2, %0;" : "+l"(d) : "l"(a), "l"(b));
}
__device__ __forceinline__ void rank1_64(u64* acc, float s, const float* wrow) {
    u64 s2 = pk2(s, s);
    const ulonglong2* w = reinterpret_cast<const ulonglong2*>(wrow);
#pragma unroll
    for (int t = 0; t < 16; t++) {
        ulonglong2 ww = w[t];
        fma2(acc[2*t],   s2, ww.x);
        fma2(acc[2*t+1], s2, ww.y);
    }
}
__device__ __forceinline__ float dot64(const u64* a, const float* wrow) {
    u64 s = 0ull;
    const ulonglong2* w = reinterpret_cast<const ulonglong2*>(wrow);
#pragma unroll
    for (int t = 0; t < 16; t++) {
        ulonglong2 ww = w[t];
        fma2(s, a[2*t],   ww.x);
        fma2(s, a[2*t+1], ww.y);
    }
    float lo, hi; up2(s, lo, hi); return lo + hi;
}
// 2 rows x 16 outputs per input column; wp is WARP-UNIFORM (broadcast LDS)
__device__ __forceinline__ void colupd(u64* a0, u64* a1, float s0, float s1,
                                       const float* wp) {
    u64 p0 = pk2(s0, s0), p1 = pk2(s1, s1);
    const ulonglong2* w = reinterpret_cast<const ulonglong2*>(wp);
    ulonglong2 wa = w[0], wb = w[1], wc = w[2], wd = w[3];
    fma2(a0[0], p0, wa.x); fma2(a1[0], p1, wa.x);
    fma2(a0[1], p0, wa.y); fma2(a1[1], p1, wa.y);
    fma2(a0[2], p0, wb.x); fma2(a1[2], p1, wb.x);
    fma2(a0[3], p0, wb.y); fma2(a1[3], p1, wb.y);
    fma2(a0[4], p0, wc.x); fma2(a1[4], p1, wc.x);
    fma2(a0[5], p0, wc.y); fma2(a1[5], p1, wc.y);
    fma2(a0[6], p0, wd.x); fma2(a1[6], p1, wd.x);
    fma2(a0[7], p0, wd.y); fma2(a1[7], p1, wd.y);
}
__device__ __forceinline__ float4 relu4(u64 a, u64 b) {
    float x, y, z, w; up2(a, x, y); up2(b, z, w);
    return make_float4(fmaxf(x, 0.f), fmaxf(y, 0.f), fmaxf(z, 0.f), fmaxf(w, 0.f));
}
__device__ __forceinline__ float4 raw4(u64 a, u64 b) {
    float x, y, z, w; up2(a, x, y); up2(b, z, w);
    return make_float4(x, y, z, w);
}
// XOR swizzle: logical (row, c4) -> physical float4 index (conflict-free LDS)
#define SWZ(row, c4) (((row) << 4) + ((c4) ^ ((row) & 15)))

// ---------------- scratch ------------------------------------------------------
__device__ float g_qk  [N_NODES * D];
__device__ float g_qb  [N_NODES];
__device__ u32   g_tfh [(size_t)N_EDGES * 32];  // fp16 tf, edge order (102.4MB)
__device__ u64   g_ac  [N_EDGES];               // CSR-pos {attn, cluster}
__device__ int   g_eid [N_EDGES];               // CSR-pos -> edge id
__device__ int   g_deg [N_NODES];
__device__ int   g_off [N_NODES + 1];
__device__ int   g_cur [N_NODES];
__device__ int   g_bsum[NBLK_SC], g_boff[NBLK_SC];
__device__ float g_cec [NC];
__device__ float g_accN[N_NODES * D];
__device__ float g_bsc [N_NODES];
__device__ float g_fused[N_NODES * D];
__device__ float g_Wqk[D * D], g_bqk[D], g_wqb[D], g_sqb;
__device__ float g_Wvo[D * D], g_bvo[D];

// ---------------- K0: zero deg + cec -------------------------------------------
__global__ void k_init() {
    int i = blockIdx.x * blockDim.x + threadIdx.x;
    if (i < N_NODES) g_deg[i] = 0;
    if (i < NC) g_cec[i] = 0.f;
}
__global__ void k_count(const int* __restrict__ ei) {
    int e = blockIdx.x * blockDim.x + threadIdx.x;
    if (e < N_EDGES) atomicAdd(&g_deg[ei[e]], 1);
}
// ---------------- scan (3 stages) ----------------------------------------------
__global__ void k_scan1() {
    __shared__ int s[256];
    int t = threadIdx.x;
    int i = blockIdx.x * 256 + t;
    int v = (i < N_NODES) ? g_deg[i] : 0;
    s[t] = v; __syncthreads();
#pragma unroll
    for (int o = 1; o < 256; o <<= 1) {
        int xv = (t >= o) ? s[t - o] : 0;
        __syncthreads();
        s[t] += xv;
        __syncthreads();
    }
    if (i < N_NODES) g_off[i] = s[t] - v;
    if (t == 255) g_bsum[blockIdx.x] = s[255];
}
__global__ void k_scan2() {
    __shared__ int s[256];
    int t = threadIdx.x;
    int v = (t < NBLK_SC) ? g_bsum[t] : 0;
    s[t] = v; __syncthreads();
#pragma unroll
    for (int o = 1; o < 256; o <<= 1) {
        int xv = (t >= o) ? s[t - o] : 0;
        __syncthreads();
        s[t] += xv;
        __syncthreads();
    }
    if (t < NBLK_SC) g_boff[t] = s[t] - v;
}
__global__ void k_scan3() {
    int i = blockIdx.x * 256 + threadIdx.x;
    if (i < N_NODES) {
        int o = g_off[i] + g_boff[blockIdx.x];
        g_off[i] = o;
        g_cur[i] = o;
    }
    if (i == 0) g_off[N_NODES] = N_EDGES;
}

// ---------------- K1: fold weights ---------------------------------------------
__global__ void k_prep(const float* __restrict__ Wq, const float* __restrict__ bq,
                       const float* __restrict__ Wk, const float* __restrict__ bk,
                       const float* __restrict__ Wv, const float* __restrict__ bv,
                       const float* __restrict__ Wo, const float* __restrict__ bo) {
    int idx = blockIdx.x * blockDim.x + threadIdx.x;
    if (idx < D * D) {
        int t = idx >> 6, j = idx & 63;
        float s1 = 0.f, s2 = 0.f;
        for (int d = 0; d < D; d++) {
            s1 = fmaf(Wq[t * D + d], Wk[j * D + d], s1);
            s2 = fmaf(Wv[t * D + d], Wo[d * D + j], s2);
        }
        g_Wqk[t * D + j] = s1;
        g_Wvo[t * D + j] = s2;
    }
    if (idx < D) {
        int j = idx;
        float a = 0.f, b = 0.f, c = 0.f;
        for (int d = 0; d < D; d++) {
            a = fmaf(bq[d], Wk[j * D + d], a);
            b = fmaf(bv[d], Wo[d * D + j], b);
            c = fmaf(Wq[j * D + d], bk[d], c);
        }
        g_bqk[j] = a; g_bvo[j] = b; g_wqb[j] = c;
        if (idx == 0) {
            float s = 0.f;
            for (int d = 0; d < D; d++) s = fmaf(bq[d], bk[d], s);
            g_sqb = s;
        }
    }
}

// ---------------- K2: FUSED nodeA — qk = relu(x@Wd+bd)@Wqk + bqk, qb -------------
__global__ __launch_bounds__(256) void k_nodeA(const float* __restrict__ x,
                                               const float* __restrict__ Wd,
                                               const float* __restrict__ bd) {
    extern __shared__ float smem[];
    float* sWd = smem;                     // 256*64
    float* sWq = sWd + IN_CH * D;          // 64*64
    float* sbd = sWq + D * D;              // 64
    float* sbq = sbd + D;                  // 64
    float* swq = sbq + D;                  // 64
    float4* sx4 = reinterpret_cast<float4*>(swq + D);  // 128 rows x 16 float4 (swizzled)
    for (int t = threadIdx.x; t < IN_CH * D / 4; t += 256)
        reinterpret_cast<float4*>(sWd)[t] = reinterpret_cast<const float4*>(Wd)[t];
    for (int t = threadIdx.x; t < D * D / 4; t += 256)
        reinterpret_cast<float4*>(sWq)[t] = reinterpret_cast<const float4*>(g_Wqk)[t];
    if (threadIdx.x < D) {
        sbd[threadIdx.x] = bd[threadIdx.x];
        sbq[threadIdx.x] = g_bqk[threadIdx.x];
        swq[threadIdx.x] = g_wqb[threadIdx.x];
    }

    int wid = threadIdx.x >> 5, lane = threadIdx.x & 31;
    int q = wid & 3, grp = wid >> 2;
    int rl0 = grp * 64 + lane, rl1 = rl0 + 32;
    int sw0 = rl0 & 15;                    // swizzle key (same for rl1)
    int r0 = blockIdx.x * 128 + rl0, r1 = blockIdx.x * 128 + rl1;

    u64 a0[8], a1[8];
    const float* wq1 = sWd + q * 16;
    // phase 1: nf = relu(x @ Wd + bd), k-chunked staging
#pragma unroll
    for (int kc = 0; kc < 4; kc++) {
        __syncthreads();
        for (int t = threadIdx.x; t < 128 * 16; t += 256) {
            int row = t >> 4, c4 = t & 15;
            int rsrc = min(blockIdx.x * 128 + row, N_NODES - 1);
            sx4[SWZ(row, c4)] =
                reinterpret_cast<const float4*>(x + (size_t)rsrc * IN_CH + kc * 64)[c4];
        }
        __syncthreads();
        if (kc == 0) {
            const u64* bb = reinterpret_cast<const u64*>(sbd + q * 16);
#pragma unroll
            for (int k = 0; k < 8; k++) { a0[k] = bb[k]; a1[k] = bb[k]; }
        }
#pragma unroll
        for (int jv = 0; jv < 16; jv++) {
            float4 v0 = sx4[(rl0 << 4) + (jv ^ sw0)];
            float4 v1 = sx4[(rl1 << 4) + (jv ^ sw0)];
            const float* w0 = wq1 + (kc * 64 + 4 * jv) * D;
            colupd(a0, a1, v0.x, v1.x, w0);
            colupd(a0, a1, v0.y, v1.y, w0 + D);
            colupd(a0, a1, v0.z, v1.z, w0 + 2 * D);
            colupd(a0, a1, v0.w, v1.w, w0 + 3 * D);
        }
    }
    // write relu(nf) tile into sx (swizzled)
    __syncthreads();
#pragma unroll
    for (int k = 0; k < 4; k++) {
        sx4[SWZ(rl0, q * 4 + k)] = relu4(a0[2*k], a0[2*k+1]);
        sx4[SWZ(rl1, q * 4 + k)] = relu4(a1[2*k], a1[2*k+1]);
    }
    __syncthreads();
    // phase 2: qk = nf @ Wqk + bqk
    {
        const u64* bb = reinterpret_cast<const u64*>(sbq + q * 16);
#pragma unroll
        for (int k = 0; k < 8; k++) { a0[k] = bb[k]; a1[k] = bb[k]; }
    }
    float qb0 = g_sqb, qb1 = g_sqb;
    const float* wq2 = sWq + q * 16;
#pragma unroll
    for (int jv = 0; jv < 16; jv++) {
        float4 v0 = sx4[(rl0 << 4) + (jv ^ sw0)];
        float4 v1 = sx4[(rl1 << 4) + (jv ^ sw0)];
        const float* w0 = wq2 + (4 * jv) * D;
        colupd(a0, a1, v0.x, v1.x, w0);
        colupd(a0, a1, v0.y, v1.y, w0 + D);
        colupd(a0, a1, v0.z, v1.z, w0 + 2 * D);
        colupd(a0, a1, v0.w, v1.w, w0 + 3 * D);
        if (q == 0) {
            qb0 = fmaf(v0.x, swq[4*jv], fmaf(v0.y, swq[4*jv+1], fmaf(v0.z, swq[4*jv+2], fmaf(v0.w, swq[4*jv+3], qb0))));
            qb1 = fmaf(v1.x, swq[4*jv], fmaf(v1.y, swq[4*jv+1], fmaf(v1.z, swq[4*jv+2], fmaf(v1.w, swq[4*jv+3], qb1))));
        }
    }
    if (r0 < N_NODES) {
        float4* o0 = reinterpret_cast<float4*>(g_qk + (size_t)r0 * D + q * 16);
#pragma unroll
        for (int k = 0; k < 4; k++) o0[k] = raw4(a0[2*k], a0[2*k+1]);
    }
    if (r1 < N_NODES) {
        float4* o1 = reinterpret_cast<float4*>(g_qk + (size_t)r1 * D + q * 16);
#pragma unroll
        for (int k = 0; k < 4; k++) o1[k] = raw4(a1[2*k], a1[2*k+1]);
    }
    if (q == 0) {
        if (r0 < N_NODES) g_qb[r0] = qb0;
        if (r1 < N_NODES) g_qb[r1] = qb1;
    }
}

// per-edge time_feat (weights warp-uniform)
__device__ __forceinline__ void edge_tf(u64* acc, const float* __restrict__ ea, int e,
                                        const float* sW, const float* sb) {
    const u64* sb2 = reinterpret_cast<const u64*>(sb);
#pragma unroll
    for (int t = 0; t < 32; t++) acc[t] = sb2[t];
    const float4* ar = reinterpret_cast<const float4*>(ea + (size_t)e * 16);
#pragma unroll
    for (int jv = 0; jv < 4; jv++) {
        float4 a = ar[jv];
        const float* w0 = sW + (jv * 4) * D;
        rank1_64(acc, a.x, w0);
        rank1_64(acc, a.y, w0 + D);
        rank1_64(acc, a.z, w0 + 2 * D);
        rank1_64(acc, a.w, w0 + 3 * D);
    }
#pragma unroll
    for (int t = 0; t < 32; t++) {
        float lo, hi; up2(acc[t], lo, hi);
        acc[t] = pk2(fmaxf(lo, 0.f), fmaxf(hi, 0.f));
    }
}

// ---------------- K4: edge pass — tf(fp16, coalesced), cluster, attn → CSR meta -
__global__ __launch_bounds__(256) void k_edge1(const float* __restrict__ ea,
                                               const int* __restrict__ ei,
                                               const float* __restrict__ Wt,
                                               const float* __restrict__ bt,
                                               const float* __restrict__ ce) {
    extern __shared__ float smem[];
    float* sW = smem;            // 16*64
    float* sb = sW + 16 * D;     // 64
    float* sc = sb + D;          // 8*64
    float* scec = sc + NC * D;   // 8
    u64* su = reinterpret_cast<u64*>(scec + NC);  // 256*17 u64 stage
    for (int t = threadIdx.x; t < 16 * D / 4; t += 256)
        reinterpret_cast<float4*>(sW)[t] = reinterpret_cast<const float4*>(Wt)[t];
    if (threadIdx.x < D) sb[threadIdx.x] = bt[threadIdx.x];
    for (int t = threadIdx.x; t < NC * D / 4; t += 256)
        reinterpret_cast<float4*>(sc)[t] = reinterpret_cast<const float4*>(ce)[t];
    if (threadIdx.x < NC) scec[threadIdx.x] = 0.f;
    __syncthreads();
    int e = blockIdx.x * 256 + threadIdx.x;   // N_EDGES % 256 == 0

    u64 tf[32];
    edge_tf(tf, ea, e, sW, sb);

    int bc = 0; float bv = dot64(tf, sc);
#pragma unroll
    for (int c = 1; c < NC; c++) {
        float s = dot64(tf, sc + c * D);
        if (s > bv) { bv = s; bc = c; }
    }

    int src = ei[e];
    const float4* qr = reinterpret_cast<const float4*>(g_qk + (size_t)src * D);
    u64 s = 0ull;
#pragma unroll
    for (int tv = 0; tv < 16; tv++) {
        float4 qv = qr[tv];
        fma2(s, tf[2*tv],   pk2(qv.x, qv.y));
        fma2(s, tf[2*tv+1], pk2(qv.z, qv.w));
    }
    float lo, hi; up2(s, lo, hi);
    float attn = (lo + hi + g_qb[src]) * 0.125f;

    atomicAdd(&scec[bc], 1.f);
    int pos = atomicAdd(&g_cur[src], 1);
    g_ac[pos] = pk2(attn, __int_as_float(bc));
    g_eid[pos] = e;

    // convert tf -> fp16 pairs, stage in smem, store coalesced (edge order)
#pragma unroll
    for (int c = 0; c < 16; c++) {
        float a, b; up2(tf[2*c], a, b);
        float cc, d; up2(tf[2*c+1], cc, d);
        __half2 h0 = __floats2half2_rn(a, b);
        __half2 h1 = __floats2half2_rn(cc, d);
        u32 l0 = *reinterpret_cast<u32*>(&h0);
        u32 l1 = *reinterpret_cast<u32*>(&h1);
        su[threadIdx.x * 17 + c] = (u64)l0 | ((u64)l1 << 32);
    }
    __syncthreads();
    u64* gout = reinterpret_cast<u64*>(g_tfh) + (size_t)blockIdx.x * 4096;
#pragma unroll
    for (int k = 0; k < 16; k++) {
        int idx = threadIdx.x + k * 256;
        int el = idx >> 4, c = idx & 15;
        gout[idx] = su[el * 17 + c];
    }
    if (threadIdx.x < NC) atomicAdd(&g_cec[threadIdx.x], scec[threadIdx.x]);
}

// ---------------- K5: warp-per-node gather --------------------------------------
__global__ __launch_bounds__(256) void k_gather() {
    int wid = threadIdx.x >> 5, lane = threadIdx.x & 31;
    int n = blockIdx.x * 8 + wid;           // grid = 6250 exact
    int off = g_off[n];
    int deg = g_off[n + 1] - off;

    float nne = 0.f;
#pragma unroll
    for (int c = 0; c < NC; c++) nne += (g_cec[c] > 0.f) ? 1.f : 0.f;
    float inv = 1.0f / nne;

    // phase 1: per-cluster max (lane-parallel over edges)
    float pm[NC];
#pragma unroll
    for (int c = 0; c < NC; c++) pm[c] = -3.4e38f;
    for (int j = lane; j < deg; j += 32) {
        float a, cf; up2(g_ac[off + j], a, cf);
        int cc = __float_as_int(cf);
#pragma unroll
        for (int c = 0; c < NC; c++) if (cc == c) pm[c] = fmaxf(pm[c], a);
    }
#pragma unroll
    for (int c = 0; c < NC; c++)
#pragma unroll
        for (int o = 16; o > 0; o >>= 1)
            pm[c] = fmaxf(pm[c], __shfl_xor_sync(0xFFFFFFFFu, pm[c], o));

    // phase 2: per-cluster denom + count
    float pd[NC], pc[NC];
#pragma unroll
    for (int c = 0; c < NC; c++) { pd[c] = 0.f; pc[c] = 0.f; }
    for (int j = lane; j < deg; j += 32) {
        float a, cf; up2(g_ac[off + j], a, cf);
        int cc = __float_as_int(cf);
        float cmv = 0.f;
#pragma unroll
        for (int c = 0; c < NC; c++) if (cc == c) cmv = pm[c];
        float e = __expf(a - cmv);
#pragma unroll
        for (int c = 0; c < NC; c++) {
            pd[c] += (cc == c) ? e : 0.f;
            pc[c] += (cc == c) ? 1.f : 0.f;
        }
    }
#pragma unroll
    for (int c = 0; c < NC; c++)
#pragma unroll
        for (int o = 16; o > 0; o >>= 1) {
            pd[c] += __shfl_xor_sync(0xFFFFFFFFu, pd[c], o);
            pc[c] += __shfl_xor_sync(0xFFFFFFFFu, pc[c], o);
        }

    float sinv[NC]; float bsc = 0.f;
#pragma unroll
    for (int c = 0; c < NC; c++) {
        if (pc[c] > 0.f) {
            sinv[c] = inv / (pd[c] * pc[c]);
            bsc += 1.0f / pc[c];
        } else sinv[c] = 0.f;
    }

    // phase 3: weighted sum; tf read fp16 via eid (1 line / edge / warp)
    u64 acc = 0ull;
    if (deg > 0) {
        u64 ac_n = g_ac[off];
        int eid_n = g_eid[off];
        u32 tv_n = g_tfh[(size_t)eid_n * 32 + lane];
        for (int j = 0; j < deg; j++) {
            u64 acj = ac_n; u32 tv = tv_n;
            if (j + 1 < deg) {
                ac_n = g_ac[off + j + 1];
                eid_n = g_eid[off + j + 1];
                tv_n = g_tfh[(size_t)eid_n * 32 + lane];
            }
            float a, cf; up2(acj, a, cf);
            int cc = __float_as_int(cf);
            float cmv = 0.f, sv = 0.f;
#pragma unroll
            for (int c = 0; c < NC; c++) if (cc == c) { cmv = pm[c]; sv = sinv[c]; }
            float coef = __expf(a - cmv) * sv;
            __half2 h = *reinterpret_cast<__half2*>(&tv);
            float2 f = __half22float2(h);
            fma2(acc, pk2(coef, coef), pk2(f.x, f.y));
        }
    }
    float lo, hi; up2(acc, lo, hi);
    reinterpret_cast<float2*>(g_accN + (size_t)n * D)[lane] = make_float2(lo, hi);
    if (lane == 0) g_bsc[n] = bsc * inv;
}

// ---------------- K6: fused = relu(accN @ Wvo + bvo*bsc + b_out)  [swizzled] ----
__global__ __launch_bounds__(256) void k_E2(const float* __restrict__ bo) {
    extern __shared__ float smem[];
    float* sW  = smem;            // 64*64
    float* sbv = sW + D * D;
    float* sbo = sbv + D;
    float4* sx4 = reinterpret_cast<float4*>(sbo + D);   // 128 x 16 float4 swizzled
    for (int t = threadIdx.x; t < D * D / 4; t += 256)
        reinterpret_cast<float4*>(sW)[t] = reinterpret_cast<const float4*>(g_Wvo)[t];
    if (threadIdx.x < D) { sbv[threadIdx.x] = g_bvo[threadIdx.x]; sbo[threadIdx.x] = bo[threadIdx.x]; }
    for (int t = threadIdx.x; t < 128 * 16; t += 256) {
        int row = t >> 4, c4 = t & 15;
        int rsrc = min(blockIdx.x * 128 + row, N_NODES - 1);
        sx4[SWZ(row, c4)] =
            reinterpret_cast<const float4*>(g_accN + (size_t)rsrc * D)[c4];
    }
    __syncthreads();
    int wid = threadIdx.x >> 5, lane = threadIdx.x & 31;
    int q = wid & 3, grp = wid >> 2;
    int rl0 = grp * 64 + lane, rl1 = rl0 + 32;
    int sw0 = rl0 & 15;
    int r0 = blockIdx.x * 128 + rl0, r1 = blockIdx.x * 128 + rl1;
    int r0c = min(r0, N_NODES - 1), r1c = min(r1, N_NODES - 1);
    float bs0 = g_bsc[r0c], bs1 = g_bsc[r1c];

    u64 a0[8], a1[8];
    const float* bvq = sbv + q * 16;
    const float* boq = sbo + q * 16;
#pragma unroll
    for (int k = 0; k < 8; k++) {
        a0[k] = pk2(fmaf(bvq[2*k], bs0, boq[2*k]), fmaf(bvq[2*k+1], bs0, boq[2*k+1]));
        a1[k] = pk2(fmaf(bvq[2*k], bs1, boq[2*k]), fmaf(bvq[2*k+1], bs1, boq[2*k+1]));
    }
    const float* wq = sW + q * 16;
#pragma unroll
    for (int jv = 0; jv < 16; jv++) {
        float4 v0 = sx4[(rl0 << 4) + (jv ^ sw0)];
        float4 v1 = sx4[(rl1 << 4) + (jv ^ sw0)];
        const float* w0 = wq + (4 * jv) * D;
        colupd(a0, a1, v0.x, v1.x, w0);
        colupd(a0, a1, v0.y, v1.y, w0 + D);
        colupd(a0, a1, v0.z, v1.z, w0 + 2 * D);
        colupd(a0, a1, v0.w, v1.w, w0 + 3 * D);
    }
    if (r0 < N_NODES) {
        float4* o0 = reinterpret_cast<float4*>(g_fused + (size_t)r0 * D + q * 16);
#pragma unroll
        for (int k = 0; k < 4; k++) o0[k] = relu4(a0[2*k], a0[2*k+1]);
    }
    if (r1 < N_NODES) {
        float4* o1 = reinterpret_cast<float4*>(g_fused + (size_t)r1 * D + q * 16);
#pragma unroll
        for (int k = 0; k < 4; k++) o1[k] = relu4(a1[2*k], a1[2*k+1]);
    }
}

// ---------------- K7: out = x + fused @ W_up + b_up  [swizzled] -----------------
__global__ __launch_bounds__(256) void k_E3(const float* __restrict__ x,
                                            const float* __restrict__ Wup,
                                            const float* __restrict__ bup,
                                            float* __restrict__ out) {
    extern __shared__ float smem[];
    float* sW = smem;                 // 64 x 128 slice
    float* sb = sW + D * 128;         // 128
    float4* sx4 = reinterpret_cast<float4*>(sb + 128);  // 64 x 16 float4 swizzled
    int gy = blockIdx.y;
    for (int t = threadIdx.x; t < D * 128 / 4; t += 256) {
        int row = t >> 5, c4 = t & 31;
        reinterpret_cast<float4*>(sW + row * 128)[c4] =
            reinterpret_cast<const float4*>(Wup + row * IN_CH + gy * 128)[c4];
    }
    if (threadIdx.x < 128) sb[threadIdx.x] = bup[gy * 128 + threadIdx.x];
    for (int t = threadIdx.x; t < 64 * 16; t += 256) {
        int row = t >> 4, c4 = t & 15;
        int rsrc = min(blockIdx.x * 64 + row, N_NODES - 1);
        sx4[SWZ(row, c4)] =
            reinterpret_cast<const float4*>(g_fused + (size_t)rsrc * D)[c4];
    }
    __syncthreads();
    int wid = threadIdx.x >> 5, lane = threadIdx.x & 31;
    int q = wid;
    int rl0 = lane, rl1 = lane + 32;
    int sw0 = lane & 15;
    int r0 = blockIdx.x * 64 + rl0, r1 = blockIdx.x * 64 + rl1;

    u64 a0[8], a1[8];
    const u64* bb = reinterpret_cast<const u64*>(sb + q * 16);
#pragma unroll
    for (int k = 0; k < 8; k++) { a0[k] = bb[k]; a1[k] = bb[k]; }

    const float* wq = sW + q * 16;
#pragma unroll
    for (int jv = 0; jv < 16; jv++) {
        float4 v0 = sx4[(rl0 << 4) + (jv ^ sw0)];
        float4 v1 = sx4[(rl1 << 4) + (jv ^ sw0)];
        const float* w0 = wq + (4 * jv) * 128;
        colupd(a0, a1, v0.x, v1.x, w0);
        colupd(a0, a1, v0.y, v1.y, w0 + 128);
        colupd(a0, a1, v0.z, v1.z, w0 + 2 * 128);
        colupd(a0, a1, v0.w, v1.w, w0 + 3 * 128);
    }
    int colbase = gy * 128 + q * 16;
    if (r0 < N_NODES) {
        const float4* xr = reinterpret_cast<const float4*>(x + (size_t)r0 * IN_CH + colbase);
        float4* o = reinterpret_cast<float4*>(out + (size_t)r0 * IN_CH + colbase);
#pragma unroll
        for (int k = 0; k < 4; k++) {
            float4 r = raw4(a0[2*k], a0[2*k+1]);
            float4 xv = xr[k];
            o[k] = make_float4(xv.x + r.x, xv.y + r.y, xv.z + r.z, xv.w + r.w);
        }
    }
    if (r1 < N_NODES) {
        const float4* xr = reinterpret_cast<const float4*>(x + (size_t)r1 * IN_CH + colbase);
        float4* o = reinterpret_cast<float4*>(out + (size_t)r1 * IN_CH + colbase);
#pragma unroll
        for (int k = 0; k < 4; k++) {
            float4 r = raw4(a1[2*k], a1[2*k+1]);
            float4 xv = xr[k];
            o[k] = make_float4(xv.x + r.x, xv.y + r.y, xv.z + r.z, xv.w + r.w);
        }
    }
}

// -------------------------------------------------------------------------------
extern "C" void kernel_launch(void* const* d_in, const int* in_sizes, int n_in,
                              void* d_out, int out_size) {
    const float* x   = (const float*)d_in[0];
    const float* ea  = (const float*)d_in[1];
    const int*   ei  = (const int*)  d_in[2];
    const float* Wd  = (const float*)d_in[3];
    const float* bd  = (const float*)d_in[4];
    const float* Wup = (const float*)d_in[5];
    const float* bup = (const float*)d_in[6];
    const float* Wt  = (const float*)d_in[7];
    const float* bt  = (const float*)d_in[8];
    const float* Wq  = (const float*)d_in[9];
    const float* bq  = (const float*)d_in[10];
    const float* Wk  = (const float*)d_in[11];
    const float* bk  = (const float*)d_in[12];
    const float* Wv  = (const float*)d_in[13];
    const float* bv  = (const float*)d_in[14];
    const float* ce  = (const float*)d_in[15];
    const float* Wo  = (const float*)d_in[16];
    const float* bo  = (const float*)d_in[17];
    float* out = (float*)d_out;

    int smA  = (IN_CH * D + D * D + 3 * D) * 4 + 128 * 64 * 4;   // ~114.7KB
    int smE1 = (16 * D + D + NC * D + NC) * 4 + 256 * 17 * 8;    // ~41.2KB
    int smE2 = (D * D + 2 * D) * 4 + 128 * 64 * 4;               // ~48.5KB
    int smE3 = (D * 128 + 128) * 4 + 64 * 64 * 4;                // ~48.5KB
    cudaFuncSetAttribute(k_nodeA, cudaFuncAttributeMaxDynamicSharedMemorySize, smA);
    cudaFuncSetAttribute(k_E2,    cudaFuncAttributeMaxDynamicSharedMemorySize, smE2);
    cudaFuncSetAttribute(k_E3,    cudaFuncAttributeMaxDynamicSharedMemorySize, smE3);

    int nblk128 = (N_NODES + 127) / 128;       // 391
    k_init  <<<(N_NODES + 255) / 256, 256>>>();
    k_count <<<(N_EDGES + 255) / 256, 256>>>(ei);
    k_scan1 <<<NBLK_SC, 256>>>();
    k_scan2 <<<1, 256>>>();
    k_scan3 <<<NBLK_SC, 256>>>();
    k_prep  <<<16, 256>>>(Wq, bq, Wk, bk, Wv, bv, Wo, bo);
    k_nodeA <<<nblk128, 256, smA>>>(x, Wd, bd);
    k_edge1 <<<N_EDGES / 256, 256, smE1>>>(ea, ei, Wt, bt, ce);
    k_gather<<<N_NODES / 8, 256>>>();
    k_E2    <<<nblk128, 256, smE2>>>(bo);
    k_E3    <<<dim3((N_NODES + 63) / 64, 2), 256, smE3>>>(x, Wup, bup, out);
}

// round 8
// speedup vs baseline: 1.8449x; 1.1658x over previous
#include <cuda_runtime.h>
#include <cuda_fp16.h>
#include <math.h>

#define N_NODES 50000
#define N_EDGES 800000
#define IN_CH   256
#define D       64
#define NC      8
#define NBLK_SC 196         // ceil(50000/256)
#define DEG_CAP 132         // smem attn cache per warp (max observed deg ~45)

typedef unsigned long long u64;
typedef unsigned int u32;

// ---------------- f32x2 packed helpers ----------------------------------------
__device__ __forceinline__ u64 pk2(float lo, float hi) {
    u64 r; asm("mov.b64 %0, {%1, %2};" : "=l"(r) : "f"(lo), "f"(hi)); return r;
}
__device__ __forceinline__ void up2(u64 v, float& lo, float& hi) {
    asm("mov.b64 {%0, %1}, %2;" : "=f"(lo), "=f"(hi) : "l"(v));
}
__device__ __forceinline__ void fma2(u64& d, u64 a, u64 b) {
    asm("fma.rn.f32x2 %0, %1, %2, %0;" : "+l"(d) : "l"(a), "l"(b));
}
__device__ __forceinline__ u64 add2(u64 a, u64 b) {
    u64 r; asm("add.rn.f32x2 %0, %1, %2;" : "=l"(r) : "l"(a), "l"(b)); return r;
}
__device__ __forceinline__ void rank1_64(u64* acc, float s, const float* wrow) {
    u64 s2 = pk2(s, s);
    const ulonglong2* w = reinterpret_cast<const ulonglong2*>(wrow);
#pragma unroll
    for (int t = 0; t < 16; t++) {
        ulonglong2 ww = w[t];
        fma2(acc[2*t],   s2, ww.x);
        fma2(acc[2*t+1], s2, ww.y);
    }
}
__device__ __forceinline__ float dot64(const u64* a, const float* wrow) {
    u64 s = 0ull;
    const ulonglong2* w = reinterpret_cast<const ulonglong2*>(wrow);
#pragma unroll
    for (int t = 0; t < 16; t++) {
        ulonglong2 ww = w[t];
        fma2(s, a[2*t],   ww.x);
        fma2(s, a[2*t+1], ww.y);
    }
    float lo, hi; up2(s, lo, hi); return lo + hi;
}
// 2 rows x 16 outputs per input column; wp is WARP-UNIFORM (broadcast LDS)
__device__ __forceinline__ void colupd(u64* a0, u64* a1, float s0, float s1,
                                       const float* wp) {
    u64 p0 = pk2(s0, s0), p1 = pk2(s1, s1);
    const ulonglong2* w = reinterpret_cast<const ulonglong2*>(wp);
    ulonglong2 wa = w[0], wb = w[1], wc = w[2], wd = w[3];
    fma2(a0[0], p0, wa.x); fma2(a1[0], p1, wa.x);
    fma2(a0[1], p0, wa.y); fma2(a1[1], p1, wa.y);
    fma2(a0[2], p0, wb.x); fma2(a1[2], p1, wb.x);
    fma2(a0[3], p0, wb.y); fma2(a1[3], p1, wb.y);
    fma2(a0[4], p0, wc.x); fma2(a1[4], p1, wc.x);
    fma2(a0[5], p0, wc.y); fma2(a1[5], p1, wc.y);
    fma2(a0[6], p0, wd.x); fma2(a1[6], p1, wd.x);
    fma2(a0[7], p0, wd.y); fma2(a1[7], p1, wd.y);
}
__device__ __forceinline__ float4 relu4(u64 a, u64 b) {
    float x, y, z, w; up2(a, x, y); up2(b, z, w);
    return make_float4(fmaxf(x, 0.f), fmaxf(y, 0.f), fmaxf(z, 0.f), fmaxf(w, 0.f));
}
__device__ __forceinline__ float4 raw4(u64 a, u64 b) {
    float x, y, z, w; up2(a, x, y); up2(b, z, w);
    return make_float4(x, y, z, w);
}
// XOR swizzle: logical (row, c4) -> physical float4 index (conflict-free LDS)
#define SWZ(row, c4) (((row) << 4) + ((c4) ^ ((row) & 15)))

// ---------------- scratch ------------------------------------------------------
__device__ float g_qk  [N_NODES * D];
__device__ float g_qb  [N_NODES];
__device__ u32   g_tfh [(size_t)N_EDGES * 32];  // fp16 tf, edge order (102.4MB)
__device__ int   g_eidc[N_EDGES];               // CSR-pos -> (edge id << 3) | cluster
__device__ int   g_deg [N_NODES];
__device__ int   g_off [N_NODES + 1];
__device__ int   g_cur [N_NODES];
__device__ int   g_flag[NBLK_SC];
__device__ int   g_aggr[NBLK_SC];
__device__ int   g_incl[NBLK_SC];
__device__ unsigned g_ticket;
__device__ float g_cec [NC];
__device__ float g_accN[N_NODES * D];
__device__ float g_bsc [N_NODES];
__device__ float g_fused[N_NODES * D];
__device__ float g_Wqk[D * D], g_bqk[D], g_wqb[D], g_sqb;
__device__ float g_Wvo[D * D], g_bvo[D];

// ---------------- K prep: fold weights ------------------------------------------
__global__ void k_prep(const float* __restrict__ Wq, const float* __restrict__ bq,
                       const float* __restrict__ Wk, const float* __restrict__ bk,
                       const float* __restrict__ Wv, const float* __restrict__ bv,
                       const float* __restrict__ Wo, const float* __restrict__ bo) {
    int idx = blockIdx.x * blockDim.x + threadIdx.x;
    if (idx < D * D) {
        int t = idx >> 6, j = idx & 63;
        float s1 = 0.f, s2 = 0.f;
        for (int d = 0; d < D; d++) {
            s1 = fmaf(Wq[t * D + d], Wk[j * D + d], s1);
            s2 = fmaf(Wv[t * D + d], Wo[d * D + j], s2);
        }
        g_Wqk[t * D + j] = s1;
        g_Wvo[t * D + j] = s2;
    }
    if (idx < D) {
        int j = idx;
        float a = 0.f, b = 0.f, c = 0.f;
        for (int d = 0; d < D; d++) {
            a = fmaf(bq[d], Wk[j * D + d], a);
            b = fmaf(bv[d], Wo[d * D + j], b);
            c = fmaf(Wq[j * D + d], bk[d], c);
        }
        g_bqk[j] = a; g_bvo[j] = b; g_wqb[j] = c;
        if (idx == 0) {
            float s = 0.f;
            for (int d = 0; d < D; d++) s = fmaf(bq[d], bk[d], s);
            g_sqb = s;
        }
    }
}

// ---------------- K init: zero deg/cec/scan-state --------------------------------
__global__ void k_init() {
    int i = blockIdx.x * blockDim.x + threadIdx.x;
    if (i < N_NODES) g_deg[i] = 0;
    if (i < NC) g_cec[i] = 0.f;
    if (i < NBLK_SC) g_flag[i] = 0;
    if (i == 0) g_ticket = 0u;
}
__global__ void k_count(const int* __restrict__ ei) {
    int e = blockIdx.x * blockDim.x + threadIdx.x;
    if (e < N_EDGES) atomicAdd(&g_deg[ei[e]], 1);
}

// ---------------- K scan: single-pass decoupled lookback -------------------------
__global__ void k_scan() {
    __shared__ int s[256];
    __shared__ int sbid, sexcl;
    int t = threadIdx.x;
    if (t == 0) sbid = (int)atomicAdd(&g_ticket, 1u);
    __syncthreads();
    int bid = sbid;
    int i = bid * 256 + t;
    int v = (i < N_NODES) ? g_deg[i] : 0;
    s[t] = v; __syncthreads();
#pragma unroll
    for (int o = 1; o < 256; o <<= 1) {
        int xv = (t >= o) ? s[t - o] : 0;
        __syncthreads();
        s[t] += xv;
        __syncthreads();
    }
    int total = s[255];
    if (t == 0) {
        if (bid == 0) {
            ((volatile int*)g_incl)[0] = total;
            __threadfence();
            atomicExch(&g_flag[0], 2);
            sexcl = 0;
        } else {
            ((volatile int*)g_aggr)[bid] = total;
            __threadfence();
            atomicExch(&g_flag[bid], 1);
            int excl = 0;
            for (int p = bid - 1; p >= 0; ) {
                int f;
                do { f = ((volatile int*)g_flag)[p]; } while (f == 0);
                __threadfence();
                if (f == 2) { excl += ((volatile int*)g_incl)[p]; break; }
                excl += ((volatile int*)g_aggr)[p];
                p--;
            }
            ((volatile int*)g_incl)[bid] = excl + total;
            __threadfence();
            atomicExch(&g_flag[bid], 2);
            sexcl = excl;
        }
    }
    __syncthreads();
    int o = sexcl + s[t] - v;   // exclusive prefix
    if (i < N_NODES) { g_off[i] = o; g_cur[i] = o; }
    if (i == 0) g_off[N_NODES] = N_EDGES;
}

// ---------------- K nodeA: FUSED qk = relu(x@Wd+bd)@Wqk + bqk, qb ---------------
__global__ __launch_bounds__(256) void k_nodeA(const float* __restrict__ x,
                                               const float* __restrict__ Wd,
                                               const float* __restrict__ bd) {
    extern __shared__ float smem[];
    float* sWd = smem;                     // 256*64
    float* sWq = sWd + IN_CH * D;          // 64*64
    float* sbd = sWq + D * D;              // 64
    float* sbq = sbd + D;                  // 64
    float* swq = sbq + D;                  // 64
    float4* sx4 = reinterpret_cast<float4*>(swq + D);  // 128 rows x 16 float4 (swizzled)
    for (int t = threadIdx.x; t < IN_CH * D / 4; t += 256)
        reinterpret_cast<float4*>(sWd)[t] = reinterpret_cast<const float4*>(Wd)[t];
    for (int t = threadIdx.x; t < D * D / 4; t += 256)
        reinterpret_cast<float4*>(sWq)[t] = reinterpret_cast<const float4*>(g_Wqk)[t];
    if (threadIdx.x < D) {
        sbd[threadIdx.x] = bd[threadIdx.x];
        sbq[threadIdx.x] = g_bqk[threadIdx.x];
        swq[threadIdx.x] = g_wqb[threadIdx.x];
    }

    int wid = threadIdx.x >> 5, lane = threadIdx.x & 31;
    int q = wid & 3, grp = wid >> 2;
    int rl0 = grp * 64 + lane, rl1 = rl0 + 32;
    int sw0 = rl0 & 15;
    int r0 = blockIdx.x * 128 + rl0, r1 = blockIdx.x * 128 + rl1;

    u64 a0[8], a1[8];
    const float* wq1 = sWd + q * 16;
#pragma unroll
    for (int kc = 0; kc < 4; kc++) {
        __syncthreads();
        for (int t = threadIdx.x; t < 128 * 16; t += 256) {
            int row = t >> 4, c4 = t & 15;
            int rsrc = min(blockIdx.x * 128 + row, N_NODES - 1);
            sx4[SWZ(row, c4)] =
                reinterpret_cast<const float4*>(x + (size_t)rsrc * IN_CH + kc * 64)[c4];
        }
        __syncthreads();
        if (kc == 0) {
            const u64* bb = reinterpret_cast<const u64*>(sbd + q * 16);
#pragma unroll
            for (int k = 0; k < 8; k++) { a0[k] = bb[k]; a1[k] = bb[k]; }
        }
#pragma unroll
        for (int jv = 0; jv < 16; jv++) {
            float4 v0 = sx4[(rl0 << 4) + (jv ^ sw0)];
            float4 v1 = sx4[(rl1 << 4) + (jv ^ sw0)];
            const float* w0 = wq1 + (kc * 64 + 4 * jv) * D;
            colupd(a0, a1, v0.x, v1.x, w0);
            colupd(a0, a1, v0.y, v1.y, w0 + D);
            colupd(a0, a1, v0.z, v1.z, w0 + 2 * D);
            colupd(a0, a1, v0.w, v1.w, w0 + 3 * D);
        }
    }
    __syncthreads();
#pragma unroll
    for (int k = 0; k < 4; k++) {
        sx4[SWZ(rl0, q * 4 + k)] = relu4(a0[2*k], a0[2*k+1]);
        sx4[SWZ(rl1, q * 4 + k)] = relu4(a1[2*k], a1[2*k+1]);
    }
    __syncthreads();
    {
        const u64* bb = reinterpret_cast<const u64*>(sbq + q * 16);
#pragma unroll
        for (int k = 0; k < 8; k++) { a0[k] = bb[k]; a1[k] = bb[k]; }
    }
    float qb0 = g_sqb, qb1 = g_sqb;
    const float* wq2 = sWq + q * 16;
#pragma unroll
    for (int jv = 0; jv < 16; jv++) {
        float4 v0 = sx4[(rl0 << 4) + (jv ^ sw0)];
        float4 v1 = sx4[(rl1 << 4) + (jv ^ sw0)];
        const float* w0 = wq2 + (4 * jv) * D;
        colupd(a0, a1, v0.x, v1.x, w0);
        colupd(a0, a1, v0.y, v1.y, w0 + D);
        colupd(a0, a1, v0.z, v1.z, w0 + 2 * D);
        colupd(a0, a1, v0.w, v1.w, w0 + 3 * D);
        if (q == 0) {
            qb0 = fmaf(v0.x, swq[4*jv], fmaf(v0.y, swq[4*jv+1], fmaf(v0.z, swq[4*jv+2], fmaf(v0.w, swq[4*jv+3], qb0))));
            qb1 = fmaf(v1.x, swq[4*jv], fmaf(v1.y, swq[4*jv+1], fmaf(v1.z, swq[4*jv+2], fmaf(v1.w, swq[4*jv+3], qb1))));
        }
    }
    if (r0 < N_NODES) {
        float4* o0 = reinterpret_cast<float4*>(g_qk + (size_t)r0 * D + q * 16);
#pragma unroll
        for (int k = 0; k < 4; k++) o0[k] = raw4(a0[2*k], a0[2*k+1]);
    }
    if (r1 < N_NODES) {
        float4* o1 = reinterpret_cast<float4*>(g_qk + (size_t)r1 * D + q * 16);
#pragma unroll
        for (int k = 0; k < 4; k++) o1[k] = raw4(a1[2*k], a1[2*k+1]);
    }
    if (q == 0) {
        if (r0 < N_NODES) g_qb[r0] = qb0;
        if (r1 < N_NODES) g_qb[r1] = qb1;
    }
}

// per-edge time_feat (weights warp-uniform)
__device__ __forceinline__ void edge_tf(u64* acc, const float* __restrict__ ea, int e,
                                        const float* sW, const float* sb) {
    const u64* sb2 = reinterpret_cast<const u64*>(sb);
#pragma unroll
    for (int t = 0; t < 32; t++) acc[t] = sb2[t];
    const float4* ar = reinterpret_cast<const float4*>(ea + (size_t)e * 16);
#pragma unroll
    for (int jv = 0; jv < 4; jv++) {
        float4 a = ar[jv];
        const float* w0 = sW + (jv * 4) * D;
        rank1_64(acc, a.x, w0);
        rank1_64(acc, a.y, w0 + D);
        rank1_64(acc, a.z, w0 + 2 * D);
        rank1_64(acc, a.w, w0 + 3 * D);
    }
#pragma unroll
    for (int t = 0; t < 32; t++) {
        float lo, hi; up2(acc[t], lo, hi);
        acc[t] = pk2(fmaxf(lo, 0.f), fmaxf(hi, 0.f));
    }
}

// ---------------- K edge1: tf(fp16, coalesced) + cluster argmax → CSR ------------
__global__ __launch_bounds__(256) void k_edge1(const float* __restrict__ ea,
                                               const int* __restrict__ ei,
                                               const float* __restrict__ Wt,
                                               const float* __restrict__ bt,
                                               const float* __restrict__ ce) {
    extern __shared__ float smem[];
    float* sW = smem;            // 16*64
    float* sb = sW + 16 * D;     // 64
    float* sc = sb + D;          // 8*64
    float* scec = sc + NC * D;   // 8
    u64* su = reinterpret_cast<u64*>(scec + NC);  // 256*17 u64 stage
    for (int t = threadIdx.x; t < 16 * D / 4; t += 256)
        reinterpret_cast<float4*>(sW)[t] = reinterpret_cast<const float4*>(Wt)[t];
    if (threadIdx.x < D) sb[threadIdx.x] = bt[threadIdx.x];
    for (int t = threadIdx.x; t < NC * D / 4; t += 256)
        reinterpret_cast<float4*>(sc)[t] = reinterpret_cast<const float4*>(ce)[t];
    if (threadIdx.x < NC) scec[threadIdx.x] = 0.f;
    __syncthreads();
    int e = blockIdx.x * 256 + threadIdx.x;   // N_EDGES % 256 == 0

    u64 tf[32];
    edge_tf(tf, ea, e, sW, sb);

    int bc = 0; float bv = dot64(tf, sc);
#pragma unroll
    for (int c = 1; c < NC; c++) {
        float s = dot64(tf, sc + c * D);
        if (s > bv) { bv = s; bc = c; }
    }

    int src = ei[e];
    atomicAdd(&scec[bc], 1.f);
    int pos = atomicAdd(&g_cur[src], 1);
    g_eidc[pos] = (e << 3) | bc;

    // convert tf -> fp16 pairs, stage in smem, store coalesced (edge order)
#pragma unroll
    for (int c = 0; c < 16; c++) {
        float a, b; up2(tf[2*c], a, b);
        float cc, d; up2(tf[2*c+1], cc, d);
        __half2 h0 = __floats2half2_rn(a, b);
        __half2 h1 = __floats2half2_rn(cc, d);
        u32 l0 = *reinterpret_cast<u32*>(&h0);
        u32 l1 = *reinterpret_cast<u32*>(&h1);
        su[threadIdx.x * 17 + c] = (u64)l0 | ((u64)l1 << 32);
    }
    __syncthreads();
    u64* gout = reinterpret_cast<u64*>(g_tfh) + (size_t)blockIdx.x * 4096;
#pragma unroll
    for (int k = 0; k < 16; k++) {
        int idx = threadIdx.x + k * 256;
        int el = idx >> 4, c = idx & 15;
        gout[idx] = su[el * 17 + c];
    }
    if (threadIdx.x < NC) atomicAdd(&g_cec[threadIdx.x], scec[threadIdx.x]);
}

// ---------------- K gather: warp-per-node, attn in-kernel, shfl lookups ---------
__global__ __launch_bounds__(256) void k_gather() {
    __shared__ float s_attn[8][DEG_CAP];
    __shared__ int   s_ec  [8][DEG_CAP];
    int wid = threadIdx.x >> 5, lane = threadIdx.x & 31;
    int n = blockIdx.x * 8 + wid;           // grid = 6250 exact
    int off = g_off[n];
    int deg = g_off[n + 1] - off;
    int eg = lane >> 3, dg = lane & 7;      // edge-group, dim-group

    float nne = 0.f;
#pragma unroll
    for (int c = 0; c < NC; c++) nne += (g_cec[c] > 0.f) ? 1.f : 0.f;
    float inv = 1.0f / nne;

    // qk dims [8dg, 8dg+8) as 4 f32 pairs; qb
    u64 qkd[4];
    {
        const float2* qrow = reinterpret_cast<const float2*>(g_qk + (size_t)n * D) + dg * 4;
#pragma unroll
        for (int k = 0; k < 4; k++) { float2 f = qrow[k]; qkd[k] = pk2(f.x, f.y); }
    }
    float qbn = g_qb[n];

    // Phase A: attn per edge (4 edges x 8 lanes), cache in smem
    for (int j0 = 0; j0 < deg; j0 += 4) {
        int j = j0 + eg;
        bool valid = (j < deg);
        int jj = valid ? j : (deg - 1);
        int ec = g_eidc[off + jj];
        int eid = ec >> 3;
        uint4 tv = *reinterpret_cast<const uint4*>(g_tfh + (size_t)eid * 32 + dg * 4);
        u64 dacc = 0ull;
#pragma unroll
        for (int k = 0; k < 4; k++) {
            u32 h = (&tv.x)[k];
            __half2 hh = *reinterpret_cast<const __half2*>(&h);
            float2 f = __half22float2(hh);
            fma2(dacc, pk2(f.x, f.y), qkd[k]);
        }
        float lo, hi; up2(dacc, lo, hi);
        float part = lo + hi;
        part += __shfl_xor_sync(0xFFFFFFFFu, part, 1);
        part += __shfl_xor_sync(0xFFFFFFFFu, part, 2);
        part += __shfl_xor_sync(0xFFFFFFFFu, part, 4);
        if (valid && dg == 0) {
            s_attn[wid][j] = (part + qbn) * 0.125f;
            s_ec[wid][j] = ec;
        }
    }
    __syncwarp();

    // Phase B1: per-cluster max
    float pm[NC];
#pragma unroll
    for (int c = 0; c < NC; c++) pm[c] = -3.4e38f;
    for (int j = lane; j < deg; j += 32) {
        float a = s_attn[wid][j];
        int cc = s_ec[wid][j] & 7;
#pragma unroll
        for (int c = 0; c < NC; c++) if (cc == c) pm[c] = fmaxf(pm[c], a);
    }
#pragma unroll
    for (int c = 0; c < NC; c++)
#pragma unroll
        for (int o = 16; o > 0; o >>= 1)
            pm[c] = fmaxf(pm[c], __shfl_xor_sync(0xFFFFFFFFu, pm[c], o));
    float mxL = 0.f;
#pragma unroll
    for (int c = 0; c < NC; c++) if (lane == c) mxL = pm[c];

    // Phase B2: per-cluster denom + count (uniform trips for shfl)
    float pd[NC], pc[NC];
#pragma unroll
    for (int c = 0; c < NC; c++) { pd[c] = 0.f; pc[c] = 0.f; }
    int rounds = (deg + 31) >> 5;
    for (int r = 0; r < rounds; r++) {
        int j = r * 32 + lane;
        bool v = j < deg;
        int jj = v ? j : 0;
        float a = s_attn[wid][jj];
        int cc = s_ec[wid][jj] & 7;
        float cmv = __shfl_sync(0xFFFFFFFFu, mxL, cc);
        float ex = v ? __expf(a - cmv) : 0.f;
        float on = v ? 1.f : 0.f;
#pragma unroll
        for (int c = 0; c < NC; c++) {
            pd[c] += (cc == c) ? ex : 0.f;
            pc[c] += (cc == c) ? on : 0.f;
        }
    }
#pragma unroll
    for (int c = 0; c < NC; c++)
#pragma unroll
        for (int o = 16; o > 0; o >>= 1) {
            pd[c] += __shfl_xor_sync(0xFFFFFFFFu, pd[c], o);
            pc[c] += __shfl_xor_sync(0xFFFFFFFFu, pc[c], o);
        }

    float bsc = 0.f, svL = 0.f;
#pragma unroll
    for (int c = 0; c < NC; c++) {
        if (pc[c] > 0.f) bsc += 1.0f / pc[c];
        if (lane == c) svL = (pc[c] > 0.f) ? inv / (pd[c] * pc[c]) : 0.f;
    }
    if (lane == 0) g_bsc[n] = bsc * inv;

    // Phase C: weighted tf sum (4 edges x 8 lanes; tf lines L1-hot from phase A)
    u64 acc[4] = {0ull, 0ull, 0ull, 0ull};
    for (int j0 = 0; j0 < deg; j0 += 4) {
        int j = j0 + eg;
        bool v = j < deg;
        int jj = v ? j : (deg - 1);
        float a = s_attn[wid][jj];
        int ec = s_ec[wid][jj];
        int cc = ec & 7;
        float cmv = __shfl_sync(0xFFFFFFFFu, mxL, cc);
        float sv  = __shfl_sync(0xFFFFFFFFu, svL, cc);
        float coef = v ? __expf(a - cmv) * sv : 0.f;
        int eid = ec >> 3;
        uint4 tv = *reinterpret_cast<const uint4*>(g_tfh + (size_t)eid * 32 + dg * 4);
        u64 cf2 = pk2(coef, coef);
#pragma unroll
        for (int k = 0; k < 4; k++) {
            u32 h = (&tv.x)[k];
            __half2 hh = *reinterpret_cast<const __half2*>(&h);
            float2 f = __half22float2(hh);
            fma2(acc[k], cf2, pk2(f.x, f.y));
        }
    }
#pragma unroll
    for (int k = 0; k < 4; k++) {
        acc[k] = add2(acc[k], __shfl_xor_sync(0xFFFFFFFFu, acc[k], 8));
        acc[k] = add2(acc[k], __shfl_xor_sync(0xFFFFFFFFu, acc[k], 16));
    }
    if (eg == 0) {
        float2* o = reinterpret_cast<float2*>(g_accN + (size_t)n * D + dg * 8);
#pragma unroll
        for (int k = 0; k < 4; k++) {
            float lo, hi; up2(acc[k], lo, hi);
            o[k] = make_float2(lo, hi);
        }
    }
}

// ---------------- K E2: fused = relu(accN @ Wvo + bvo*bsc + b_out) --------------
__global__ __launch_bounds__(256) void k_E2(const float* __restrict__ bo) {
    extern __shared__ float smem[];
    float* sW  = smem;            // 64*64
    float* sbv = sW + D * D;
    float* sbo = sbv + D;
    float4* sx4 = reinterpret_cast<float4*>(sbo + D);   // 128 x 16 float4 swizzled
    for (int t = threadIdx.x; t < D * D / 4; t += 256)
        reinterpret_cast<float4*>(sW)[t] = reinterpret_cast<const float4*>(g_Wvo)[t];
    if (threadIdx.x < D) { sbv[threadIdx.x] = g_bvo[threadIdx.x]; sbo[threadIdx.x] = bo[threadIdx.x]; }
    for (int t = threadIdx.x; t < 128 * 16; t += 256) {
        int row = t >> 4, c4 = t & 15;
        int rsrc = min(blockIdx.x * 128 + row, N_NODES - 1);
        sx4[SWZ(row, c4)] =
            reinterpret_cast<const float4*>(g_accN + (size_t)rsrc * D)[c4];
    }
    __syncthreads();
    int wid = threadIdx.x >> 5, lane = threadIdx.x & 31;
    int q = wid & 3, grp = wid >> 2;
    int rl0 = grp * 64 + lane, rl1 = rl0 + 32;
    int sw0 = rl0 & 15;
    int r0 = blockIdx.x * 128 + rl0, r1 = blockIdx.x * 128 + rl1;
    int r0c = min(r0, N_NODES - 1), r1c = min(r1, N_NODES - 1);
    float bs0 = g_bsc[r0c], bs1 = g_bsc[r1c];

    u64 a0[8], a1[8];
    const float* bvq = sbv + q * 16;
    const float* boq = sbo + q * 16;
#pragma unroll
    for (int k = 0; k < 8; k++) {
        a0[k] = pk2(fmaf(bvq[2*k], bs0, boq[2*k]), fmaf(bvq[2*k+1], bs0, boq[2*k+1]));
        a1[k] = pk2(fmaf(bvq[2*k], bs1, boq[2*k]), fmaf(bvq[2*k+1], bs1, boq[2*k+1]));
    }
    const float* wq = sW + q * 16;
#pragma unroll
    for (int jv = 0; jv < 16; jv++) {
        float4 v0 = sx4[(rl0 << 4) + (jv ^ sw0)];
        float4 v1 = sx4[(rl1 << 4) + (jv ^ sw0)];
        const float* w0 = wq + (4 * jv) * D;
        colupd(a0, a1, v0.x, v1.x, w0);
        colupd(a0, a1, v0.y, v1.y, w0 + D);
        colupd(a0, a1, v0.z, v1.z, w0 + 2 * D);
        colupd(a0, a1, v0.w, v1.w, w0 + 3 * D);
    }
    if (r0 < N_NODES) {
        float4* o0 = reinterpret_cast<float4*>(g_fused + (size_t)r0 * D + q * 16);
#pragma unroll
        for (int k = 0; k < 4; k++) o0[k] = relu4(a0[2*k], a0[2*k+1]);
    }
    if (r1 < N_NODES) {
        float4* o1 = reinterpret_cast<float4*>(g_fused + (size_t)r1 * D + q * 16);
#pragma unroll
        for (int k = 0; k < 4; k++) o1[k] = relu4(a1[2*k], a1[2*k+1]);
    }
}

// ---------------- K E3: out = x + fused @ W_up + b_up ---------------------------
__global__ __launch_bounds__(256) void k_E3(const float* __restrict__ x,
                                            const float* __restrict__ Wup,
                                            const float* __restrict__ bup,
                                            float* __restrict__ out) {
    extern __shared__ float smem[];
    float* sW = smem;                 // 64 x 128 slice
    float* sb = sW + D * 128;         // 128
    float4* sx4 = reinterpret_cast<float4*>(sb + 128);  // 64 x 16 float4 swizzled
    int gy = blockIdx.y;
    for (int t = threadIdx.x; t < D * 128 / 4; t += 256) {
        int row = t >> 5, c4 = t & 31;
        reinterpret_cast<float4*>(sW + row * 128)[c4] =
            reinterpret_cast<const float4*>(Wup + row * IN_CH + gy * 128)[c4];
    }
    if (threadIdx.x < 128) sb[threadIdx.x] = bup[gy * 128 + threadIdx.x];
    for (int t = threadIdx.x; t < 64 * 16; t += 256) {
        int row = t >> 4, c4 = t & 15;
        int rsrc = min(blockIdx.x * 64 + row, N_NODES - 1);
        sx4[SWZ(row, c4)] =
            reinterpret_cast<const float4*>(g_fused + (size_t)rsrc * D)[c4];
    }
    __syncthreads();
    int wid = threadIdx.x >> 5, lane = threadIdx.x & 31;
    int q = wid;
    int rl0 = lane, rl1 = lane + 32;
    int sw0 = lane & 15;
    int r0 = blockIdx.x * 64 + rl0, r1 = blockIdx.x * 64 + rl1;

    u64 a0[8], a1[8];
    const u64* bb = reinterpret_cast<const u64*>(sb + q * 16);
#pragma unroll
    for (int k = 0; k < 8; k++) { a0[k] = bb[k]; a1[k] = bb[k]; }

    const float* wq = sW + q * 16;
#pragma unroll
    for (int jv = 0; jv < 16; jv++) {
        float4 v0 = sx4[(rl0 << 4) + (jv ^ sw0)];
        float4 v1 = sx4[(rl1 << 4) + (jv ^ sw0)];
        const float* w0 = wq + (4 * jv) * 128;
        colupd(a0, a1, v0.x, v1.x, w0);
        colupd(a0, a1, v0.y, v1.y, w0 + 128);
        colupd(a0, a1, v0.z, v1.z, w0 + 2 * 128);
        colupd(a0, a1, v0.w, v1.w, w0 + 3 * 128);
    }
    int colbase = gy * 128 + q * 16;
    if (r0 < N_NODES) {
        const float4* xr = reinterpret_cast<const float4*>(x + (size_t)r0 * IN_CH + colbase);
        float4* o = reinterpret_cast<float4*>(out + (size_t)r0 * IN_CH + colbase);
#pragma unroll
        for (int k = 0; k < 4; k++) {
            float4 r = raw4(a0[2*k], a0[2*k+1]);
            float4 xv = xr[k];
            o[k] = make_float4(xv.x + r.x, xv.y + r.y, xv.z + r.z, xv.w + r.w);
        }
    }
    if (r1 < N_NODES) {
        const float4* xr = reinterpret_cast<const float4*>(x + (size_t)r1 * IN_CH + colbase);
        float4* o = reinterpret_cast<float4*>(out + (size_t)r1 * IN_CH + colbase);
#pragma unroll
        for (int k = 0; k < 4; k++) {
            float4 r = raw4(a1[2*k], a1[2*k+1]);
            float4 xv = xr[k];
            o[k] = make_float4(xv.x + r.x, xv.y + r.y, xv.z + r.z, xv.w + r.w);
        }
    }
}

// -------------------------------------------------------------------------------
extern "C" void kernel_launch(void* const* d_in, const int* in_sizes, int n_in,
                              void* d_out, int out_size) {
    const float* x   = (const float*)d_in[0];
    const float* ea  = (const float*)d_in[1];
    const int*   ei  = (const int*)  d_in[2];
    const float* Wd  = (const float*)d_in[3];
    const float* bd  = (const float*)d_in[4];
    const float* Wup = (const float*)d_in[5];
    const float* bup = (const float*)d_in[6];
    const float* Wt  = (const float*)d_in[7];
    const float* bt  = (const float*)d_in[8];
    const float* Wq  = (const float*)d_in[9];
    const float* bq  = (const float*)d_in[10];
    const float* Wk  = (const float*)d_in[11];
    const float* bk  = (const float*)d_in[12];
    const float* Wv  = (const float*)d_in[13];
    const float* bv  = (const float*)d_in[14];
    const float* ce  = (const float*)d_in[15];
    const float* Wo  = (const float*)d_in[16];
    const float* bo  = (const float*)d_in[17];
    float* out = (float*)d_out;

    int smA  = (IN_CH * D + D * D + 3 * D) * 4 + 128 * 64 * 4;   // ~114.7KB
    int smE1 = (16 * D + D + NC * D + NC) * 4 + 256 * 17 * 8;    // ~41.2KB
    int smE2 = (D * D + 2 * D) * 4 + 128 * 64 * 4;               // ~48.5KB
    int smE3 = (D * 128 + 128) * 4 + 64 * 64 * 4;                // ~48.5KB
    cudaFuncSetAttribute(k_nodeA, cudaFuncAttributeMaxDynamicSharedMemorySize, smA);
    cudaFuncSetAttribute(k_E2,    cudaFuncAttributeMaxDynamicSharedMemorySize, smE2);
    cudaFuncSetAttribute(k_E3,    cudaFuncAttributeMaxDynamicSharedMemorySize, smE3);

    int nblk128 = (N_NODES + 127) / 128;       // 391
    // launch order chosen so ncu (-s 5 -c 1) captures k_edge1
    k_prep  <<<16, 256>>>(Wq, bq, Wk, bk, Wv, bv, Wo, bo);         // idx 0
    k_init  <<<NBLK_SC, 256>>>();                                   // idx 1
    k_count <<<(N_EDGES + 255) / 256, 256>>>(ei);                   // idx 2
    k_scan  <<<NBLK_SC, 256>>>();                                   // idx 3
    k_nodeA <<<nblk128, 256, smA>>>(x, Wd, bd);                     // idx 4
    k_edge1 <<<N_EDGES / 256, 256, smE1>>>(ea, ei, Wt, bt, ce);     // idx 5 (profiled)
    k_gather<<<N_NODES / 8, 256>>>();                               // idx 6
    k_E2    <<<nblk128, 256, smE2>>>(bo);                           // idx 7
    k_E3    <<<dim3((N_NODES + 63) / 64, 2), 256, smE3>>>(x, Wup, bup, out);  // idx 8
}

// round 11
// speedup vs baseline: 1.9022x; 1.0311x over previous
#include <cuda_runtime.h>
#include <cuda_fp16.h>
#include <math.h>

#define N_NODES 50000
#define N_EDGES 800000
#define IN_CH   256
#define D       64
#define NC      8
#define NBLK_SC 196         // ceil(50000/256)
#define DEG_CAP 132         // smem attn cache per warp

typedef unsigned long long u64;
typedef unsigned int u32;

// ---------------- f32x2 packed helpers ----------------------------------------
__device__ __forceinline__ u64 pk2(float lo, float hi) {
    u64 r; asm("mov.b64 %0, {%1, %2};" : "=l"(r) : "f"(lo), "f"(hi)); return r;
}
__device__ __forceinline__ void up2(u64 v, float& lo, float& hi) {
    asm("mov.b64 {%0, %1}, %2;" : "=f"(lo), "=f"(hi) : "l"(v));
}
__device__ __forceinline__ void fma2(u64& d, u64 a, u64 b) {
    asm("fma.rn.f32x2 %0, %1, %2, %0;" : "+l"(d) : "l"(a), "l"(b));
}
__device__ __forceinline__ u64 add2(u64 a, u64 b) {
    u64 r; asm("add.rn.f32x2 %0, %1, %2;" : "=l"(r) : "l"(a), "l"(b)); return r;
}
__device__ __forceinline__ void rank1_64(u64* acc, float s, const float* wrow) {
    u64 s2 = pk2(s, s);
    const ulonglong2* w = reinterpret_cast<const ulonglong2*>(wrow);
#pragma unroll
    for (int t = 0; t < 16; t++) {
        ulonglong2 ww = w[t];
        fma2(acc[2*t],   s2, ww.x);
        fma2(acc[2*t+1], s2, ww.y);
    }
}
__device__ __forceinline__ float dot64(const u64* a, const float* wrow) {
    u64 s = 0ull;
    const ulonglong2* w = reinterpret_cast<const ulonglong2*>(wrow);
#pragma unroll
    for (int t = 0; t < 16; t++) {
        ulonglong2 ww = w[t];
        fma2(s, a[2*t],   ww.x);
        fma2(s, a[2*t+1], ww.y);
    }
    float lo, hi; up2(s, lo, hi); return lo + hi;
}
__device__ __forceinline__ void colupd(u64* a0, u64* a1, float s0, float s1,
                                       const float* wp) {
    u64 p0 = pk2(s0, s0), p1 = pk2(s1, s1);
    const ulonglong2* w = reinterpret_cast<const ulonglong2*>(wp);
    ulonglong2 wa = w[0], wb = w[1], wc = w[2], wd = w[3];
    fma2(a0[0], p0, wa.x); fma2(a1[0], p1, wa.x);
    fma2(a0[1], p0, wa.y); fma2(a1[1], p1, wa.y);
    fma2(a0[2], p0, wb.x); fma2(a1[2], p1, wb.x);
    fma2(a0[3], p0, wb.y); fma2(a1[3], p1, wb.y);
    fma2(a0[4], p0, wc.x); fma2(a1[4], p1, wc.x);
    fma2(a0[5], p0, wc.y); fma2(a1[5], p1, wc.y);
    fma2(a0[6], p0, wd.x); fma2(a1[6], p1, wd.x);
    fma2(a0[7], p0, wd.y); fma2(a1[7], p1, wd.y);
}
__device__ __forceinline__ float4 relu4(u64 a, u64 b) {
    float x, y, z, w; up2(a, x, y); up2(b, z, w);
    return make_float4(fmaxf(x, 0.f), fmaxf(y, 0.f), fmaxf(z, 0.f), fmaxf(w, 0.f));
}
__device__ __forceinline__ float4 raw4(u64 a, u64 b) {
    float x, y, z, w; up2(a, x, y); up2(b, z, w);
    return make_float4(x, y, z, w);
}
#define SWZ(row, c4) (((row) << 4) + ((c4) ^ ((row) & 15)))

// ---------------- scratch ------------------------------------------------------
__device__ float g_qk  [N_NODES * D];
__device__ float g_qb  [N_NODES];
__device__ u32   g_tfh [(size_t)N_EDGES * 32];  // fp16 tf, edge order (102.4MB)
__device__ int   g_eidc[N_EDGES];               // CSR-pos -> (edge id << 3) | cluster
__device__ int   g_deg [N_NODES];
__device__ int   g_off [N_NODES + 1];
__device__ int   g_cur [N_NODES];
__device__ int   g_flag[NBLK_SC];
__device__ int   g_aggr[NBLK_SC];
__device__ int   g_incl[NBLK_SC];
__device__ unsigned g_ticket;
__device__ float g_cec [NC];
__device__ float g_accN[N_NODES * D];
__device__ float g_bsc [N_NODES];
__device__ float g_fused[N_NODES * D];
__device__ float g_Wqk[D * D], g_bqk[D], g_wqb[D], g_sqb;
__device__ float g_Wvo[D * D], g_bvo[D];

// ---------------- K0: prep (fold weights) + init (zero state), merged -----------
__global__ void k_prep_init(const float* __restrict__ Wq, const float* __restrict__ bq,
                            const float* __restrict__ Wk, const float* __restrict__ bk,
                            const float* __restrict__ Wv, const float* __restrict__ bv,
                            const float* __restrict__ Wo, const float* __restrict__ bo) {
    int idx = blockIdx.x * blockDim.x + threadIdx.x;
    // init portion
    if (idx < N_NODES) g_deg[idx] = 0;
    if (idx < NC) g_cec[idx] = 0.f;
    if (idx < NBLK_SC) g_flag[idx] = 0;
    if (idx == 0) g_ticket = 0u;
    // prep portion
    if (idx < D * D) {
        int t = idx >> 6, j = idx & 63;
        float s1 = 0.f, s2 = 0.f;
        for (int d = 0; d < D; d++) {
            s1 = fmaf(Wq[t * D + d], Wk[j * D + d], s1);
            s2 = fmaf(Wv[t * D + d], Wo[d * D + j], s2);
        }
        g_Wqk[t * D + j] = s1;
        g_Wvo[t * D + j] = s2;
    }
    if (idx < D) {
        int j = idx;
        float a = 0.f, b = 0.f, c = 0.f;
        for (int d = 0; d < D; d++) {
            a = fmaf(bq[d], Wk[j * D + d], a);
            b = fmaf(bv[d], Wo[d * D + j], b);
            c = fmaf(Wq[j * D + d], bk[d], c);
        }
        g_bqk[j] = a; g_bvo[j] = b; g_wqb[j] = c;
        if (idx == 0) {
            float s = 0.f;
            for (int d = 0; d < D; d++) s = fmaf(bq[d], bk[d], s);
            g_sqb = s;
        }
    }
}

__global__ void k_count(const int* __restrict__ ei) {
    int e = blockIdx.x * blockDim.x + threadIdx.x;
    if (e < N_EDGES) atomicAdd(&g_deg[ei[e]], 1);
}

// ---------------- K scan: single-pass, WARP-PARALLEL lookback --------------------
__global__ void k_scan() {
    __shared__ int s[256];
    __shared__ int sbid, sexcl;
    int t = threadIdx.x;
    if (t == 0) { sbid = (int)atomicAdd(&g_ticket, 1u); sexcl = 0; }
    __syncthreads();
    int bid = sbid;
    int i = bid * 256 + t;
    int v = (i < N_NODES) ? g_deg[i] : 0;
    s[t] = v; __syncthreads();
#pragma unroll
    for (int o = 1; o < 256; o <<= 1) {
        int xv = (t >= o) ? s[t - o] : 0;
        __syncthreads();
        s[t] += xv;
        __syncthreads();
    }
    int total = s[255];
    if (t < 32) {
        if (bid == 0) {
            if (t == 0) {
                ((volatile int*)g_incl)[0] = total;
                __threadfence();
                atomicExch(&g_flag[0], 2);
            }
        } else {
            if (t == 0) {
                ((volatile int*)g_aggr)[bid] = total;
                __threadfence();
                atomicExch(&g_flag[bid], 1);
            }
            __syncwarp();
            int excl = 0;
            int p = bid - 1;
            while (true) {
                int idx = p - t;         // lane 0 = nearest predecessor
                int f = 0, val = 0;
                if (idx >= 0) {
                    do { f = ((volatile int*)g_flag)[idx]; } while (f == 0);
                    __threadfence();
                    val = (f == 2) ? ((volatile int*)g_incl)[idx]
                                   : ((volatile int*)g_aggr)[idx];
                }
                unsigned m = __ballot_sync(0xFFFFFFFFu, f == 2);
                int firstP = m ? (__ffs(m) - 1) : 32;
                int contrib = (idx >= 0 && t <= firstP) ? val : 0;
#pragma unroll
                for (int o = 16; o > 0; o >>= 1)
                    contrib += __shfl_xor_sync(0xFFFFFFFFu, contrib, o);
                excl += contrib;
                if (m) break;
                p -= 32;
            }
            if (t == 0) {
                ((volatile int*)g_incl)[bid] = excl + total;
                __threadfence();
                atomicExch(&g_flag[bid], 2);
                sexcl = excl;
            }
        }
    }
    __syncthreads();
    int o = sexcl + s[t] - v;   // exclusive prefix
    if (i < N_NODES) { g_off[i] = o; g_cur[i] = o; }
    if (i == 0) g_off[N_NODES] = N_EDGES;
}

// per-edge time_feat (weights warp-uniform)
__device__ __forceinline__ void edge_tf(u64* acc, const float* __restrict__ ea, int e,
                                        const float* sW, const float* sb) {
    const u64* sb2 = reinterpret_cast<const u64*>(sb);
#pragma unroll
    for (int t = 0; t < 32; t++) acc[t] = sb2[t];
    const float4* ar = reinterpret_cast<const float4*>(ea + (size_t)e * 16);
#pragma unroll
    for (int jv = 0; jv < 4; jv++) {
        float4 a = ar[jv];
        const float* w0 = sW + (jv * 4) * D;
        rank1_64(acc, a.x, w0);
        rank1_64(acc, a.y, w0 + D);
        rank1_64(acc, a.z, w0 + 2 * D);
        rank1_64(acc, a.w, w0 + 3 * D);
    }
#pragma unroll
    for (int t = 0; t < 32; t++) {
        float lo, hi; up2(acc[t], lo, hi);
        acc[t] = pk2(fmaxf(lo, 0.f), fmaxf(hi, 0.f));
    }
}

// ---------------- K edge1 (PROFILED @ idx 3): tf + cluster argmax → CSR ---------
__global__ __launch_bounds__(256) void k_edge1(const float* __restrict__ ea,
                                               const int* __restrict__ ei,
                                               const float* __restrict__ Wt,
                                               const float* __restrict__ bt,
                                               const float* __restrict__ ce) {
    extern __shared__ float smem[];
    float* sW = smem;            // 16*64
    float* sb = sW + 16 * D;     // 64
    float* sc = sb + D;          // 8*64
    float* scec = sc + NC * D;   // 8
    u64* su = reinterpret_cast<u64*>(scec + NC);  // 256*17 u64 stage
    for (int t = threadIdx.x; t < 16 * D / 4; t += 256)
        reinterpret_cast<float4*>(sW)[t] = reinterpret_cast<const float4*>(Wt)[t];
    if (threadIdx.x < D) sb[threadIdx.x] = bt[threadIdx.x];
    for (int t = threadIdx.x; t < NC * D / 4; t += 256)
        reinterpret_cast<float4*>(sc)[t] = reinterpret_cast<const float4*>(ce)[t];
    if (threadIdx.x < NC) scec[threadIdx.x] = 0.f;
    __syncthreads();
    int e = blockIdx.x * 256 + threadIdx.x;   // N_EDGES % 256 == 0

    u64 tf[32];
    edge_tf(tf, ea, e, sW, sb);

    int bc = 0; float bv = dot64(tf, sc);
#pragma unroll
    for (int c = 1; c < NC; c++) {
        float s = dot64(tf, sc + c * D);
        if (s > bv) { bv = s; bc = c; }
    }

    int src = ei[e];
    atomicAdd(&scec[bc], 1.f);
    int pos = atomicAdd(&g_cur[src], 1);
    g_eidc[pos] = (e << 3) | bc;

#pragma unroll
    for (int c = 0; c < 16; c++) {
        float a, b; up2(tf[2*c], a, b);
        float cc, d; up2(tf[2*c+1], cc, d);
        __half2 h0 = __floats2half2_rn(a, b);
        __half2 h1 = __floats2half2_rn(cc, d);
        u32 l0 = *reinterpret_cast<u32*>(&h0);
        u32 l1 = *reinterpret_cast<u32*>(&h1);
        su[threadIdx.x * 17 + c] = (u64)l0 | ((u64)l1 << 32);
    }
    __syncthreads();
    u64* gout = reinterpret_cast<u64*>(g_tfh) + (size_t)blockIdx.x * 4096;
#pragma unroll
    for (int k = 0; k < 16; k++) {
        int idx = threadIdx.x + k * 256;
        int el = idx >> 4, c = idx & 15;
        gout[idx] = su[el * 17 + c];
    }
    if (threadIdx.x < NC) atomicAdd(&g_cec[threadIdx.x], scec[threadIdx.x]);
}

// ---------------- K nodeA: FUSED qk = relu(x@Wd+bd)@Wqk + bqk, qb ---------------
__global__ __launch_bounds__(256) void k_nodeA(const float* __restrict__ x,
                                               const float* __restrict__ Wd,
                                               const float* __restrict__ bd) {
    extern __shared__ float smem[];
    float* sWd = smem;                     // 256*64
    float* sWq = sWd + IN_CH * D;          // 64*64
    float* sbd = sWq + D * D;              // 64
    float* sbq = sbd + D;                  // 64
    float* swq = sbq + D;                  // 64
    float4* sx4 = reinterpret_cast<float4*>(swq + D);  // 128 x 16 float4 swizzled
    for (int t = threadIdx.x; t < IN_CH * D / 4; t += 256)
        reinterpret_cast<float4*>(sWd)[t] = reinterpret_cast<const float4*>(Wd)[t];
    for (int t = threadIdx.x; t < D * D / 4; t += 256)
        reinterpret_cast<float4*>(sWq)[t] = reinterpret_cast<const float4*>(g_Wqk)[t];
    if (threadIdx.x < D) {
        sbd[threadIdx.x] = bd[threadIdx.x];
        sbq[threadIdx.x] = g_bqk[threadIdx.x];
        swq[threadIdx.x] = g_wqb[threadIdx.x];
    }

    int wid = threadIdx.x >> 5, lane = threadIdx.x & 31;
    int q = wid & 3, grp = wid >> 2;
    int rl0 = grp * 64 + lane, rl1 = rl0 + 32;
    int sw0 = rl0 & 15;
    int r0 = blockIdx.x * 128 + rl0, r1 = blockIdx.x * 128 + rl1;

    u64 a0[8], a1[8];
    const float* wq1 = sWd + q * 16;
#pragma unroll
    for (int kc = 0; kc < 4; kc++) {
        __syncthreads();
        for (int t = threadIdx.x; t < 128 * 16; t += 256) {
            int row = t >> 4, c4 = t & 15;
            int rsrc = min(blockIdx.x * 128 + row, N_NODES - 1);
            sx4[SWZ(row, c4)] =
                reinterpret_cast<const float4*>(x + (size_t)rsrc * IN_CH + kc * 64)[c4];
        }
        __syncthreads();
        if (kc == 0) {
            const u64* bb = reinterpret_cast<const u64*>(sbd + q * 16);
#pragma unroll
            for (int k = 0; k < 8; k++) { a0[k] = bb[k]; a1[k] = bb[k]; }
        }
#pragma unroll
        for (int jv = 0; jv < 16; jv++) {
            float4 v0 = sx4[(rl0 << 4) + (jv ^ sw0)];
            float4 v1 = sx4[(rl1 << 4) + (jv ^ sw0)];
            const float* w0 = wq1 + (kc * 64 + 4 * jv) * D;
            colupd(a0, a1, v0.x, v1.x, w0);
            colupd(a0, a1, v0.y, v1.y, w0 + D);
            colupd(a0, a1, v0.z, v1.z, w0 + 2 * D);
            colupd(a0, a1, v0.w, v1.w, w0 + 3 * D);
        }
    }
    __syncthreads();
#pragma unroll
    for (int k = 0; k < 4; k++) {
        sx4[SWZ(rl0, q * 4 + k)] = relu4(a0[2*k], a0[2*k+1]);
        sx4[SWZ(rl1, q * 4 + k)] = relu4(a1[2*k], a1[2*k+1]);
    }
    __syncthreads();
    {
        const u64* bb = reinterpret_cast<const u64*>(sbq + q * 16);
#pragma unroll
        for (int k = 0; k < 8; k++) { a0[k] = bb[k]; a1[k] = bb[k]; }
    }
    float qb0 = g_sqb, qb1 = g_sqb;
    const float* wq2 = sWq + q * 16;
#pragma unroll
    for (int jv = 0; jv < 16; jv++) {
        float4 v0 = sx4[(rl0 << 4) + (jv ^ sw0)];
        float4 v1 = sx4[(rl1 << 4) + (jv ^ sw0)];
        const float* w0 = wq2 + (4 * jv) * D;
        colupd(a0, a1, v0.x, v1.x, w0);
        colupd(a0, a1, v0.y, v1.y, w0 + D);
        colupd(a0, a1, v0.z, v1.z, w0 + 2 * D);
        colupd(a0, a1, v0.w, v1.w, w0 + 3 * D);
        if (q == 0) {
            qb0 = fmaf(v0.x, swq[4*jv], fmaf(v0.y, swq[4*jv+1], fmaf(v0.z, swq[4*jv+2], fmaf(v0.w, swq[4*jv+3], qb0))));
            qb1 = fmaf(v1.x, swq[4*jv], fmaf(v1.y, swq[4*jv+1], fmaf(v1.z, swq[4*jv+2], fmaf(v1.w, swq[4*jv+3], qb1))));
        }
    }
    if (r0 < N_NODES) {
        float4* o0 = reinterpret_cast<float4*>(g_qk + (size_t)r0 * D + q * 16);
#pragma unroll
        for (int k = 0; k < 4; k++) o0[k] = raw4(a0[2*k], a0[2*k+1]);
    }
    if (r1 < N_NODES) {
        float4* o1 = reinterpret_cast<float4*>(g_qk + (size_t)r1 * D + q * 16);
#pragma unroll
        for (int k = 0; k < 4; k++) o1[k] = raw4(a1[2*k], a1[2*k+1]);
    }
    if (q == 0) {
        if (r0 < N_NODES) g_qb[r0] = qb0;
        if (r1 < N_NODES) g_qb[r1] = qb1;
    }
}

// ---------------- K gather: warp-per-node, attn in-kernel, shfl lookups ---------
__global__ __launch_bounds__(256) void k_gather() {
    __shared__ float s_attn[8][DEG_CAP];
    __shared__ int   s_ec  [8][DEG_CAP];
    int wid = threadIdx.x >> 5, lane = threadIdx.x & 31;
    int n = blockIdx.x * 8 + wid;           // grid = 6250 exact
    int off = g_off[n];
    int deg = g_off[n + 1] - off;
    int eg = lane >> 3, dg = lane & 7;

    float nne = 0.f;
#pragma unroll
    for (int c = 0; c < NC; c++) nne += (g_cec[c] > 0.f) ? 1.f : 0.f;
    float inv = 1.0f / nne;

    u64 qkd[4];
    {
        const float2* qrow = reinterpret_cast<const float2*>(g_qk + (size_t)n * D) + dg * 4;
#pragma unroll
        for (int k = 0; k < 4; k++) { float2 f = qrow[k]; qkd[k] = pk2(f.x, f.y); }
    }
    float qbn = g_qb[n];

    // Phase A: attn per edge (4 edges x 8 lanes), cache in smem
    for (int j0 = 0; j0 < deg; j0 += 4) {
        int j = j0 + eg;
        bool valid = (j < deg);
        int jj = valid ? j : (deg - 1);
        int ec = g_eidc[off + jj];
        int eid = ec >> 3;
        uint4 tv = *reinterpret_cast<const uint4*>(g_tfh + (size_t)eid * 32 + dg * 4);
        u64 dacc = 0ull;
#pragma unroll
        for (int k = 0; k < 4; k++) {
            u32 h = (&tv.x)[k];
            __half2 hh = *reinterpret_cast<const __half2*>(&h);
            float2 f = __half22float2(hh);
            fma2(dacc, pk2(f.x, f.y), qkd[k]);
        }
        float lo, hi; up2(dacc, lo, hi);
        float part = lo + hi;
        part += __shfl_xor_sync(0xFFFFFFFFu, part, 1);
        part += __shfl_xor_sync(0xFFFFFFFFu, part, 2);
        part += __shfl_xor_sync(0xFFFFFFFFu, part, 4);
        if (valid && dg == 0) {
            s_attn[wid][j] = (part + qbn) * 0.125f;
            s_ec[wid][j] = ec;
        }
    }
    __syncwarp();

    // Phase B1: per-cluster max
    float pm[NC];
#pragma unroll
    for (int c = 0; c < NC; c++) pm[c] = -3.4e38f;
    for (int j = lane; j < deg; j += 32) {
        float a = s_attn[wid][j];
        int cc = s_ec[wid][j] & 7;
#pragma unroll
        for (int c = 0; c < NC; c++) if (cc == c) pm[c] = fmaxf(pm[c], a);
    }
#pragma unroll
    for (int c = 0; c < NC; c++)
#pragma unroll
        for (int o = 16; o > 0; o >>= 1)
            pm[c] = fmaxf(pm[c], __shfl_xor_sync(0xFFFFFFFFu, pm[c], o));
    float mxL = 0.f;
#pragma unroll
    for (int c = 0; c < NC; c++) if (lane == c) mxL = pm[c];

    // Phase B2: per-cluster denom + count
    float pd[NC], pc[NC];
#pragma unroll
    for (int c = 0; c < NC; c++) { pd[c] = 0.f; pc[c] = 0.f; }
    int rounds = (deg + 31) >> 5;
    for (int r = 0; r < rounds; r++) {
        int j = r * 32 + lane;
        bool v = j < deg;
        int jj = v ? j : 0;
        float a = s_attn[wid][jj];
        int cc = s_ec[wid][jj] & 7;
        float cmv = __shfl_sync(0xFFFFFFFFu, mxL, cc);
        float ex = v ? __expf(a - cmv) : 0.f;
        float on = v ? 1.f : 0.f;
#pragma unroll
        for (int c = 0; c < NC; c++) {
            pd[c] += (cc == c) ? ex : 0.f;
            pc[c] += (cc == c) ? on : 0.f;
        }
    }
#pragma unroll
    for (int c = 0; c < NC; c++)
#pragma unroll
        for (int o = 16; o > 0; o >>= 1) {
            pd[c] += __shfl_xor_sync(0xFFFFFFFFu, pd[c], o);
            pc[c] += __shfl_xor_sync(0xFFFFFFFFu, pc[c], o);
        }

    float bsc = 0.f, svL = 0.f;
#pragma unroll
    for (int c = 0; c < NC; c++) {
        if (pc[c] > 0.f) bsc += 1.0f / pc[c];
        if (lane == c) svL = (pc[c] > 0.f) ? inv / (pd[c] * pc[c]) : 0.f;
    }
    if (lane == 0) g_bsc[n] = bsc * inv;

    // Phase C: weighted tf sum
    u64 acc[4] = {0ull, 0ull, 0ull, 0ull};
    for (int j0 = 0; j0 < deg; j0 += 4) {
        int j = j0 + eg;
        bool v = j < deg;
        int jj = v ? j : (deg - 1);
        float a = s_attn[wid][jj];
        int ec = s_ec[wid][jj];
        int cc = ec & 7;
        float cmv = __shfl_sync(0xFFFFFFFFu, mxL, cc);
        float sv  = __shfl_sync(0xFFFFFFFFu, svL, cc);
        float coef = v ? __expf(a - cmv) * sv : 0.f;
        int eid = ec >> 3;
        uint4 tv = *reinterpret_cast<const uint4*>(g_tfh + (size_t)eid * 32 + dg * 4);
        u64 cf2 = pk2(coef, coef);
#pragma unroll
        for (int k = 0; k < 4; k++) {
            u32 h = (&tv.x)[k];
            __half2 hh = *reinterpret_cast<const __half2*>(&h);
            float2 f = __half22float2(hh);
            fma2(acc[k], cf2, pk2(f.x, f.y));
        }
    }
#pragma unroll
    for (int k = 0; k < 4; k++) {
        acc[k] = add2(acc[k], __shfl_xor_sync(0xFFFFFFFFu, acc[k], 8));
        acc[k] = add2(acc[k], __shfl_xor_sync(0xFFFFFFFFu, acc[k], 16));
    }
    if (eg == 0) {
        float2* o = reinterpret_cast<float2*>(g_accN + (size_t)n * D + dg * 8);
#pragma unroll
        for (int k = 0; k < 4; k++) {
            float lo, hi; up2(acc[k], lo, hi);
            o[k] = make_float2(lo, hi);
        }
    }
}

// ---------------- K E2: fused = relu(accN @ Wvo + bvo*bsc + b_out) --------------
__global__ __launch_bounds__(256) void k_E2(const float* __restrict__ bo) {
    extern __shared__ float smem[];
    float* sW  = smem;            // 64*64
    float* sbv = sW + D * D;
    float* sbo = sbv + D;
    float4* sx4 = reinterpret_cast<float4*>(sbo + D);
    for (int t = threadIdx.x; t < D * D / 4; t += 256)
        reinterpret_cast<float4*>(sW)[t] = reinterpret_cast<const float4*>(g_Wvo)[t];
    if (threadIdx.x < D) { sbv[threadIdx.x] = g_bvo[threadIdx.x]; sbo[threadIdx.x] = bo[threadIdx.x]; }
    for (int t = threadIdx.x; t < 128 * 16; t += 256) {
        int row = t >> 4, c4 = t & 15;
        int rsrc = min(blockIdx.x * 128 + row, N_NODES - 1);
        sx4[SWZ(row, c4)] =
            reinterpret_cast<const float4*>(g_accN + (size_t)rsrc * D)[c4];
    }
    __syncthreads();
    int wid = threadIdx.x >> 5, lane = threadIdx.x & 31;
    int q = wid & 3, grp = wid >> 2;
    int rl0 = grp * 64 + lane, rl1 = rl0 + 32;
    int sw0 = rl0 & 15;
    int r0 = blockIdx.x * 128 + rl0, r1 = blockIdx.x * 128 + rl1;
    int r0c = min(r0, N_NODES - 1), r1c = min(r1, N_NODES - 1);
    float bs0 = g_bsc[r0c], bs1 = g_bsc[r1c];

    u64 a0[8], a1[8];
    const float* bvq = sbv + q * 16;
    const float* boq = sbo + q * 16;
#pragma unroll
    for (int k = 0; k < 8; k++) {
        a0[k] = pk2(fmaf(bvq[2*k], bs0, boq[2*k]), fmaf(bvq[2*k+1], bs0, boq[2*k+1]));
        a1[k] = pk2(fmaf(bvq[2*k], bs1, boq[2*k]), fmaf(bvq[2*k+1], bs1, boq[2*k+1]));
    }
    const float* wq = sW + q * 16;
#pragma unroll
    for (int jv = 0; jv < 16; jv++) {
        float4 v0 = sx4[(rl0 << 4) + (jv ^ sw0)];
        float4 v1 = sx4[(rl1 << 4) + (jv ^ sw0)];
        const float* w0 = wq + (4 * jv) * D;
        colupd(a0, a1, v0.x, v1.x, w0);
        colupd(a0, a1, v0.y, v1.y, w0 + D);
        colupd(a0, a1, v0.z, v1.z, w0 + 2 * D);
        colupd(a0, a1, v0.w, v1.w, w0 + 3 * D);
    }
    if (r0 < N_NODES) {
        float4* o0 = reinterpret_cast<float4*>(g_fused + (size_t)r0 * D + q * 16);
#pragma unroll
        for (int k = 0; k < 4; k++) o0[k] = relu4(a0[2*k], a0[2*k+1]);
    }
    if (r1 < N_NODES) {
        float4* o1 = reinterpret_cast<float4*>(g_fused + (size_t)r1 * D + q * 16);
#pragma unroll
        for (int k = 0; k < 4; k++) o1[k] = relu4(a1[2*k], a1[2*k+1]);
    }
}

// ---------------- K E3: out = x + fused @ W_up + b_up ---------------------------
__global__ __launch_bounds__(256) void k_E3(const float* __restrict__ x,
                                            const float* __restrict__ Wup,
                                            const float* __restrict__ bup,
                                            float* __restrict__ out) {
    extern __shared__ float smem[];
    float* sW = smem;                 // 64 x 128 slice
    float* sb = sW + D * 128;         // 128
    float4* sx4 = reinterpret_cast<float4*>(sb + 128);
    int gy = blockIdx.y;
    for (int t = threadIdx.x; t < D * 128 / 4; t += 256) {
        int row = t >> 5, c4 = t & 31;
        reinterpret_cast<float4*>(sW + row * 128)[c4] =
            reinterpret_cast<const float4*>(Wup + row * IN_CH + gy * 128)[c4];
    }
    if (threadIdx.x < 128) sb[threadIdx.x] = bup[gy * 128 + threadIdx.x];
    for (int t = threadIdx.x; t < 64 * 16; t += 256) {
        int row = t >> 4, c4 = t & 15;
        int rsrc = min(blockIdx.x * 64 + row, N_NODES - 1);
        sx4[SWZ(row, c4)] =
            reinterpret_cast<const float4*>(g_fused + (size_t)rsrc * D)[c4];
    }
    __syncthreads();
    int wid = threadIdx.x >> 5, lane = threadIdx.x & 31;
    int q = wid;
    int rl0 = lane, rl1 = lane + 32;
    int sw0 = lane & 15;
    int r0 = blockIdx.x * 64 + rl0, r1 = blockIdx.x * 64 + rl1;

    u64 a0[8], a1[8];
    const u64* bb = reinterpret_cast<const u64*>(sb + q * 16);
#pragma unroll
    for (int k = 0; k < 8; k++) { a0[k] = bb[k]; a1[k] = bb[k]; }

    const float* wq = sW + q * 16;
#pragma unroll
    for (int jv = 0; jv < 16; jv++) {
        float4 v0 = sx4[(rl0 << 4) + (jv ^ sw0)];
        float4 v1 = sx4[(rl1 << 4) + (jv ^ sw0)];
        const float* w0 = wq + (4 * jv) * 128;
        colupd(a0, a1, v0.x, v1.x, w0);
        colupd(a0, a1, v0.y, v1.y, w0 + 128);
        colupd(a0, a1, v0.z, v1.z, w0 + 2 * 128);
        colupd(a0, a1, v0.w, v1.w, w0 + 3 * 128);
    }
    int colbase = gy * 128 + q * 16;
    if (r0 < N_NODES) {
        const float4* xr = reinterpret_cast<const float4*>(x + (size_t)r0 * IN_CH + colbase);
        float4* o = reinterpret_cast<float4*>(out + (size_t)r0 * IN_CH + colbase);
#pragma unroll
        for (int k = 0; k < 4; k++) {
            float4 r = raw4(a0[2*k], a0[2*k+1]);
            float4 xv = xr[k];
            o[k] = make_float4(xv.x + r.x, xv.y + r.y, xv.z + r.z, xv.w + r.w);
        }
    }
    if (r1 < N_NODES) {
        const float4* xr = reinterpret_cast<const float4*>(x + (size_t)r1 * IN_CH + colbase);
        float4* o = reinterpret_cast<float4*>(out + (size_t)r1 * IN_CH + colbase);
#pragma unroll
        for (int k = 0; k < 4; k++) {
            float4 r = raw4(a1[2*k], a1[2*k+1]);
            float4 xv = xr[k];
            o[k] = make_float4(xv.x + r.x, xv.y + r.y, xv.z + r.z, xv.w + r.w);
        }
    }
}

// -------------------------------------------------------------------------------
extern "C" void kernel_launch(void* const* d_in, const int* in_sizes, int n_in,
                              void* d_out, int out_size) {
    const float* x   = (const float*)d_in[0];
    const float* ea  = (const float*)d_in[1];
    const int*   ei  = (const int*)  d_in[2];
    const float* Wd  = (const float*)d_in[3];
    const float* bd  = (const float*)d_in[4];
    const float* Wup = (const float*)d_in[5];
    const float* bup = (const float*)d_in[6];
    const float* Wt  = (const float*)d_in[7];
    const float* bt  = (const float*)d_in[8];
    const float* Wq  = (const float*)d_in[9];
    const float* bq  = (const float*)d_in[10];
    const float* Wk  = (const float*)d_in[11];
    const float* bk  = (const float*)d_in[12];
    const float* Wv  = (const float*)d_in[13];
    const float* bv  = (const float*)d_in[14];
    const float* ce  = (const float*)d_in[15];
    const float* Wo  = (const float*)d_in[16];
    const float* bo  = (const float*)d_in[17];
    float* out = (float*)d_out;

    int smA  = (IN_CH * D + D * D + 3 * D) * 4 + 128 * 64 * 4;   // ~114.7KB
    int smE1 = (16 * D + D + NC * D + NC) * 4 + 256 * 17 * 8;    // ~41.2KB
    int smE2 = (D * D + 2 * D) * 4 + 128 * 64 * 4;               // ~48.5KB
    int smE3 = (D * 128 + 128) * 4 + 64 * 64 * 4;                // ~48.5KB
    cudaFuncSetAttribute(k_nodeA, cudaFuncAttributeMaxDynamicSharedMemorySize, smA);
    cudaFuncSetAttribute(k_E2,    cudaFuncAttributeMaxDynamicSharedMemorySize, smE2);
    cudaFuncSetAttribute(k_E3,    cudaFuncAttributeMaxDynamicSharedMemorySize, smE3);

    int nblk128 = (N_NODES + 127) / 128;       // 391
    // edge1 no longer depends on nodeA -> place it at launch idx 3 (ncu capture slot)
    k_prep_init<<<NBLK_SC, 256>>>(Wq, bq, Wk, bk, Wv, bv, Wo, bo);  // idx 0
    k_count    <<<(N_EDGES + 255) / 256, 256>>>(ei);                 // idx 1
    k_scan     <<<NBLK_SC, 256>>>();                                 // idx 2
    k_edge1    <<<N_EDGES / 256, 256, smE1>>>(ea, ei, Wt, bt, ce);   // idx 3 (PROFILED)
    k_nodeA    <<<nblk128, 256, smA>>>(x, Wd, bd);                   // idx 4
    k_gather   <<<N_NODES / 8, 256>>>();                             // idx 5
    k_E2       <<<nblk128, 256, smE2>>>(bo);                         // idx 6
    k_E3       <<<dim3((N_NODES + 63) / 64, 2), 256, smE3>>>(x, Wup, bup, out);  // idx 7
}